// round 1
// baseline (speedup 1.0000x reference)
#include <cuda_runtime.h>
#include <math.h>

// ---------------- problem constants ----------------
#define BB   32
#define TT   12
#define NNODE 512
#define HID  64
#define CIN  66          // DIN(2)+HID  == dec_in(2)+HID
#define KC   198         // 3*CIN
#define EMB  10
#define BN   (BB*NNODE)  // 16384

// ---------------- device scratch (no allocations allowed) ----------------
__device__ float g_h[BN*HID];            // GRU state           (4 MB)
__device__ float g_xg[BN*KC];            // [inp | S@inp | 2S(S inp)-inp]  (13 MB)
__device__ float g_zr[BN*128];           // sigmoid gates z|r   (8 MB)
__device__ float g_sup_en[NNODE*NNODE];  // encoder support     (1 MB)
__device__ float g_sup_de[BB*NNODE*NNODE]; // decoder support   (33.5 MB)
__device__ float g_ne[BN*EMB];           // hyper embedding
__device__ float g_go[BN];               // decoder feedback

// ---------------- init ----------------
__global__ void k_zero() {
    int i = blockIdx.x*blockDim.x + threadIdx.x;
    int stride = gridDim.x*blockDim.x;
    for (int j=i; j<BN*HID; j+=stride) g_h[j]  = 0.f;
    for (int j=i; j<BN;     j+=stride) g_go[j] = 0.f;
}

// ---------------- supports: softmax(relu(E E^T)) row-wise ----------------
__global__ void k_support_en(const float* __restrict__ emb) {
    int n   = blockIdx.x;
    int tid = threadIdx.x;
    __shared__ float embn[EMB];
    __shared__ float row[NNODE];
    __shared__ float red[256];
    if (tid < EMB) embn[tid] = emb[n*EMB + tid];
    __syncthreads();
    for (int m=tid; m<NNODE; m+=256) {
        float s = 0.f;
        #pragma unroll
        for (int e=0; e<EMB; e++) s += embn[e]*emb[m*EMB+e];
        row[m] = fmaxf(s, 0.f);
    }
    __syncthreads();
    float lm = -1e30f;
    for (int m=tid; m<NNODE; m+=256) lm = fmaxf(lm, row[m]);
    red[tid] = lm; __syncthreads();
    for (int s=128; s>0; s>>=1) { if (tid<s) red[tid]=fmaxf(red[tid],red[tid+s]); __syncthreads(); }
    float mx = red[0];
    __syncthreads();
    float ls = 0.f;
    for (int m=tid; m<NNODE; m+=256) { float e = expf(row[m]-mx); row[m]=e; ls += e; }
    red[tid] = ls; __syncthreads();
    for (int s=128; s>0; s>>=1) { if (tid<s) red[tid]+=red[tid+s]; __syncthreads(); }
    float inv = 1.f/red[0];
    for (int m=tid; m<NNODE; m+=256) g_sup_en[n*NNODE+m] = row[m]*inv;
}

__global__ void k_support_de() {
    int bn = blockIdx.x;
    int b  = bn / NNODE, n = bn % NNODE;
    int tid = threadIdx.x;
    const float* neb = g_ne + (size_t)b*NNODE*EMB;
    __shared__ float embn[EMB];
    __shared__ float row[NNODE];
    __shared__ float red[256];
    if (tid < EMB) embn[tid] = neb[n*EMB + tid];
    __syncthreads();
    for (int m=tid; m<NNODE; m+=256) {
        float s = 0.f;
        #pragma unroll
        for (int e=0; e<EMB; e++) s += embn[e]*neb[m*EMB+e];
        row[m] = fmaxf(s, 0.f);
    }
    __syncthreads();
    float lm = -1e30f;
    for (int m=tid; m<NNODE; m+=256) lm = fmaxf(lm, row[m]);
    red[tid] = lm; __syncthreads();
    for (int s=128; s>0; s>>=1) { if (tid<s) red[tid]=fmaxf(red[tid],red[tid+s]); __syncthreads(); }
    float mx = red[0];
    __syncthreads();
    float ls = 0.f;
    for (int m=tid; m<NNODE; m+=256) { float e = expf(row[m]-mx); row[m]=e; ls += e; }
    red[tid] = ls; __syncthreads();
    for (int s=128; s>0; s>>=1) { if (tid<s) red[tid]+=red[tid+s]; __syncthreads(); }
    float inv = 1.f/red[0];
    float* outr = g_sup_de + (size_t)b*NNODE*NNODE + (size_t)n*NNODE;
    for (int m=tid; m<NNODE; m+=256) outr[m] = row[m]*inv;
}

// ---------------- input builders ----------------
__global__ void k_build_enc_gate(const float* __restrict__ x, int t) {
    int idx = blockIdx.x*blockDim.x + threadIdx.x;
    if (idx >= BN*CIN) return;
    int bn = idx / CIN, c = idx % CIN;
    int b  = bn / NNODE, n = bn % NNODE;
    float v;
    if (c < 2) v = x[(((size_t)b*TT + t)*NNODE + n)*2 + c];
    else       v = g_h[bn*HID + (c-2)];
    g_xg[bn*KC + c] = v;
}

__global__ void k_build_dec_gate(const float* __restrict__ ycov, int t) {
    int idx = blockIdx.x*blockDim.x + threadIdx.x;
    if (idx >= BN*CIN) return;
    int bn = idx / CIN, c = idx % CIN;
    int b  = bn / NNODE, n = bn % NNODE;
    float v;
    if      (c == 0) v = g_go[bn];
    else if (c == 1) v = ycov[((size_t)b*TT + t)*NNODE + n];
    else             v = g_h[bn*HID + (c-2)];
    g_xg[bn*KC + c] = v;
}

// cand: only columns 2..65 change (z * h); cols 0..1 already hold x_t
__global__ void k_build_cand() {
    int idx = blockIdx.x*blockDim.x + threadIdx.x;
    if (idx >= BN*HID) return;
    int bn = idx / HID, c = idx % HID;
    g_xg[bn*KC + 2 + c] = g_zr[bn*128 + c] * g_h[bn*HID + c];
}

// ---------------- batched support matmul: out = alpha*S@in + beta*base -----
// S is g_sup_en (shared over batch) or g_sup_de (per-batch)
__global__ void __launch_bounds__(256) k_spmm(int deFlag, int inOff, int outOff,
                                              float alpha, float beta, int baseOff) {
    __shared__ float Ssh[64][33];
    __shared__ float Xsh[32][80];
    int b  = blockIdx.y;
    int m0 = blockIdx.x * 64;
    int tx = threadIdx.x, ty = threadIdx.y;
    int tid = ty*16 + tx;
    const float* Sb = deFlag ? (g_sup_de + (size_t)b*NNODE*NNODE) : g_sup_en;

    float acc[4][5];
    #pragma unroll
    for (int i=0;i<4;i++)
        #pragma unroll
        for (int j=0;j<5;j++) acc[i][j] = 0.f;

    for (int k0=0; k0<NNODE; k0+=32) {
        #pragma unroll
        for (int i=0;i<8;i++) {                   // 64x32 S tile
            int e = tid + i*256;
            int r = e >> 5, kl = e & 31;
            Ssh[r][kl] = Sb[(size_t)(m0+r)*NNODE + k0 + kl];
        }
        #pragma unroll
        for (int i=0;i<10;i++) {                  // 32x80 X tile (zero-padded cols)
            int e = tid + i*256;
            int kl = e/80, c = e%80;
            Xsh[kl][c] = (c < CIN) ? g_xg[((size_t)b*NNODE + (k0+kl))*KC + inOff + c] : 0.f;
        }
        __syncthreads();
        #pragma unroll
        for (int k=0;k<32;k++) {
            float a[4], xv[5];
            #pragma unroll
            for (int i=0;i<4;i++) a[i] = Ssh[ty*4+i][k];
            #pragma unroll
            for (int j=0;j<5;j++) xv[j] = Xsh[k][tx + 16*j];
            #pragma unroll
            for (int i=0;i<4;i++)
                #pragma unroll
                for (int j=0;j<5;j++) acc[i][j] += a[i]*xv[j];
        }
        __syncthreads();
    }
    #pragma unroll
    for (int i=0;i<4;i++) {
        int n = m0 + ty*4 + i;
        size_t rowbase = ((size_t)b*NNODE + n)*KC;
        #pragma unroll
        for (int j=0;j<5;j++) {
            int c = tx + 16*j;
            if (c < CIN) {
                float v = alpha*acc[i][j];
                if (beta != 0.f) v += beta * g_xg[rowbase + baseOff + c];
                g_xg[rowbase + outOff + c] = v;
            }
        }
    }
}

// ---------------- gate GEMM: zr = sigmoid(Xg @ W(198x128) + b) --------------
__global__ void __launch_bounds__(256) k_gemm_gate(const float* __restrict__ W,
                                                   const float* __restrict__ bias) {
    __shared__ float Ash[64][33];
    __shared__ float Bsh[32][68];
    int m0 = blockIdx.x*64;
    int o0 = blockIdx.y*64;
    int tx = threadIdx.x, ty = threadIdx.y;
    int tid = ty*16 + tx;
    float acc[4][4];
    #pragma unroll
    for (int i=0;i<4;i++)
        #pragma unroll
        for (int j=0;j<4;j++) acc[i][j] = 0.f;

    for (int k0=0; k0<KC; k0+=32) {
        #pragma unroll
        for (int i=0;i<8;i++) {
            int e = tid + i*256;
            int r = e >> 5, kl = e & 31;
            int k = k0 + kl;
            Ash[r][kl] = (k < KC) ? g_xg[(size_t)(m0+r)*KC + k] : 0.f;
        }
        #pragma unroll
        for (int i=0;i<8;i++) {
            int e = tid + i*256;
            int kl = e >> 6, o = e & 63;
            int k = k0 + kl;
            Bsh[kl][o] = (k < KC) ? W[(size_t)k*128 + o0 + o] : 0.f;
        }
        __syncthreads();
        #pragma unroll
        for (int k=0;k<32;k++) {
            float a[4], bv[4];
            #pragma unroll
            for (int i=0;i<4;i++) a[i]  = Ash[ty*4+i][k];
            #pragma unroll
            for (int j=0;j<4;j++) bv[j] = Bsh[k][tx + 16*j];
            #pragma unroll
            for (int i=0;i<4;i++)
                #pragma unroll
                for (int j=0;j<4;j++) acc[i][j] += a[i]*bv[j];
        }
        __syncthreads();
    }
    #pragma unroll
    for (int i=0;i<4;i++) {
        int row = m0 + ty*4 + i;
        #pragma unroll
        for (int j=0;j<4;j++) {
            int o = o0 + tx + 16*j;
            float v = acc[i][j] + bias[o];
            g_zr[(size_t)row*128 + o] = 1.f/(1.f + expf(-v));
        }
    }
}

// ---------------- update GEMM: h = r*h + (1-r)*tanh(Xg @ W(198x64) + b) ----
__global__ void __launch_bounds__(256) k_gemm_update(const float* __restrict__ W,
                                                     const float* __restrict__ bias) {
    __shared__ float Ash[64][33];
    __shared__ float Bsh[32][68];
    int m0 = blockIdx.x*64;
    int tx = threadIdx.x, ty = threadIdx.y;
    int tid = ty*16 + tx;
    float acc[4][4];
    #pragma unroll
    for (int i=0;i<4;i++)
        #pragma unroll
        for (int j=0;j<4;j++) acc[i][j] = 0.f;

    for (int k0=0; k0<KC; k0+=32) {
        #pragma unroll
        for (int i=0;i<8;i++) {
            int e = tid + i*256;
            int r = e >> 5, kl = e & 31;
            int k = k0 + kl;
            Ash[r][kl] = (k < KC) ? g_xg[(size_t)(m0+r)*KC + k] : 0.f;
        }
        #pragma unroll
        for (int i=0;i<8;i++) {
            int e = tid + i*256;
            int kl = e >> 6, o = e & 63;
            int k = k0 + kl;
            Bsh[kl][o] = (k < KC) ? W[(size_t)k*64 + o] : 0.f;
        }
        __syncthreads();
        #pragma unroll
        for (int k=0;k<32;k++) {
            float a[4], bv[4];
            #pragma unroll
            for (int i=0;i<4;i++) a[i]  = Ash[ty*4+i][k];
            #pragma unroll
            for (int j=0;j<4;j++) bv[j] = Bsh[k][tx + 16*j];
            #pragma unroll
            for (int i=0;i<4;i++)
                #pragma unroll
                for (int j=0;j<4;j++) acc[i][j] += a[i]*bv[j];
        }
        __syncthreads();
    }
    #pragma unroll
    for (int i=0;i<4;i++) {
        int row = m0 + ty*4 + i;
        #pragma unroll
        for (int j=0;j<4;j++) {
            int o = tx + 16*j;
            float hc = tanhf(acc[i][j] + bias[o]);
            float r  = g_zr[(size_t)row*128 + 64 + o];
            float hv = g_h[(size_t)row*64 + o];
            g_h[(size_t)row*64 + o] = r*hv + (1.f - r)*hc;
        }
    }
}

// ---------------- hyper projection ne = h @ Wh + bh ----------------
__global__ void k_hyper(const float* __restrict__ hW, const float* __restrict__ hb) {
    int idx = blockIdx.x*blockDim.x + threadIdx.x;
    if (idx >= BN*EMB) return;
    int bn = idx / EMB, e = idx % EMB;
    float s = hb[e];
    #pragma unroll
    for (int k=0;k<HID;k++) s += g_h[bn*HID + k] * hW[k*EMB + e];
    g_ne[idx] = s;
}

// ---------------- output projection: go = h @ pW + pb ----------------
__global__ void k_proj(const float* __restrict__ pW, const float* __restrict__ pb,
                       float* __restrict__ out, int t) {
    int gtid = blockIdx.x*blockDim.x + threadIdx.x;
    int warp = gtid >> 5;
    int lane = threadIdx.x & 31;
    if (warp >= BN) return;
    float s = g_h[(size_t)warp*64 + lane]      * pW[lane]
            + g_h[(size_t)warp*64 + 32 + lane] * pW[32 + lane];
    #pragma unroll
    for (int o=16; o>0; o>>=1) s += __shfl_xor_sync(0xffffffffu, s, o);
    if (lane == 0) {
        float go = s + pb[0];
        g_go[warp] = go;
        int b = warp / NNODE, n = warp % NNODE;
        out[((size_t)b*TT + t)*NNODE + n] = go;
    }
}

// ---------------- orchestration ----------------
extern "C" void kernel_launch(void* const* d_in, const int* in_sizes, int n_in,
                              void* d_out, int out_size) {
    const float* x       = (const float*)d_in[0];
    const float* ycov    = (const float*)d_in[1];
    const float* emb     = (const float*)d_in[2];
    const float* enc_gW  = (const float*)d_in[3];
    const float* enc_gb  = (const float*)d_in[4];
    const float* enc_uW  = (const float*)d_in[5];
    const float* enc_ub  = (const float*)d_in[6];
    const float* dec_gW  = (const float*)d_in[7];
    const float* dec_gb  = (const float*)d_in[8];
    const float* dec_uW  = (const float*)d_in[9];
    const float* dec_ub  = (const float*)d_in[10];
    const float* proj_W  = (const float*)d_in[11];
    const float* proj_b  = (const float*)d_in[12];
    const float* hyper_W = (const float*)d_in[13];
    const float* hyper_b = (const float*)d_in[14];
    float* out = (float*)d_out;

    dim3 bs2(16,16);
    dim3 gs_spmm(NNODE/64, BB);
    dim3 gs_gate(BN/64, 2);
    dim3 gs_upd (BN/64, 1);
    int  nb_build = (BN*CIN + 255)/256;
    int  nb_cand  = (BN*HID + 255)/256;

    k_zero<<<256,256>>>();
    k_support_en<<<NNODE,256>>>(emb);

    // ---- encoder ----
    for (int t=0; t<TT; t++) {
        k_build_enc_gate<<<nb_build,256>>>(x, t);
        k_spmm<<<gs_spmm,bs2>>>(0, 0, CIN, 1.f, 0.f, 0);
        k_spmm<<<gs_spmm,bs2>>>(0, CIN, 2*CIN, 2.f, -1.f, 0);
        k_gemm_gate<<<gs_gate,bs2>>>(enc_gW, enc_gb);
        k_build_cand<<<nb_cand,256>>>();
        k_spmm<<<gs_spmm,bs2>>>(0, 0, CIN, 1.f, 0.f, 0);
        k_spmm<<<gs_spmm,bs2>>>(0, CIN, 2*CIN, 2.f, -1.f, 0);
        k_gemm_update<<<gs_upd,bs2>>>(enc_uW, enc_ub);
    }

    // ---- adaptive decoder support ----
    k_hyper<<<(BN*EMB+255)/256,256>>>(hyper_W, hyper_b);
    k_support_de<<<BN,256>>>();

    // ---- decoder ----
    for (int t=0; t<TT; t++) {
        k_build_dec_gate<<<nb_build,256>>>(ycov, t);
        k_spmm<<<gs_spmm,bs2>>>(1, 0, CIN, 1.f, 0.f, 0);
        k_spmm<<<gs_spmm,bs2>>>(1, CIN, 2*CIN, 2.f, -1.f, 0);
        k_gemm_gate<<<gs_gate,bs2>>>(dec_gW, dec_gb);
        k_build_cand<<<nb_cand,256>>>();
        k_spmm<<<gs_spmm,bs2>>>(1, 0, CIN, 1.f, 0.f, 0);
        k_spmm<<<gs_spmm,bs2>>>(1, CIN, 2*CIN, 2.f, -1.f, 0);
        k_gemm_update<<<gs_upd,bs2>>>(dec_uW, dec_ub);
        k_proj<<<(BN*32+255)/256,256>>>(proj_W, proj_b, out, t);
    }
}

// round 2
// speedup vs baseline: 1.0542x; 1.0542x over previous
#include <cuda_runtime.h>
#include <math.h>

// ---------------- problem constants ----------------
#define BB   32
#define TT   12
#define NN   512
#define HID  64
#define EMB  10
#define BN   (BB*NN)     // 16384

// feature buffer layout (per row, stride XGP):
//   [0..65]    X   (2 input ch + 64 hidden/cand)
//   [66..67]   pad (always 0)
//   [68..133]  Y1 = S@X
//   [134..135] pad (always 0)
//   [136..201] Y2 = 2S@Y1 - X
//   [202..203] pad (always 0)
#define XGP  204
#define OY1  68
#define OY2  136

// ---------------- device scratch ----------------
__device__ float g_h[BN*HID];              // GRU state (4 MB)
__device__ float g_xg[BN*XGP];             // feature buffer (13.4 MB)
__device__ float g_r[BN*HID];              // reset gate r  (4 MB)
__device__ float g_sup_en[NN*NN];          // encoder support (1 MB)
__device__ float g_sup_de[(size_t)BB*NN*NN]; // decoder support (33.5 MB)
__device__ float g_ne[BN*EMB];
__device__ float g_go[BN];

// ---------------- init (must run every launch: graph replays) --------------
__global__ void k_zero() {
    int i = blockIdx.x*blockDim.x + threadIdx.x;
    int st = gridDim.x*blockDim.x;
    for (int j=i; j<BN*XGP; j+=st) g_xg[j] = 0.f;
    for (int j=i; j<BN*HID; j+=st) g_h[j]  = 0.f;
    for (int j=i; j<BN;     j+=st) g_go[j] = 0.f;
}

// ---------------- supports: softmax(relu(E E^T)) row-wise ------------------
__global__ void k_support_en(const float* __restrict__ emb) {
    int n   = blockIdx.x;
    int tid = threadIdx.x;
    __shared__ float embn[EMB];
    __shared__ float row[NN];
    __shared__ float red[256];
    if (tid < EMB) embn[tid] = emb[n*EMB + tid];
    __syncthreads();
    for (int m=tid; m<NN; m+=256) {
        float s = 0.f;
        #pragma unroll
        for (int e=0; e<EMB; e++) s += embn[e]*emb[m*EMB+e];
        row[m] = fmaxf(s, 0.f);
    }
    __syncthreads();
    float lm = -1e30f;
    for (int m=tid; m<NN; m+=256) lm = fmaxf(lm, row[m]);
    red[tid] = lm; __syncthreads();
    for (int s=128; s>0; s>>=1) { if (tid<s) red[tid]=fmaxf(red[tid],red[tid+s]); __syncthreads(); }
    float mx = red[0];
    __syncthreads();
    float ls = 0.f;
    for (int m=tid; m<NN; m+=256) { float e = expf(row[m]-mx); row[m]=e; ls += e; }
    red[tid] = ls; __syncthreads();
    for (int s=128; s>0; s>>=1) { if (tid<s) red[tid]+=red[tid+s]; __syncthreads(); }
    float inv = 1.f/red[0];
    for (int m=tid; m<NN; m+=256) g_sup_en[n*NN+m] = row[m]*inv;
}

__global__ void k_support_de() {
    int bn = blockIdx.x;
    int b  = bn >> 9, n = bn & 511;
    int tid = threadIdx.x;
    const float* neb = g_ne + (size_t)b*NN*EMB;
    __shared__ float embn[EMB];
    __shared__ float row[NN];
    __shared__ float red[256];
    if (tid < EMB) embn[tid] = neb[n*EMB + tid];
    __syncthreads();
    for (int m=tid; m<NN; m+=256) {
        float s = 0.f;
        #pragma unroll
        for (int e=0; e<EMB; e++) s += embn[e]*neb[m*EMB+e];
        row[m] = fmaxf(s, 0.f);
    }
    __syncthreads();
    float lm = -1e30f;
    for (int m=tid; m<NN; m+=256) lm = fmaxf(lm, row[m]);
    red[tid] = lm; __syncthreads();
    for (int s=128; s>0; s>>=1) { if (tid<s) red[tid]=fmaxf(red[tid],red[tid+s]); __syncthreads(); }
    float mx = red[0];
    __syncthreads();
    float ls = 0.f;
    for (int m=tid; m<NN; m+=256) { float e = expf(row[m]-mx); row[m]=e; ls += e; }
    red[tid] = ls; __syncthreads();
    for (int s=128; s>0; s>>=1) { if (tid<s) red[tid]+=red[tid+s]; __syncthreads(); }
    float inv = 1.f/red[0];
    float* outr = g_sup_de + (size_t)b*NN*NN + (size_t)n*NN;
    for (int m=tid; m<NN; m+=256) outr[m] = row[m]*inv;
}

// ---------------- tiny builders (only 2 cols each) --------------------------
__global__ void k_build_enc(const float* __restrict__ x, int t) {
    int bn = blockIdx.x*blockDim.x + threadIdx.x;
    if (bn >= BN) return;
    int b = bn >> 9, n = bn & 511;
    const float* xp = &x[(((size_t)b*TT + t)*NN + n)*2];
    float* f = &g_xg[(size_t)bn*XGP];
    f[0] = xp[0];
    f[1] = xp[1];
}

__global__ void k_build_dec(const float* __restrict__ ycov, int t) {
    int bn = blockIdx.x*blockDim.x + threadIdx.x;
    if (bn >= BN) return;
    int b = bn >> 9, n = bn & 511;
    float* f = &g_xg[(size_t)bn*XGP];
    f[0] = g_go[bn];
    f[1] = ycov[((size_t)b*TT + t)*NN + n];
}

// ---------------- batched support matmul ------------------------------------
// cheb==1:  Y1 = S @ X          (reads cols [0..65], writes [68..133])
// cheb==2:  Y2 = 2 S @ Y1 - X   (reads [68..133] + base [0..65], writes [136..201])
// tile: 64 rows x 66 cols, k-tile 32, 256 threads, micro 4x4 + 1 extra col.
#define SPMM_LOAD(buf, k0) do { \
    _Pragma("unroll") \
    for (int i=0;i<2;i++) { \
        int q = tid + 256*i; \
        int rw = q >> 3, kq = q & 7; \
        float4 v = *(const float4*)&Sb[(size_t)(m0+rw)*NN + (k0) + 4*kq]; \
        Ssh[buf][4*kq+0][rw] = v.x; Ssh[buf][4*kq+1][rw] = v.y; \
        Ssh[buf][4*kq+2][rw] = v.z; Ssh[buf][4*kq+3][rw] = v.w; \
    } \
    _Pragma("unroll") \
    for (int i=0;i<2;i++) { \
        int q = tid + 256*i; \
        int kk = q >> 4, cq = q & 15; \
        float4 v = *(const float4*)&Xg[(size_t)((k0)+kk)*XGP + inOff + 4*cq]; \
        *(float4*)&Xsh[buf][kk][4*cq] = v; \
    } \
    if (tid < 64) { \
        int kk = tid >> 1, c = 64 + (tid & 1); \
        Xsh[buf][kk][c] = Xg[(size_t)((k0)+kk)*XGP + inOff + c]; \
    } \
} while(0)

__global__ void __launch_bounds__(256) k_spmm(int deFlag, int cheb) {
    __shared__ float Ssh[2][32][68];
    __shared__ float Xsh[2][32][68];
    int b   = blockIdx.y;
    int m0  = blockIdx.x * 64;
    int tid = threadIdx.x;
    int tx  = tid & 15, ty = tid >> 4;
    const float* Sb = deFlag ? g_sup_de + (size_t)b*NN*NN : g_sup_en;
    float* Xg = g_xg + (size_t)b*NN*XGP;
    const int inOff = (cheb == 1) ? 0 : OY1;
    const int outOff = (cheb == 1) ? OY1 : OY2;

    float acc[4][4] = {};
    float acce = 0.f;
    int erow = tid >> 1;           // extra-col row (tid<128)
    int ecol = 64 + (tid & 1);

    SPMM_LOAD(0, 0);
    __syncthreads();
    for (int kt = 0; kt < 16; kt++) {
        int buf = kt & 1;
        if (kt < 15) SPMM_LOAD(buf^1, (kt+1)*32);
        #pragma unroll
        for (int k = 0; k < 32; k++) {
            float4 a  = *(const float4*)&Ssh[buf][k][4*ty];
            float4 xv = *(const float4*)&Xsh[buf][k][4*tx];
            acc[0][0] += a.x*xv.x; acc[0][1] += a.x*xv.y; acc[0][2] += a.x*xv.z; acc[0][3] += a.x*xv.w;
            acc[1][0] += a.y*xv.x; acc[1][1] += a.y*xv.y; acc[1][2] += a.y*xv.z; acc[1][3] += a.y*xv.w;
            acc[2][0] += a.z*xv.x; acc[2][1] += a.z*xv.y; acc[2][2] += a.z*xv.z; acc[2][3] += a.z*xv.w;
            acc[3][0] += a.w*xv.x; acc[3][1] += a.w*xv.y; acc[3][2] += a.w*xv.z; acc[3][3] += a.w*xv.w;
            if (tid < 128)
                acce += Ssh[buf][k][erow] * Xsh[buf][k][ecol];
        }
        __syncthreads();
    }

    #pragma unroll
    for (int i = 0; i < 4; i++) {
        int rw = m0 + 4*ty + i;
        float* outp = &Xg[(size_t)rw*XGP];
        float4 o;
        if (cheb == 1) {
            o.x = acc[i][0]; o.y = acc[i][1]; o.z = acc[i][2]; o.w = acc[i][3];
        } else {
            float4 bx = *(const float4*)&outp[4*tx];
            o.x = 2.f*acc[i][0] - bx.x; o.y = 2.f*acc[i][1] - bx.y;
            o.z = 2.f*acc[i][2] - bx.z; o.w = 2.f*acc[i][3] - bx.w;
        }
        *(float4*)&outp[outOff + 4*tx] = o;
    }
    if (tid < 128) {
        int rw = m0 + erow;
        float* outp = &Xg[(size_t)rw*XGP];
        float v = (cheb == 1) ? acce : 2.f*acce - outp[ecol];
        outp[outOff + ecol] = v;
    }
}

// weight-row mapping: feature col -> W row (skipping pad cols)
__device__ __forceinline__ int wmap(int k) {
    int wr = (k < 66) ? k : ((k < 134) ? k - 2 : k - 4);
    return wr > 197 ? 197 : wr;
}

// ---------------- gate GEMM: zr = sigmoid(F @ W(198x128) + b) ---------------
// tile 64 rows x 128 cols (full N), k-tile 16, micro 4x8.
// epilogue: writes cand features (z*h) into cols [2..65] and r into g_r.
__global__ void __launch_bounds__(256) k_gate(const float* __restrict__ W,
                                              const float* __restrict__ bias) {
    __shared__ float Ash[2][16][68];
    __shared__ float Bsh[2][16][128];
    int m0  = blockIdx.x * 64;
    int tid = threadIdx.x;
    int tx  = tid & 15, ty = tid >> 4;
    float acc[4][8] = {};

#define GATE_LOAD(buf, k0) do { \
    { \
        int q = tid; \
        int rw = q >> 2, kq = q & 3; \
        int k = (k0) + 4*kq; \
        float4 v = make_float4(0.f,0.f,0.f,0.f); \
        if (k < XGP) v = *(const float4*)&g_xg[(size_t)(m0+rw)*XGP + k]; \
        Ash[buf][4*kq+0][rw] = v.x; Ash[buf][4*kq+1][rw] = v.y; \
        Ash[buf][4*kq+2][rw] = v.z; Ash[buf][4*kq+3][rw] = v.w; \
    } \
    _Pragma("unroll") \
    for (int i=0;i<2;i++) { \
        int q = tid + 256*i; \
        int kk = q >> 5, oq = q & 31; \
        int wr = wmap((k0) + kk); \
        float4 v = *(const float4*)&W[(size_t)wr*128 + 4*oq]; \
        *(float4*)&Bsh[buf][kk][4*oq] = v; \
    } \
} while(0)

    GATE_LOAD(0, 0);
    __syncthreads();
    for (int kt = 0; kt < 13; kt++) {     // 13*16 = 208 >= 204
        int buf = kt & 1;
        if (kt < 12) GATE_LOAD(buf^1, (kt+1)*16);
        #pragma unroll
        for (int k = 0; k < 16; k++) {
            float4 a  = *(const float4*)&Ash[buf][k][4*ty];
            float4 b0 = *(const float4*)&Bsh[buf][k][4*tx];
            float4 b1 = *(const float4*)&Bsh[buf][k][64 + 4*tx];
            acc[0][0]+=a.x*b0.x; acc[0][1]+=a.x*b0.y; acc[0][2]+=a.x*b0.z; acc[0][3]+=a.x*b0.w;
            acc[0][4]+=a.x*b1.x; acc[0][5]+=a.x*b1.y; acc[0][6]+=a.x*b1.z; acc[0][7]+=a.x*b1.w;
            acc[1][0]+=a.y*b0.x; acc[1][1]+=a.y*b0.y; acc[1][2]+=a.y*b0.z; acc[1][3]+=a.y*b0.w;
            acc[1][4]+=a.y*b1.x; acc[1][5]+=a.y*b1.y; acc[1][6]+=a.y*b1.z; acc[1][7]+=a.y*b1.w;
            acc[2][0]+=a.z*b0.x; acc[2][1]+=a.z*b0.y; acc[2][2]+=a.z*b0.z; acc[2][3]+=a.z*b0.w;
            acc[2][4]+=a.z*b1.x; acc[2][5]+=a.z*b1.y; acc[2][6]+=a.z*b1.z; acc[2][7]+=a.z*b1.w;
            acc[3][0]+=a.w*b0.x; acc[3][1]+=a.w*b0.y; acc[3][2]+=a.w*b0.z; acc[3][3]+=a.w*b0.w;
            acc[3][4]+=a.w*b1.x; acc[3][5]+=a.w*b1.y; acc[3][6]+=a.w*b1.z; acc[3][7]+=a.w*b1.w;
        }
        __syncthreads();
    }

    #pragma unroll
    for (int i = 0; i < 4; i++) {
        int rw = m0 + 4*ty + i;
        #pragma unroll
        for (int j = 0; j < 4; j++) {
            int o = 4*tx + j;
            float z = 1.f/(1.f + expf(-(acc[i][j]   + bias[o])));
            float r = 1.f/(1.f + expf(-(acc[i][4+j] + bias[64+o])));
            g_xg[(size_t)rw*XGP + 2 + o] = z * g_h[(size_t)rw*HID + o];
            g_r[(size_t)rw*HID + o] = r;
        }
    }
}

// ---------------- update GEMM: h = r*h + (1-r)*tanh(F @ W(198x64) + b) ------
// tile 64x64, k-tile 32, micro 4x4. epilogue writes h and next gate features.
__global__ void __launch_bounds__(256) k_upd(const float* __restrict__ W,
                                             const float* __restrict__ bias) {
    __shared__ float Ash[2][32][68];
    __shared__ float Bsh[2][32][68];
    int m0  = blockIdx.x * 64;
    int tid = threadIdx.x;
    int tx  = tid & 15, ty = tid >> 4;
    float acc[4][4] = {};

#define UPD_LOAD(buf, k0) do { \
    _Pragma("unroll") \
    for (int i=0;i<2;i++) { \
        int q = tid + 256*i; \
        int rw = q >> 3, kq = q & 7; \
        int k = (k0) + 4*kq; \
        float4 v = make_float4(0.f,0.f,0.f,0.f); \
        if (k < XGP) v = *(const float4*)&g_xg[(size_t)(m0+rw)*XGP + k]; \
        Ash[buf][4*kq+0][rw] = v.x; Ash[buf][4*kq+1][rw] = v.y; \
        Ash[buf][4*kq+2][rw] = v.z; Ash[buf][4*kq+3][rw] = v.w; \
    } \
    _Pragma("unroll") \
    for (int i=0;i<2;i++) { \
        int q = tid + 256*i; \
        int kk = q >> 4, oq = q & 15; \
        int wr = wmap((k0) + kk); \
        float4 v = *(const float4*)&W[(size_t)wr*64 + 4*oq]; \
        *(float4*)&Bsh[buf][kk][4*oq] = v; \
    } \
} while(0)

    UPD_LOAD(0, 0);
    __syncthreads();
    for (int kt = 0; kt < 7; kt++) {     // 7*32 = 224 >= 204
        int buf = kt & 1;
        if (kt < 6) UPD_LOAD(buf^1, (kt+1)*32);
        #pragma unroll
        for (int k = 0; k < 32; k++) {
            float4 a  = *(const float4*)&Ash[buf][k][4*ty];
            float4 bv = *(const float4*)&Bsh[buf][k][4*tx];
            acc[0][0]+=a.x*bv.x; acc[0][1]+=a.x*bv.y; acc[0][2]+=a.x*bv.z; acc[0][3]+=a.x*bv.w;
            acc[1][0]+=a.y*bv.x; acc[1][1]+=a.y*bv.y; acc[1][2]+=a.y*bv.z; acc[1][3]+=a.y*bv.w;
            acc[2][0]+=a.z*bv.x; acc[2][1]+=a.z*bv.y; acc[2][2]+=a.z*bv.z; acc[2][3]+=a.z*bv.w;
            acc[3][0]+=a.w*bv.x; acc[3][1]+=a.w*bv.y; acc[3][2]+=a.w*bv.z; acc[3][3]+=a.w*bv.w;
        }
        __syncthreads();
    }

    #pragma unroll
    for (int i = 0; i < 4; i++) {
        int rw = m0 + 4*ty + i;
        #pragma unroll
        for (int j = 0; j < 4; j++) {
            int o = 4*tx + j;
            float hc = tanhf(acc[i][j] + bias[o]);
            float r  = g_r[(size_t)rw*HID + o];
            float h  = g_h[(size_t)rw*HID + o];
            float hn = r*h + (1.f - r)*hc;
            g_h[(size_t)rw*HID + o] = hn;
            g_xg[(size_t)rw*XGP + 2 + o] = hn;   // features for next gate phase
        }
    }
}

// ---------------- hyper projection ne = h @ Wh + bh -------------------------
__global__ void k_hyper(const float* __restrict__ hW, const float* __restrict__ hb) {
    int idx = blockIdx.x*blockDim.x + threadIdx.x;
    if (idx >= BN*EMB) return;
    int bn = idx / EMB, e = idx % EMB;
    float s = hb[e];
    #pragma unroll
    for (int k = 0; k < HID; k++) s += g_h[(size_t)bn*HID + k] * hW[k*EMB + e];
    g_ne[idx] = s;
}

// ---------------- output projection: go = h @ pW + pb -----------------------
__global__ void k_proj(const float* __restrict__ pW, const float* __restrict__ pb,
                       float* __restrict__ out, int t) {
    int gtid = blockIdx.x*blockDim.x + threadIdx.x;
    int warp = gtid >> 5;
    int lane = threadIdx.x & 31;
    if (warp >= BN) return;
    float s = g_h[(size_t)warp*64 + lane]      * pW[lane]
            + g_h[(size_t)warp*64 + 32 + lane] * pW[32 + lane];
    #pragma unroll
    for (int o = 16; o > 0; o >>= 1) s += __shfl_xor_sync(0xffffffffu, s, o);
    if (lane == 0) {
        float go = s + pb[0];
        g_go[warp] = go;
        int b = warp >> 9, n = warp & 511;
        out[((size_t)b*TT + t)*NN + n] = go;
    }
}

// ---------------- orchestration ---------------------------------------------
extern "C" void kernel_launch(void* const* d_in, const int* in_sizes, int n_in,
                              void* d_out, int out_size) {
    const float* x       = (const float*)d_in[0];
    const float* ycov    = (const float*)d_in[1];
    const float* emb     = (const float*)d_in[2];
    const float* enc_gW  = (const float*)d_in[3];
    const float* enc_gb  = (const float*)d_in[4];
    const float* enc_uW  = (const float*)d_in[5];
    const float* enc_ub  = (const float*)d_in[6];
    const float* dec_gW  = (const float*)d_in[7];
    const float* dec_gb  = (const float*)d_in[8];
    const float* dec_uW  = (const float*)d_in[9];
    const float* dec_ub  = (const float*)d_in[10];
    const float* proj_W  = (const float*)d_in[11];
    const float* proj_b  = (const float*)d_in[12];
    const float* hyper_W = (const float*)d_in[13];
    const float* hyper_b = (const float*)d_in[14];
    float* out = (float*)d_out;

    dim3 gs_spmm(NN/64, BB);     // 8 x 32 = 256 blocks
    int  gs_mm = BN/64;          // 256 blocks
    int  nb2 = (BN + 255)/256;

    k_zero<<<1024, 256>>>();
    k_support_en<<<NN, 256>>>(emb);

    // ---- encoder ----
    for (int t = 0; t < TT; t++) {
        k_build_enc<<<nb2, 256>>>(x, t);
        k_spmm<<<gs_spmm, 256>>>(0, 1);
        k_spmm<<<gs_spmm, 256>>>(0, 2);
        k_gate<<<gs_mm, 256>>>(enc_gW, enc_gb);
        k_spmm<<<gs_spmm, 256>>>(0, 1);
        k_spmm<<<gs_spmm, 256>>>(0, 2);
        k_upd<<<gs_mm, 256>>>(enc_uW, enc_ub);
    }

    // ---- adaptive decoder support ----
    k_hyper<<<(BN*EMB + 255)/256, 256>>>(hyper_W, hyper_b);
    k_support_de<<<BN, 256>>>();

    // ---- decoder ----
    for (int t = 0; t < TT; t++) {
        k_build_dec<<<nb2, 256>>>(ycov, t);
        k_spmm<<<gs_spmm, 256>>>(1, 1);
        k_spmm<<<gs_spmm, 256>>>(1, 2);
        k_gate<<<gs_mm, 256>>>(dec_gW, dec_gb);
        k_spmm<<<gs_spmm, 256>>>(1, 1);
        k_spmm<<<gs_spmm, 256>>>(1, 2);
        k_upd<<<gs_mm, 256>>>(dec_uW, dec_ub);
        k_proj<<<(BN*32 + 255)/256, 256>>>(proj_W, proj_b, out, t);
    }
}

// round 3
// speedup vs baseline: 1.3442x; 1.2751x over previous
#include <cuda_runtime.h>
#include <math.h>

// ---------------- problem constants ----------------
#define BB   32
#define TT   12
#define NN   512
#define HID  64
#define EMB  10
#define BN   (BB*NN)     // 16384

// feature row layout, stride XGP=200:
//  [0..63]    X      (h  or z*h)            <-> W rows 2..65
//  [64..127]  S@X                           <-> W rows 68..131
//  [128..191] 2S(S@X)-X                     <-> W rows 134..197
//  [192..197] x-features [x0,x1,Sx0,Sx1,S2x0,S2x1] <-> W rows 0,1,66,67,132,133
//  [198..199] pad (always 0)
#define XGP  200

// ---------------- device scratch ----------------
__device__ float g_h[BN*HID];
__device__ float g_r[BN*HID];
__device__ float g_xg[(size_t)BN*XGP];
__device__ float g_sup_en[NN*NN];
__device__ float g_sup_de[(size_t)BB*NN*NN];
__device__ float g_ne[BN*EMB];
__device__ float g_go[BN];
__device__ float g_tmp[BN];
__device__ float g_xf1[BN*24];   // encoder S@x   [b][n][t*2+c]
__device__ float g_xf2[BN*24];   // encoder S2@x
__device__ float g_yf1[BN*TT];   // decoder S@ycov  [b][n][t]
__device__ float g_yf2[BN*TT];   // decoder S2@ycov

// feature col -> W row
__device__ __forceinline__ int wmap(int c) {
    if (c < 64)  return c + 2;
    if (c < 128) return c + 4;
    if (c < 192) return c + 6;
    if (c < 198) return ((c - 192) >> 1) * 66 + (c & 1);
    return 197;  // pad cols (A holds 0 there)
}

// ---------------- init ----------------
__global__ void k_zero() {
    size_t i = (size_t)blockIdx.x*blockDim.x + threadIdx.x;
    size_t st = (size_t)gridDim.x*blockDim.x;
    for (size_t j=i; j<(size_t)BN*XGP; j+=st) g_xg[j] = 0.f;
    for (size_t j=i; j<BN*HID; j+=st) g_h[j]  = 0.f;
    for (size_t j=i; j<BN;     j+=st) g_go[j] = 0.f;
}

// ---------------- supports ----------------
__global__ void k_support_en(const float* __restrict__ emb) {
    int n = blockIdx.x, tid = threadIdx.x;
    __shared__ float embn[EMB];
    __shared__ float row[NN];
    __shared__ float red[256];
    if (tid < EMB) embn[tid] = emb[n*EMB + tid];
    __syncthreads();
    for (int m=tid; m<NN; m+=256) {
        float s = 0.f;
        #pragma unroll
        for (int e=0; e<EMB; e++) s += embn[e]*emb[m*EMB+e];
        row[m] = fmaxf(s, 0.f);
    }
    __syncthreads();
    float lm = -1e30f;
    for (int m=tid; m<NN; m+=256) lm = fmaxf(lm, row[m]);
    red[tid]=lm; __syncthreads();
    for (int s=128;s>0;s>>=1){ if(tid<s) red[tid]=fmaxf(red[tid],red[tid+s]); __syncthreads(); }
    float mx = red[0]; __syncthreads();
    float ls = 0.f;
    for (int m=tid; m<NN; m+=256){ float e=expf(row[m]-mx); row[m]=e; ls+=e; }
    red[tid]=ls; __syncthreads();
    for (int s=128;s>0;s>>=1){ if(tid<s) red[tid]+=red[tid+s]; __syncthreads(); }
    float inv = 1.f/red[0];
    for (int m=tid; m<NN; m+=256) g_sup_en[n*NN+m] = row[m]*inv;
}

__global__ void k_support_de() {
    int bn = blockIdx.x;
    int b = bn >> 9, n = bn & 511;
    int tid = threadIdx.x;
    const float* neb = g_ne + (size_t)b*NN*EMB;
    __shared__ float embn[EMB];
    __shared__ float row[NN];
    __shared__ float red[256];
    if (tid < EMB) embn[tid] = neb[n*EMB + tid];
    __syncthreads();
    for (int m=tid; m<NN; m+=256) {
        float s = 0.f;
        #pragma unroll
        for (int e=0; e<EMB; e++) s += embn[e]*neb[m*EMB+e];
        row[m] = fmaxf(s, 0.f);
    }
    __syncthreads();
    float lm = -1e30f;
    for (int m=tid; m<NN; m+=256) lm = fmaxf(lm, row[m]);
    red[tid]=lm; __syncthreads();
    for (int s=128;s>0;s>>=1){ if(tid<s) red[tid]=fmaxf(red[tid],red[tid+s]); __syncthreads(); }
    float mx = red[0]; __syncthreads();
    float ls = 0.f;
    for (int m=tid; m<NN; m+=256){ float e=expf(row[m]-mx); row[m]=e; ls+=e; }
    red[tid]=ls; __syncthreads();
    for (int s=128;s>0;s>>=1){ if(tid<s) red[tid]+=red[tid+s]; __syncthreads(); }
    float inv = 1.f/red[0];
    float* outr = g_sup_de + (size_t)b*NN*NN + (size_t)n*NN;
    for (int m=tid; m<NN; m+=256) outr[m] = row[m]*inv;
}

// ---------------- encoder x-feature precompute ------------------------------
// phase1: g_xf1 = S_en @ x_all   (cols = 12t*2c = 24 per batch)
// phase2: g_xf2 = 2*S_en @ g_xf1 - x_all
__global__ void __launch_bounds__(256) k_pre_enc(const float* __restrict__ x, int phase) {
    __shared__ float xsh[512*24];   // 48KB
    int b = blockIdx.y, m0 = blockIdx.x*64;
    int tid = threadIdx.x;
    for (int idx = tid; idx < 512*24; idx += 256) {
        int k = idx/24, tc = idx%24;
        float v;
        if (phase == 1) { int t = tc>>1, c = tc&1; v = x[(((size_t)b*TT+t)*NN + k)*2 + c]; }
        else            v = g_xf1[((size_t)b*NN + k)*24 + tc];
        xsh[idx] = v;
    }
    __syncthreads();
    int row = m0 + (tid>>2);
    int g   = (tid&3)*6;
    float acc[6] = {};
    const float* Srow = g_sup_en + (size_t)row*NN;
    for (int k=0; k<NN; k+=4) {
        float4 s = *(const float4*)&Srow[k];
        #pragma unroll
        for (int j=0;j<6;j++) {
            acc[j] += s.x*xsh[(k+0)*24 + g + j] + s.y*xsh[(k+1)*24 + g + j]
                    + s.z*xsh[(k+2)*24 + g + j] + s.w*xsh[(k+3)*24 + g + j];
        }
    }
    #pragma unroll
    for (int j=0;j<6;j++) {
        int col = g + j;
        if (phase == 1) g_xf1[((size_t)b*NN + row)*24 + col] = acc[j];
        else {
            int t = col>>1, c = col&1;
            g_xf2[((size_t)b*NN + row)*24 + col] =
                2.f*acc[j] - x[(((size_t)b*TT+t)*NN + row)*2 + c];
        }
    }
}

// ---------------- decoder ycov-feature precompute ---------------------------
__global__ void __launch_bounds__(256) k_pre_dec(const float* __restrict__ ycov, int phase) {
    __shared__ float ysh[512*12];   // 24KB
    int b = blockIdx.y, m0 = blockIdx.x*64;
    int tid = threadIdx.x;
    for (int idx = tid; idx < 512*12; idx += 256) {
        int k = idx/12, t = idx%12;
        float v;
        if (phase == 1) v = ycov[((size_t)b*TT+t)*NN + k];
        else            v = g_yf1[((size_t)b*NN + k)*12 + t];
        ysh[idx] = v;
    }
    __syncthreads();
    int row = m0 + (tid>>2);
    int g   = (tid&3)*3;
    float acc[3] = {};
    const float* Srow = g_sup_de + (size_t)b*NN*NN + (size_t)row*NN;
    for (int k=0; k<NN; k+=4) {
        float4 s = *(const float4*)&Srow[k];
        #pragma unroll
        for (int j=0;j<3;j++) {
            acc[j] += s.x*ysh[(k+0)*12 + g + j] + s.y*ysh[(k+1)*12 + g + j]
                    + s.z*ysh[(k+2)*12 + g + j] + s.w*ysh[(k+3)*12 + g + j];
        }
    }
    #pragma unroll
    for (int j=0;j<3;j++) {
        int t = g + j;
        if (phase == 1) g_yf1[((size_t)b*NN + row)*12 + t] = acc[j];
        else            g_yf2[((size_t)b*NN + row)*12 + t] =
                            2.f*acc[j] - ycov[((size_t)b*TT+t)*NN + row];
    }
}

// ---------------- decoder go mat-vecs ---------------------------------------
// phase1: col194 = S@go, also -> g_tmp.  phase2: col196 = 2*S@g_tmp - go
__global__ void __launch_bounds__(256) k_mv_go(int phase) {
    __shared__ float gsh[NN];
    int b = blockIdx.y;
    int tid = threadIdx.x, lane = tid & 31, w = tid >> 5;
    int row = blockIdx.x*8 + w;
    const float* src = (phase == 1) ? g_go : g_tmp;
    gsh[tid]       = src[(size_t)b*NN + tid];
    gsh[tid + 256] = src[(size_t)b*NN + tid + 256];
    __syncthreads();
    const float* Srow = g_sup_de + (size_t)b*NN*NN + (size_t)row*NN;
    float acc = 0.f;
    #pragma unroll
    for (int i=0;i<4;i++) {
        int k = lane*4 + 128*i;
        float4 s = *(const float4*)&Srow[k];
        acc += s.x*gsh[k] + s.y*gsh[k+1] + s.z*gsh[k+2] + s.w*gsh[k+3];
    }
    #pragma unroll
    for (int o=16;o>0;o>>=1) acc += __shfl_xor_sync(0xffffffffu, acc, o);
    if (lane == 0) {
        size_t bn = (size_t)b*NN + row;
        if (phase == 1) { g_tmp[bn] = acc; g_xg[bn*XGP + 194] = acc; }
        else            g_xg[bn*XGP + 196] = 2.f*acc - g_go[bn];
    }
}

// ---------------- builders ---------------------------------------------------
__global__ void k_build_enc(const float* __restrict__ x, int t) {
    int bn = blockIdx.x*blockDim.x + threadIdx.x;
    if (bn >= BN) return;
    int b = bn >> 9, n = bn & 511;
    float* f = &g_xg[(size_t)bn*XGP];
    const float* xp = &x[(((size_t)b*TT+t)*NN + n)*2];
    f[192] = xp[0];
    f[193] = xp[1];
    f[194] = g_xf1[(size_t)bn*24 + t*2 + 0];
    f[195] = g_xf1[(size_t)bn*24 + t*2 + 1];
    f[196] = g_xf2[(size_t)bn*24 + t*2 + 0];
    f[197] = g_xf2[(size_t)bn*24 + t*2 + 1];
}

__global__ void k_build_dec(const float* __restrict__ ycov, int t) {
    int bn = blockIdx.x*blockDim.x + threadIdx.x;
    if (bn >= BN) return;
    int b = bn >> 9, n = bn & 511;
    float* f = &g_xg[(size_t)bn*XGP];
    f[192] = g_go[bn];
    f[193] = ycov[((size_t)b*TT+t)*NN + n];
    f[195] = g_yf1[(size_t)bn*12 + t];
    f[197] = g_yf2[(size_t)bn*12 + t];
    // 194, 196 written by k_mv_go
}

// ---------------- h-chain spmm: 128x64 tile, micro 8x4 ----------------------
// cheb==1: sec1 = S @ sec0       cheb==2: sec2 = 2*S@sec1 - sec0
__global__ void __launch_bounds__(256) k_spmm(int deFlag, int cheb) {
    __shared__ float Ssh[2][16][132];
    __shared__ float Xsh[2][16][68];
    const int b = blockIdx.y;
    const int m0 = blockIdx.x*128;
    const int tid = threadIdx.x;
    const int tx = tid & 15, ty = tid >> 4;
    const float* Sb = deFlag ? g_sup_de + (size_t)b*NN*NN : g_sup_en;
    float* Xg = g_xg + (size_t)b*NN*XGP;
    const int inOff  = (cheb == 1) ? 0  : 64;
    const int outOff = (cheb == 1) ? 64 : 128;

    const int rwS = tid >> 2;          // 0..63 (and +64)
    const int kqS = (tid & 3) * 4;     // 0,4,8,12
    const int kkX = tid >> 4;          // 0..15
    const int cqX = (tid & 15) * 4;    // 0..60

    float4 sA0, sA1, xA;
    float acc[8][4] = {};

#define SP_LDG(k0) do { \
    sA0 = *(const float4*)&Sb[(size_t)(m0+rwS)*NN + (k0) + kqS]; \
    sA1 = *(const float4*)&Sb[(size_t)(m0+rwS+64)*NN + (k0) + kqS]; \
    xA  = *(const float4*)&Xg[(size_t)((k0)+kkX)*XGP + inOff + cqX]; \
} while(0)
#define SP_STS(bf) do { \
    Ssh[bf][kqS+0][rwS]=sA0.x; Ssh[bf][kqS+1][rwS]=sA0.y; \
    Ssh[bf][kqS+2][rwS]=sA0.z; Ssh[bf][kqS+3][rwS]=sA0.w; \
    Ssh[bf][kqS+0][rwS+64]=sA1.x; Ssh[bf][kqS+1][rwS+64]=sA1.y; \
    Ssh[bf][kqS+2][rwS+64]=sA1.z; Ssh[bf][kqS+3][rwS+64]=sA1.w; \
    *(float4*)&Xsh[bf][kkX][cqX] = xA; \
} while(0)

    SP_LDG(0); SP_STS(0); __syncthreads();
    for (int kt = 0; kt < 32; kt++) {
        int buf = kt & 1;
        if (kt < 31) SP_LDG((kt+1)*16);
        #pragma unroll
        for (int k = 0; k < 16; k++) {
            float4 a0 = *(const float4*)&Ssh[buf][k][8*ty];
            float4 a1 = *(const float4*)&Ssh[buf][k][8*ty+4];
            float4 xv = *(const float4*)&Xsh[buf][k][4*tx];
            acc[0][0]+=a0.x*xv.x; acc[0][1]+=a0.x*xv.y; acc[0][2]+=a0.x*xv.z; acc[0][3]+=a0.x*xv.w;
            acc[1][0]+=a0.y*xv.x; acc[1][1]+=a0.y*xv.y; acc[1][2]+=a0.y*xv.z; acc[1][3]+=a0.y*xv.w;
            acc[2][0]+=a0.z*xv.x; acc[2][1]+=a0.z*xv.y; acc[2][2]+=a0.z*xv.z; acc[2][3]+=a0.z*xv.w;
            acc[3][0]+=a0.w*xv.x; acc[3][1]+=a0.w*xv.y; acc[3][2]+=a0.w*xv.z; acc[3][3]+=a0.w*xv.w;
            acc[4][0]+=a1.x*xv.x; acc[4][1]+=a1.x*xv.y; acc[4][2]+=a1.x*xv.z; acc[4][3]+=a1.x*xv.w;
            acc[5][0]+=a1.y*xv.x; acc[5][1]+=a1.y*xv.y; acc[5][2]+=a1.y*xv.z; acc[5][3]+=a1.y*xv.w;
            acc[6][0]+=a1.z*xv.x; acc[6][1]+=a1.z*xv.y; acc[6][2]+=a1.z*xv.z; acc[6][3]+=a1.z*xv.w;
            acc[7][0]+=a1.w*xv.x; acc[7][1]+=a1.w*xv.y; acc[7][2]+=a1.w*xv.z; acc[7][3]+=a1.w*xv.w;
        }
        if (kt < 31) SP_STS(buf^1);
        __syncthreads();
    }
    #pragma unroll
    for (int i = 0; i < 8; i++) {
        int r = m0 + 8*ty + i;
        float4 o = make_float4(acc[i][0], acc[i][1], acc[i][2], acc[i][3]);
        if (cheb == 2) {
            float4 bx = *(const float4*)&Xg[(size_t)r*XGP + 4*tx];
            o.x = 2.f*o.x - bx.x; o.y = 2.f*o.y - bx.y;
            o.z = 2.f*o.z - bx.z; o.w = 2.f*o.w - bx.w;
        }
        *(float4*)&Xg[(size_t)r*XGP + outOff + 4*tx] = o;
    }
#undef SP_LDG
#undef SP_STS
}

// ---------------- gate GEMM: 128x128 tile, micro 8x8 ------------------------
__global__ void __launch_bounds__(256) k_gate(const float* __restrict__ W,
                                              const float* __restrict__ bias) {
    __shared__ float Ash[2][16][132];
    __shared__ float Bsh[2][16][132];
    const int m0 = blockIdx.x*128;
    const int tid = threadIdx.x;
    const int tx = tid & 15, ty = tid >> 4;
    const int rwA = tid >> 2, kqA = (tid & 3)*4;
    const int kkB = tid >> 5, oqB = (tid & 31)*4;   // +256: kkB+8
    float4 aA0, aA1, bB0, bB1;
    float acc[8][8] = {};

#define GT_LDG(k0) do { \
    aA0 = ((k0)+kqA < XGP) ? *(const float4*)&g_xg[(size_t)(m0+rwA)*XGP + (k0) + kqA] : make_float4(0,0,0,0); \
    aA1 = ((k0)+kqA < XGP) ? *(const float4*)&g_xg[(size_t)(m0+rwA+64)*XGP + (k0) + kqA] : make_float4(0,0,0,0); \
    bB0 = *(const float4*)&W[(size_t)wmap((k0)+kkB)*128 + oqB]; \
    bB1 = *(const float4*)&W[(size_t)wmap((k0)+kkB+8)*128 + oqB]; \
} while(0)
#define GT_STS(bf) do { \
    Ash[bf][kqA+0][rwA]=aA0.x; Ash[bf][kqA+1][rwA]=aA0.y; \
    Ash[bf][kqA+2][rwA]=aA0.z; Ash[bf][kqA+3][rwA]=aA0.w; \
    Ash[bf][kqA+0][rwA+64]=aA1.x; Ash[bf][kqA+1][rwA+64]=aA1.y; \
    Ash[bf][kqA+2][rwA+64]=aA1.z; Ash[bf][kqA+3][rwA+64]=aA1.w; \
    *(float4*)&Bsh[bf][kkB][oqB]   = bB0; \
    *(float4*)&Bsh[bf][kkB+8][oqB] = bB1; \
} while(0)

    GT_LDG(0); GT_STS(0); __syncthreads();
    for (int kt = 0; kt < 13; kt++) {
        int buf = kt & 1;
        if (kt < 12) GT_LDG((kt+1)*16);
        #pragma unroll
        for (int k = 0; k < 16; k++) {
            float4 a0 = *(const float4*)&Ash[buf][k][8*ty];
            float4 a1 = *(const float4*)&Ash[buf][k][8*ty+4];
            float4 b0 = *(const float4*)&Bsh[buf][k][8*tx];
            float4 b1 = *(const float4*)&Bsh[buf][k][8*tx+4];
            float av[8] = {a0.x,a0.y,a0.z,a0.w,a1.x,a1.y,a1.z,a1.w};
            float bv[8] = {b0.x,b0.y,b0.z,b0.w,b1.x,b1.y,b1.z,b1.w};
            #pragma unroll
            for (int i=0;i<8;i++)
                #pragma unroll
                for (int j=0;j<8;j++) acc[i][j] += av[i]*bv[j];
        }
        if (kt < 12) GT_STS(buf^1);
        __syncthreads();
    }
    #pragma unroll
    for (int i = 0; i < 8; i++) {
        int row = m0 + 8*ty + i;
        #pragma unroll
        for (int j = 0; j < 8; j++) {
            int o = 8*tx + j;       // 0..127
            float v = 1.f/(1.f + expf(-(acc[i][j] + bias[o])));
            if (o < 64) g_xg[(size_t)row*XGP + o] = v * g_h[(size_t)row*HID + o];  // z*h
            else        g_r[(size_t)row*HID + (o-64)] = v;                          // r
        }
    }
#undef GT_LDG
#undef GT_STS
}

// ---------------- update GEMM: 128x64 tile, micro 8x4 -----------------------
__global__ void __launch_bounds__(256) k_upd(const float* __restrict__ W,
                                             const float* __restrict__ bias) {
    __shared__ float Ash[2][16][132];
    __shared__ float Bsh[2][16][68];
    const int m0 = blockIdx.x*128;
    const int tid = threadIdx.x;
    const int tx = tid & 15, ty = tid >> 4;
    const int rwA = tid >> 2, kqA = (tid & 3)*4;
    const int kkB = tid >> 4, oqB = (tid & 15)*4;
    float4 aA0, aA1, bB0;
    float acc[8][4] = {};

#define UP_LDG(k0) do { \
    aA0 = ((k0)+kqA < XGP) ? *(const float4*)&g_xg[(size_t)(m0+rwA)*XGP + (k0) + kqA] : make_float4(0,0,0,0); \
    aA1 = ((k0)+kqA < XGP) ? *(const float4*)&g_xg[(size_t)(m0+rwA+64)*XGP + (k0) + kqA] : make_float4(0,0,0,0); \
    bB0 = *(const float4*)&W[(size_t)wmap((k0)+kkB)*64 + oqB]; \
} while(0)
#define UP_STS(bf) do { \
    Ash[bf][kqA+0][rwA]=aA0.x; Ash[bf][kqA+1][rwA]=aA0.y; \
    Ash[bf][kqA+2][rwA]=aA0.z; Ash[bf][kqA+3][rwA]=aA0.w; \
    Ash[bf][kqA+0][rwA+64]=aA1.x; Ash[bf][kqA+1][rwA+64]=aA1.y; \
    Ash[bf][kqA+2][rwA+64]=aA1.z; Ash[bf][kqA+3][rwA+64]=aA1.w; \
    *(float4*)&Bsh[bf][kkB][oqB] = bB0; \
} while(0)

    UP_LDG(0); UP_STS(0); __syncthreads();
    for (int kt = 0; kt < 13; kt++) {
        int buf = kt & 1;
        if (kt < 12) UP_LDG((kt+1)*16);
        #pragma unroll
        for (int k = 0; k < 16; k++) {
            float4 a0 = *(const float4*)&Ash[buf][k][8*ty];
            float4 a1 = *(const float4*)&Ash[buf][k][8*ty+4];
            float4 bv = *(const float4*)&Bsh[buf][k][4*tx];
            acc[0][0]+=a0.x*bv.x; acc[0][1]+=a0.x*bv.y; acc[0][2]+=a0.x*bv.z; acc[0][3]+=a0.x*bv.w;
            acc[1][0]+=a0.y*bv.x; acc[1][1]+=a0.y*bv.y; acc[1][2]+=a0.y*bv.z; acc[1][3]+=a0.y*bv.w;
            acc[2][0]+=a0.z*bv.x; acc[2][1]+=a0.z*bv.y; acc[2][2]+=a0.z*bv.z; acc[2][3]+=a0.z*bv.w;
            acc[3][0]+=a0.w*bv.x; acc[3][1]+=a0.w*bv.y; acc[3][2]+=a0.w*bv.z; acc[3][3]+=a0.w*bv.w;
            acc[4][0]+=a1.x*bv.x; acc[4][1]+=a1.x*bv.y; acc[4][2]+=a1.x*bv.z; acc[4][3]+=a1.x*bv.w;
            acc[5][0]+=a1.y*bv.x; acc[5][1]+=a1.y*bv.y; acc[5][2]+=a1.y*bv.z; acc[5][3]+=a1.y*bv.w;
            acc[6][0]+=a1.z*bv.x; acc[6][1]+=a1.z*bv.y; acc[6][2]+=a1.z*bv.z; acc[6][3]+=a1.z*bv.w;
            acc[7][0]+=a1.w*bv.x; acc[7][1]+=a1.w*bv.y; acc[7][2]+=a1.w*bv.z; acc[7][3]+=a1.w*bv.w;
        }
        if (kt < 12) UP_STS(buf^1);
        __syncthreads();
    }
    #pragma unroll
    for (int i = 0; i < 8; i++) {
        int row = m0 + 8*ty + i;
        #pragma unroll
        for (int j = 0; j < 4; j++) {
            int o = 4*tx + j;
            float hc = tanhf(acc[i][j] + bias[o]);
            float r  = g_r[(size_t)row*HID + o];
            float h  = g_h[(size_t)row*HID + o];
            float hn = r*h + (1.f - r)*hc;
            g_h[(size_t)row*HID + o] = hn;
            g_xg[(size_t)row*XGP + o] = hn;   // sec0 for next cell
        }
    }
#undef UP_LDG
#undef UP_STS
}

// ---------------- hyper projection ------------------------------------------
__global__ void k_hyper(const float* __restrict__ hW, const float* __restrict__ hb) {
    int idx = blockIdx.x*blockDim.x + threadIdx.x;
    if (idx >= BN*EMB) return;
    int bn = idx / EMB, e = idx % EMB;
    float s = hb[e];
    #pragma unroll
    for (int k = 0; k < HID; k++) s += g_h[(size_t)bn*HID + k] * hW[k*EMB + e];
    g_ne[idx] = s;
}

// ---------------- output projection -----------------------------------------
__global__ void k_proj(const float* __restrict__ pW, const float* __restrict__ pb,
                       float* __restrict__ out, int t) {
    int gtid = blockIdx.x*blockDim.x + threadIdx.x;
    int warp = gtid >> 5;
    int lane = threadIdx.x & 31;
    if (warp >= BN) return;
    float s = g_h[(size_t)warp*64 + lane]      * pW[lane]
            + g_h[(size_t)warp*64 + 32 + lane] * pW[32 + lane];
    #pragma unroll
    for (int o = 16; o > 0; o >>= 1) s += __shfl_xor_sync(0xffffffffu, s, o);
    if (lane == 0) {
        float go = s + pb[0];
        g_go[warp] = go;
        int b = warp >> 9, n = warp & 511;
        out[((size_t)b*TT + t)*NN + n] = go;
    }
}

// ---------------- orchestration ---------------------------------------------
extern "C" void kernel_launch(void* const* d_in, const int* in_sizes, int n_in,
                              void* d_out, int out_size) {
    const float* x       = (const float*)d_in[0];
    const float* ycov    = (const float*)d_in[1];
    const float* emb     = (const float*)d_in[2];
    const float* enc_gW  = (const float*)d_in[3];
    const float* enc_gb  = (const float*)d_in[4];
    const float* enc_uW  = (const float*)d_in[5];
    const float* enc_ub  = (const float*)d_in[6];
    const float* dec_gW  = (const float*)d_in[7];
    const float* dec_gb  = (const float*)d_in[8];
    const float* dec_uW  = (const float*)d_in[9];
    const float* dec_ub  = (const float*)d_in[10];
    const float* proj_W  = (const float*)d_in[11];
    const float* proj_b  = (const float*)d_in[12];
    const float* hyper_W = (const float*)d_in[13];
    const float* hyper_b = (const float*)d_in[14];
    float* out = (float*)d_out;

    dim3 gs_spmm(4, BB);       // 128 CTAs
    dim3 gs_pre(8, BB);
    dim3 gs_mv(64, BB);
    int  gs_gate = BN/128;     // 128
    int  gs_upd  = BN/128;     // 128
    int  nb2 = (BN + 255)/256;

    k_zero<<<1024, 256>>>();
    k_support_en<<<NN, 256>>>(emb);
    k_pre_enc<<<gs_pre, 256>>>(x, 1);
    k_pre_enc<<<gs_pre, 256>>>(x, 2);

    for (int t = 0; t < TT; t++) {
        k_build_enc<<<nb2, 256>>>(x, t);
        k_spmm<<<gs_spmm, 256>>>(0, 1);
        k_spmm<<<gs_spmm, 256>>>(0, 2);
        k_gate<<<gs_gate, 256>>>(enc_gW, enc_gb);
        k_spmm<<<gs_spmm, 256>>>(0, 1);
        k_spmm<<<gs_spmm, 256>>>(0, 2);
        k_upd<<<gs_upd, 256>>>(enc_uW, enc_ub);
    }

    k_hyper<<<(BN*EMB + 255)/256, 256>>>(hyper_W, hyper_b);
    k_support_de<<<BN, 256>>>();
    k_pre_dec<<<gs_pre, 256>>>(ycov, 1);
    k_pre_dec<<<gs_pre, 256>>>(ycov, 2);

    for (int t = 0; t < TT; t++) {
        k_build_dec<<<nb2, 256>>>(ycov, t);
        k_mv_go<<<gs_mv, 256>>>(1);
        k_mv_go<<<gs_mv, 256>>>(2);
        k_spmm<<<gs_spmm, 256>>>(1, 1);
        k_spmm<<<gs_spmm, 256>>>(1, 2);
        k_gate<<<gs_gate, 256>>>(dec_gW, dec_gb);
        k_spmm<<<gs_spmm, 256>>>(1, 1);
        k_spmm<<<gs_spmm, 256>>>(1, 2);
        k_upd<<<gs_upd, 256>>>(dec_uW, dec_ub);
        k_proj<<<(BN*32 + 255)/256, 256>>>(proj_W, proj_b, out, t);
    }
}

// round 4
// speedup vs baseline: 1.7271x; 1.2849x over previous
#include <cuda_runtime.h>
#include <math.h>

// ---------------- problem constants ----------------
#define BB   32
#define TT   12
#define NN   512
#define HID  64
#define EMB  10
#define BN   (BB*NN)     // 16384

// feature row layout, stride XGP=200:
//  [0..63]    X      (h  or z*h)            <-> W rows 2..65
//  [64..127]  S@X                           <-> W rows 68..131
//  [128..191] 2S(S@X)-X                     <-> W rows 134..197
//  [192..197] x-features [x0,x1,Sx0,Sx1,S2x0,S2x1] <-> W rows 0,1,66,67,132,133
//  [198..199] pad (always 0)
#define XGP  200

// ---------------- device scratch ----------------
__device__ float g_h[BN*HID];
__device__ float g_r[BN*HID];
__device__ float g_xg[(size_t)BN*XGP];
__device__ float g_sup_en[NN*NN];
__device__ float g_sup_de[(size_t)BB*NN*NN];
__device__ float g_ne[BN*EMB];
__device__ float g_go[BN];
__device__ float g_tmp[BN];
__device__ float g_xf1[BN*24];
__device__ float g_xf2[BN*24];
__device__ float g_yf1[BN*TT];
__device__ float g_yf2[BN*TT];

// feature col -> W row
__device__ __forceinline__ int wmap(int c) {
    if (c < 64)  return c + 2;
    if (c < 128) return c + 4;
    if (c < 192) return c + 6;
    if (c < 198) return ((c - 192) >> 1) * 66 + (c & 1);
    return 197;
}

// ---------------- tf32 mma helpers ----------------
__device__ __forceinline__ unsigned f2tf(float f) {
    unsigned u;
    asm("cvt.rna.tf32.f32 %0, %1;" : "=r"(u) : "f"(f));
    return u;
}
__device__ __forceinline__ void mma_tf32(float* d,
    unsigned a0, unsigned a1, unsigned a2, unsigned a3,
    unsigned b0, unsigned b1) {
    asm volatile(
        "mma.sync.aligned.m16n8k8.row.col.f32.tf32.tf32.f32 "
        "{%0,%1,%2,%3}, {%4,%5,%6,%7}, {%8,%9}, {%0,%1,%2,%3};\n"
        : "+f"(d[0]), "+f"(d[1]), "+f"(d[2]), "+f"(d[3])
        : "r"(a0), "r"(a1), "r"(a2), "r"(a3), "r"(b0), "r"(b1));
}

// ---------------- init ----------------
__global__ void k_zero() {
    size_t i = (size_t)blockIdx.x*blockDim.x + threadIdx.x;
    size_t st = (size_t)gridDim.x*blockDim.x;
    for (size_t j=i; j<(size_t)BN*XGP; j+=st) g_xg[j] = 0.f;
    for (size_t j=i; j<BN*HID; j+=st) g_h[j]  = 0.f;
    for (size_t j=i; j<BN;     j+=st) g_go[j] = 0.f;
}

// ---------------- supports ----------------
__global__ void k_support_en(const float* __restrict__ emb) {
    int n = blockIdx.x, tid = threadIdx.x;
    __shared__ float embn[EMB];
    __shared__ float row[NN];
    __shared__ float red[256];
    if (tid < EMB) embn[tid] = emb[n*EMB + tid];
    __syncthreads();
    for (int m=tid; m<NN; m+=256) {
        float s = 0.f;
        #pragma unroll
        for (int e=0; e<EMB; e++) s += embn[e]*emb[m*EMB+e];
        row[m] = fmaxf(s, 0.f);
    }
    __syncthreads();
    float lm = -1e30f;
    for (int m=tid; m<NN; m+=256) lm = fmaxf(lm, row[m]);
    red[tid]=lm; __syncthreads();
    for (int s=128;s>0;s>>=1){ if(tid<s) red[tid]=fmaxf(red[tid],red[tid+s]); __syncthreads(); }
    float mx = red[0]; __syncthreads();
    float ls = 0.f;
    for (int m=tid; m<NN; m+=256){ float e=expf(row[m]-mx); row[m]=e; ls+=e; }
    red[tid]=ls; __syncthreads();
    for (int s=128;s>0;s>>=1){ if(tid<s) red[tid]+=red[tid+s]; __syncthreads(); }
    float inv = 1.f/red[0];
    for (int m=tid; m<NN; m+=256) g_sup_en[n*NN+m] = row[m]*inv;
}

__global__ void k_support_de() {
    int bn = blockIdx.x;
    int b = bn >> 9, n = bn & 511;
    int tid = threadIdx.x;
    const float* neb = g_ne + (size_t)b*NN*EMB;
    __shared__ float embn[EMB];
    __shared__ float row[NN];
    __shared__ float red[256];
    if (tid < EMB) embn[tid] = neb[n*EMB + tid];
    __syncthreads();
    for (int m=tid; m<NN; m+=256) {
        float s = 0.f;
        #pragma unroll
        for (int e=0; e<EMB; e++) s += embn[e]*neb[m*EMB+e];
        row[m] = fmaxf(s, 0.f);
    }
    __syncthreads();
    float lm = -1e30f;
    for (int m=tid; m<NN; m+=256) lm = fmaxf(lm, row[m]);
    red[tid]=lm; __syncthreads();
    for (int s=128;s>0;s>>=1){ if(tid<s) red[tid]=fmaxf(red[tid],red[tid+s]); __syncthreads(); }
    float mx = red[0]; __syncthreads();
    float ls = 0.f;
    for (int m=tid; m<NN; m+=256){ float e=expf(row[m]-mx); row[m]=e; ls+=e; }
    red[tid]=ls; __syncthreads();
    for (int s=128;s>0;s>>=1){ if(tid<s) red[tid]+=red[tid+s]; __syncthreads(); }
    float inv = 1.f/red[0];
    float* outr = g_sup_de + (size_t)b*NN*NN + (size_t)n*NN;
    for (int m=tid; m<NN; m+=256) outr[m] = row[m]*inv;
}

// ---------------- encoder x-feature precompute ------------------------------
__global__ void __launch_bounds__(256) k_pre_enc(const float* __restrict__ x, int phase) {
    __shared__ float xsh[512*24];
    int b = blockIdx.y, m0 = blockIdx.x*64;
    int tid = threadIdx.x;
    for (int idx = tid; idx < 512*24; idx += 256) {
        int k = idx/24, tc = idx%24;
        float v;
        if (phase == 1) { int t = tc>>1, c = tc&1; v = x[(((size_t)b*TT+t)*NN + k)*2 + c]; }
        else            v = g_xf1[((size_t)b*NN + k)*24 + tc];
        xsh[idx] = v;
    }
    __syncthreads();
    int row = m0 + (tid>>2);
    int g   = (tid&3)*6;
    float acc[6] = {};
    const float* Srow = g_sup_en + (size_t)row*NN;
    for (int k=0; k<NN; k+=4) {
        float4 s = *(const float4*)&Srow[k];
        #pragma unroll
        for (int j=0;j<6;j++) {
            acc[j] += s.x*xsh[(k+0)*24 + g + j] + s.y*xsh[(k+1)*24 + g + j]
                    + s.z*xsh[(k+2)*24 + g + j] + s.w*xsh[(k+3)*24 + g + j];
        }
    }
    #pragma unroll
    for (int j=0;j<6;j++) {
        int col = g + j;
        if (phase == 1) g_xf1[((size_t)b*NN + row)*24 + col] = acc[j];
        else {
            int t = col>>1, c = col&1;
            g_xf2[((size_t)b*NN + row)*24 + col] =
                2.f*acc[j] - x[(((size_t)b*TT+t)*NN + row)*2 + c];
        }
    }
}

// ---------------- decoder ycov-feature precompute ---------------------------
__global__ void __launch_bounds__(256) k_pre_dec(const float* __restrict__ ycov, int phase) {
    __shared__ float ysh[512*12];
    int b = blockIdx.y, m0 = blockIdx.x*64;
    int tid = threadIdx.x;
    for (int idx = tid; idx < 512*12; idx += 256) {
        int k = idx/12, t = idx%12;
        float v;
        if (phase == 1) v = ycov[((size_t)b*TT+t)*NN + k];
        else            v = g_yf1[((size_t)b*NN + k)*12 + t];
        ysh[idx] = v;
    }
    __syncthreads();
    int row = m0 + (tid>>2);
    int g   = (tid&3)*3;
    float acc[3] = {};
    const float* Srow = g_sup_de + (size_t)b*NN*NN + (size_t)row*NN;
    for (int k=0; k<NN; k+=4) {
        float4 s = *(const float4*)&Srow[k];
        #pragma unroll
        for (int j=0;j<3;j++) {
            acc[j] += s.x*ysh[(k+0)*12 + g + j] + s.y*ysh[(k+1)*12 + g + j]
                    + s.z*ysh[(k+2)*12 + g + j] + s.w*ysh[(k+3)*12 + g + j];
        }
    }
    #pragma unroll
    for (int j=0;j<3;j++) {
        int t = g + j;
        if (phase == 1) g_yf1[((size_t)b*NN + row)*12 + t] = acc[j];
        else            g_yf2[((size_t)b*NN + row)*12 + t] =
                            2.f*acc[j] - ycov[((size_t)b*TT+t)*NN + row];
    }
}

// ---------------- decoder go mat-vecs ---------------------------------------
__global__ void __launch_bounds__(256) k_mv_go(int phase) {
    __shared__ float gsh[NN];
    int b = blockIdx.y;
    int tid = threadIdx.x, lane = tid & 31, w = tid >> 5;
    int row = blockIdx.x*8 + w;
    const float* src = (phase == 1) ? g_go : g_tmp;
    gsh[tid]       = src[(size_t)b*NN + tid];
    gsh[tid + 256] = src[(size_t)b*NN + tid + 256];
    __syncthreads();
    const float* Srow = g_sup_de + (size_t)b*NN*NN + (size_t)row*NN;
    float acc = 0.f;
    #pragma unroll
    for (int i=0;i<4;i++) {
        int k = lane*4 + 128*i;
        float4 s = *(const float4*)&Srow[k];
        acc += s.x*gsh[k] + s.y*gsh[k+1] + s.z*gsh[k+2] + s.w*gsh[k+3];
    }
    #pragma unroll
    for (int o=16;o>0;o>>=1) acc += __shfl_xor_sync(0xffffffffu, acc, o);
    if (lane == 0) {
        size_t bn = (size_t)b*NN + row;
        if (phase == 1) { g_tmp[bn] = acc; g_xg[bn*XGP + 194] = acc; }
        else            g_xg[bn*XGP + 196] = 2.f*acc - g_go[bn];
    }
}

// ---------------- builders ---------------------------------------------------
__global__ void k_build_enc(const float* __restrict__ x, int t) {
    int bn = blockIdx.x*blockDim.x + threadIdx.x;
    if (bn >= BN) return;
    int b = bn >> 9, n = bn & 511;
    float* f = &g_xg[(size_t)bn*XGP];
    const float* xp = &x[(((size_t)b*TT+t)*NN + n)*2];
    f[192] = xp[0];
    f[193] = xp[1];
    f[194] = g_xf1[(size_t)bn*24 + t*2 + 0];
    f[195] = g_xf1[(size_t)bn*24 + t*2 + 1];
    f[196] = g_xf2[(size_t)bn*24 + t*2 + 0];
    f[197] = g_xf2[(size_t)bn*24 + t*2 + 1];
}

__global__ void k_build_dec(const float* __restrict__ ycov, int t) {
    int bn = blockIdx.x*blockDim.x + threadIdx.x;
    if (bn >= BN) return;
    int b = bn >> 9, n = bn & 511;
    float* f = &g_xg[(size_t)bn*XGP];
    f[192] = g_go[bn];
    f[193] = ycov[((size_t)b*TT+t)*NN + n];
    f[195] = g_yf1[(size_t)bn*12 + t];
    f[197] = g_yf2[(size_t)bn*12 + t];
}

// ---------------- h-chain spmm via TF32 tensor-core MMA ---------------------
// CTA: 128 rows x 64 cols, K=512, chunks of 16. 8 warps = 4(M) x 2(N).
// Warp tile 32x32 -> A frags 2 (m16k8), B frags 4 (k8n8), acc 2x4 m16n8.
// A smem [row][k] pitch 20 (conflict-free for frag reads);
// B smem [k][n] pitch 72 (conflict-free).
__global__ void __launch_bounds__(256) k_spmm(int deFlag, int cheb) {
    __shared__ unsigned As[2][128*20];
    __shared__ unsigned Bs[2][16*72];
    const int b   = blockIdx.y;
    const int m0  = blockIdx.x*128;
    const int tid = threadIdx.x;
    const int warp = tid >> 5, lane = tid & 31;
    const int mw = warp & 3, nw = warp >> 2;
    const int tq = lane >> 2, tr = lane & 3;
    const float* Sb = deFlag ? g_sup_de + (size_t)b*NN*NN : g_sup_en;
    float* Xg = g_xg + (size_t)b*NN*XGP;
    const int inOff  = (cheb == 1) ? 0  : 64;
    const int outOff = (cheb == 1) ? 64 : 128;

    // loader indices
    const int lr = tid >> 1, lc = (tid & 1)*8;   // A: row, col(0|8)
    const int bk = tid >> 4, bn = (tid & 15)*4;  // B: k, n

    float4 aR0, aR1, bR;
    float acc[2][4][4] = {};

#define SP_LDG(k0) do { \
    aR0 = *(const float4*)&Sb[(size_t)(m0+lr)*NN + (k0) + lc]; \
    aR1 = *(const float4*)&Sb[(size_t)(m0+lr)*NN + (k0) + lc + 4]; \
    bR  = *(const float4*)&Xg[(size_t)((k0)+bk)*XGP + inOff + bn]; \
} while(0)
#define SP_STS(bf) do { \
    unsigned* ap = &As[bf][lr*20 + lc]; \
    ap[0]=f2tf(aR0.x); ap[1]=f2tf(aR0.y); ap[2]=f2tf(aR0.z); ap[3]=f2tf(aR0.w); \
    ap[4]=f2tf(aR1.x); ap[5]=f2tf(aR1.y); ap[6]=f2tf(aR1.z); ap[7]=f2tf(aR1.w); \
    unsigned* bp = &Bs[bf][bk*72 + bn]; \
    bp[0]=f2tf(bR.x); bp[1]=f2tf(bR.y); bp[2]=f2tf(bR.z); bp[3]=f2tf(bR.w); \
} while(0)

    SP_LDG(0); SP_STS(0); __syncthreads();
    for (int kt = 0; kt < 32; kt++) {
        int buf = kt & 1;
        if (kt < 31) SP_LDG((kt+1)*16);
        #pragma unroll
        for (int ks = 0; ks < 16; ks += 8) {
            unsigned a[2][4], bb[4][2];
            #pragma unroll
            for (int mi = 0; mi < 2; mi++) {
                int r = mw*32 + mi*16 + tq;
                a[mi][0] = As[buf][r*20 + ks + tr];
                a[mi][1] = As[buf][(r+8)*20 + ks + tr];
                a[mi][2] = As[buf][r*20 + ks + tr + 4];
                a[mi][3] = As[buf][(r+8)*20 + ks + tr + 4];
            }
            #pragma unroll
            for (int nj = 0; nj < 4; nj++) {
                int c = nw*32 + nj*8 + tq;
                bb[nj][0] = Bs[buf][(ks+tr)*72 + c];
                bb[nj][1] = Bs[buf][(ks+tr+4)*72 + c];
            }
            #pragma unroll
            for (int mi = 0; mi < 2; mi++)
                #pragma unroll
                for (int nj = 0; nj < 4; nj++)
                    mma_tf32(acc[mi][nj], a[mi][0], a[mi][1], a[mi][2], a[mi][3],
                             bb[nj][0], bb[nj][1]);
        }
        if (kt < 31) SP_STS(buf^1);
        __syncthreads();
    }

    #pragma unroll
    for (int mi = 0; mi < 2; mi++) {
        int r0 = m0 + mw*32 + mi*16 + tq;
        #pragma unroll
        for (int nj = 0; nj < 4; nj++) {
            int c = nw*32 + nj*8 + tr*2;
            float2 v0 = make_float2(acc[mi][nj][0], acc[mi][nj][1]);
            float2 v1 = make_float2(acc[mi][nj][2], acc[mi][nj][3]);
            if (cheb == 2) {
                float2 x0 = *(const float2*)&Xg[(size_t)r0*XGP + c];
                float2 x1 = *(const float2*)&Xg[(size_t)(r0+8)*XGP + c];
                v0.x = 2.f*v0.x - x0.x; v0.y = 2.f*v0.y - x0.y;
                v1.x = 2.f*v1.x - x1.x; v1.y = 2.f*v1.y - x1.y;
            }
            *(float2*)&Xg[(size_t)r0*XGP + outOff + c]     = v0;
            *(float2*)&Xg[(size_t)(r0+8)*XGP + outOff + c] = v1;
        }
    }
#undef SP_LDG
#undef SP_STS
}

// ---------------- gate GEMM: 128x128 tile, micro 8x8 (scalar fp32) ----------
__global__ void __launch_bounds__(256) k_gate(const float* __restrict__ W,
                                              const float* __restrict__ bias) {
    __shared__ float Ash[2][16][132];
    __shared__ float Bsh[2][16][132];
    const int m0 = blockIdx.x*128;
    const int tid = threadIdx.x;
    const int tx = tid & 15, ty = tid >> 4;
    const int rwA = tid >> 2, kqA = (tid & 3)*4;
    const int kkB = tid >> 5, oqB = (tid & 31)*4;
    float4 aA0, aA1, bB0, bB1;
    float acc[8][8] = {};

#define GT_LDG(k0) do { \
    aA0 = ((k0)+kqA < XGP) ? *(const float4*)&g_xg[(size_t)(m0+rwA)*XGP + (k0) + kqA] : make_float4(0,0,0,0); \
    aA1 = ((k0)+kqA < XGP) ? *(const float4*)&g_xg[(size_t)(m0+rwA+64)*XGP + (k0) + kqA] : make_float4(0,0,0,0); \
    bB0 = *(const float4*)&W[(size_t)wmap((k0)+kkB)*128 + oqB]; \
    bB1 = *(const float4*)&W[(size_t)wmap((k0)+kkB+8)*128 + oqB]; \
} while(0)
#define GT_STS(bf) do { \
    Ash[bf][kqA+0][rwA]=aA0.x; Ash[bf][kqA+1][rwA]=aA0.y; \
    Ash[bf][kqA+2][rwA]=aA0.z; Ash[bf][kqA+3][rwA]=aA0.w; \
    Ash[bf][kqA+0][rwA+64]=aA1.x; Ash[bf][kqA+1][rwA+64]=aA1.y; \
    Ash[bf][kqA+2][rwA+64]=aA1.z; Ash[bf][kqA+3][rwA+64]=aA1.w; \
    *(float4*)&Bsh[bf][kkB][oqB]   = bB0; \
    *(float4*)&Bsh[bf][kkB+8][oqB] = bB1; \
} while(0)

    GT_LDG(0); GT_STS(0); __syncthreads();
    for (int kt = 0; kt < 13; kt++) {
        int buf = kt & 1;
        if (kt < 12) GT_LDG((kt+1)*16);
        #pragma unroll
        for (int k = 0; k < 16; k++) {
            float4 a0 = *(const float4*)&Ash[buf][k][8*ty];
            float4 a1 = *(const float4*)&Ash[buf][k][8*ty+4];
            float4 b0 = *(const float4*)&Bsh[buf][k][8*tx];
            float4 b1 = *(const float4*)&Bsh[buf][k][8*tx+4];
            float av[8] = {a0.x,a0.y,a0.z,a0.w,a1.x,a1.y,a1.z,a1.w};
            float bv[8] = {b0.x,b0.y,b0.z,b0.w,b1.x,b1.y,b1.z,b1.w};
            #pragma unroll
            for (int i=0;i<8;i++)
                #pragma unroll
                for (int j=0;j<8;j++) acc[i][j] += av[i]*bv[j];
        }
        if (kt < 12) GT_STS(buf^1);
        __syncthreads();
    }
    #pragma unroll
    for (int i = 0; i < 8; i++) {
        int row = m0 + 8*ty + i;
        #pragma unroll
        for (int j = 0; j < 8; j++) {
            int o = 8*tx + j;
            float v = 1.f/(1.f + expf(-(acc[i][j] + bias[o])));
            if (o < 64) g_xg[(size_t)row*XGP + o] = v * g_h[(size_t)row*HID + o];
            else        g_r[(size_t)row*HID + (o-64)] = v;
        }
    }
#undef GT_LDG
#undef GT_STS
}

// ---------------- update GEMM: 128x64 tile, micro 8x4 (scalar fp32) ---------
__global__ void __launch_bounds__(256) k_upd(const float* __restrict__ W,
                                             const float* __restrict__ bias) {
    __shared__ float Ash[2][16][132];
    __shared__ float Bsh[2][16][68];
    const int m0 = blockIdx.x*128;
    const int tid = threadIdx.x;
    const int tx = tid & 15, ty = tid >> 4;
    const int rwA = tid >> 2, kqA = (tid & 3)*4;
    const int kkB = tid >> 4, oqB = (tid & 15)*4;
    float4 aA0, aA1, bB0;
    float acc[8][4] = {};

#define UP_LDG(k0) do { \
    aA0 = ((k0)+kqA < XGP) ? *(const float4*)&g_xg[(size_t)(m0+rwA)*XGP + (k0) + kqA] : make_float4(0,0,0,0); \
    aA1 = ((k0)+kqA < XGP) ? *(const float4*)&g_xg[(size_t)(m0+rwA+64)*XGP + (k0) + kqA] : make_float4(0,0,0,0); \
    bB0 = *(const float4*)&W[(size_t)wmap((k0)+kkB)*64 + oqB]; \
} while(0)
#define UP_STS(bf) do { \
    Ash[bf][kqA+0][rwA]=aA0.x; Ash[bf][kqA+1][rwA]=aA0.y; \
    Ash[bf][kqA+2][rwA]=aA0.z; Ash[bf][kqA+3][rwA]=aA0.w; \
    Ash[bf][kqA+0][rwA+64]=aA1.x; Ash[bf][kqA+1][rwA+64]=aA1.y; \
    Ash[bf][kqA+2][rwA+64]=aA1.z; Ash[bf][kqA+3][rwA+64]=aA1.w; \
    *(float4*)&Bsh[bf][kkB][oqB] = bB0; \
} while(0)

    UP_LDG(0); UP_STS(0); __syncthreads();
    for (int kt = 0; kt < 13; kt++) {
        int buf = kt & 1;
        if (kt < 12) UP_LDG((kt+1)*16);
        #pragma unroll
        for (int k = 0; k < 16; k++) {
            float4 a0 = *(const float4*)&Ash[buf][k][8*ty];
            float4 a1 = *(const float4*)&Ash[buf][k][8*ty+4];
            float4 bv = *(const float4*)&Bsh[buf][k][4*tx];
            acc[0][0]+=a0.x*bv.x; acc[0][1]+=a0.x*bv.y; acc[0][2]+=a0.x*bv.z; acc[0][3]+=a0.x*bv.w;
            acc[1][0]+=a0.y*bv.x; acc[1][1]+=a0.y*bv.y; acc[1][2]+=a0.y*bv.z; acc[1][3]+=a0.y*bv.w;
            acc[2][0]+=a0.z*bv.x; acc[2][1]+=a0.z*bv.y; acc[2][2]+=a0.z*bv.z; acc[2][3]+=a0.z*bv.w;
            acc[3][0]+=a0.w*bv.x; acc[3][1]+=a0.w*bv.y; acc[3][2]+=a0.w*bv.z; acc[3][3]+=a0.w*bv.w;
            acc[4][0]+=a1.x*bv.x; acc[4][1]+=a1.x*bv.y; acc[4][2]+=a1.x*bv.z; acc[4][3]+=a1.x*bv.w;
            acc[5][0]+=a1.y*bv.x; acc[5][1]+=a1.y*bv.y; acc[5][2]+=a1.y*bv.z; acc[5][3]+=a1.y*bv.w;
            acc[6][0]+=a1.z*bv.x; acc[6][1]+=a1.z*bv.y; acc[6][2]+=a1.z*bv.z; acc[6][3]+=a1.z*bv.w;
            acc[7][0]+=a1.w*bv.x; acc[7][1]+=a1.w*bv.y; acc[7][2]+=a1.w*bv.z; acc[7][3]+=a1.w*bv.w;
        }
        if (kt < 12) UP_STS(buf^1);
        __syncthreads();
    }
    #pragma unroll
    for (int i = 0; i < 8; i++) {
        int row = m0 + 8*ty + i;
        #pragma unroll
        for (int j = 0; j < 4; j++) {
            int o = 4*tx + j;
            float hc = tanhf(acc[i][j] + bias[o]);
            float r  = g_r[(size_t)row*HID + o];
            float h  = g_h[(size_t)row*HID + o];
            float hn = r*h + (1.f - r)*hc;
            g_h[(size_t)row*HID + o] = hn;
            g_xg[(size_t)row*XGP + o] = hn;
        }
    }
#undef UP_LDG
#undef UP_STS
}

// ---------------- hyper projection ------------------------------------------
__global__ void k_hyper(const float* __restrict__ hW, const float* __restrict__ hb) {
    int idx = blockIdx.x*blockDim.x + threadIdx.x;
    if (idx >= BN*EMB) return;
    int bn = idx / EMB, e = idx % EMB;
    float s = hb[e];
    #pragma unroll
    for (int k = 0; k < HID; k++) s += g_h[(size_t)bn*HID + k] * hW[k*EMB + e];
    g_ne[idx] = s;
}

// ---------------- output projection -----------------------------------------
__global__ void k_proj(const float* __restrict__ pW, const float* __restrict__ pb,
                       float* __restrict__ out, int t) {
    int gtid = blockIdx.x*blockDim.x + threadIdx.x;
    int warp = gtid >> 5;
    int lane = threadIdx.x & 31;
    if (warp >= BN) return;
    float s = g_h[(size_t)warp*64 + lane]      * pW[lane]
            + g_h[(size_t)warp*64 + 32 + lane] * pW[32 + lane];
    #pragma unroll
    for (int o = 16; o > 0; o >>= 1) s += __shfl_xor_sync(0xffffffffu, s, o);
    if (lane == 0) {
        float go = s + pb[0];
        g_go[warp] = go;
        int b = warp >> 9, n = warp & 511;
        out[((size_t)b*TT + t)*NN + n] = go;
    }
}

// ---------------- orchestration ---------------------------------------------
extern "C" void kernel_launch(void* const* d_in, const int* in_sizes, int n_in,
                              void* d_out, int out_size) {
    const float* x       = (const float*)d_in[0];
    const float* ycov    = (const float*)d_in[1];
    const float* emb     = (const float*)d_in[2];
    const float* enc_gW  = (const float*)d_in[3];
    const float* enc_gb  = (const float*)d_in[4];
    const float* enc_uW  = (const float*)d_in[5];
    const float* enc_ub  = (const float*)d_in[6];
    const float* dec_gW  = (const float*)d_in[7];
    const float* dec_gb  = (const float*)d_in[8];
    const float* dec_uW  = (const float*)d_in[9];
    const float* dec_ub  = (const float*)d_in[10];
    const float* proj_W  = (const float*)d_in[11];
    const float* proj_b  = (const float*)d_in[12];
    const float* hyper_W = (const float*)d_in[13];
    const float* hyper_b = (const float*)d_in[14];
    float* out = (float*)d_out;

    dim3 gs_spmm(4, BB);
    dim3 gs_pre(8, BB);
    dim3 gs_mv(64, BB);
    int  gs_gate = BN/128;
    int  gs_upd  = BN/128;
    int  nb2 = (BN + 255)/256;

    k_zero<<<1024, 256>>>();
    k_support_en<<<NN, 256>>>(emb);
    k_pre_enc<<<gs_pre, 256>>>(x, 1);
    k_pre_enc<<<gs_pre, 256>>>(x, 2);

    for (int t = 0; t < TT; t++) {
        k_build_enc<<<nb2, 256>>>(x, t);
        k_spmm<<<gs_spmm, 256>>>(0, 1);
        k_spmm<<<gs_spmm, 256>>>(0, 2);
        k_gate<<<gs_gate, 256>>>(enc_gW, enc_gb);
        k_spmm<<<gs_spmm, 256>>>(0, 1);
        k_spmm<<<gs_spmm, 256>>>(0, 2);
        k_upd<<<gs_upd, 256>>>(enc_uW, enc_ub);
    }

    k_hyper<<<(BN*EMB + 255)/256, 256>>>(hyper_W, hyper_b);
    k_support_de<<<BN, 256>>>();
    k_pre_dec<<<gs_pre, 256>>>(ycov, 1);
    k_pre_dec<<<gs_pre, 256>>>(ycov, 2);

    for (int t = 0; t < TT; t++) {
        k_build_dec<<<nb2, 256>>>(ycov, t);
        k_mv_go<<<gs_mv, 256>>>(1);
        k_mv_go<<<gs_mv, 256>>>(2);
        k_spmm<<<gs_spmm, 256>>>(1, 1);
        k_spmm<<<gs_spmm, 256>>>(1, 2);
        k_gate<<<gs_gate, 256>>>(dec_gW, dec_gb);
        k_spmm<<<gs_spmm, 256>>>(1, 1);
        k_spmm<<<gs_spmm, 256>>>(1, 2);
        k_upd<<<gs_upd, 256>>>(dec_uW, dec_ub);
        k_proj<<<(BN*32 + 255)/256, 256>>>(proj_W, proj_b, out, t);
    }
}

// round 6
// speedup vs baseline: 2.1767x; 1.2603x over previous
#include <cuda_runtime.h>
#include <math.h>

// ---------------- problem constants ----------------
#define BB   32
#define TT   12
#define NN   512
#define HID  64
#define EMB  10
#define BN   (BB*NN)     // 16384

// feature row layout, stride XGP=208:
//  [0..63]    X      (h or z*h)   <-> W rows 2..65
//  [64..127]  S@X                 <-> W rows 68..131
//  [128..191] 2S(S@X)-X           <-> W rows 134..197
//  [192..197] [x0,x1,Sx0,Sx1,S2x0,S2x1] <-> W rows 0,1,66,67,132,133
//  [198..207] pad (always 0)
#define XGP  208

// ---------------- device scratch ----------------
__device__ float g_h[BN*HID];
__device__ float g_r[BN*HID];
__device__ float g_xg[(size_t)BN*XGP];
__device__ float g_sup_en[NN*NN];
__device__ float g_sup_de[(size_t)BB*NN*NN];
__device__ float g_ne[BN*EMB];
__device__ float g_go[BN];
__device__ float g_tmp[BN];
__device__ float g_xf1[BN*24];
__device__ float g_xf2[BN*24];
__device__ float g_yf1[BN*TT];
__device__ float g_yf2[BN*TT];
// reordered + tf32-rounded weights, feature-column order, 208 rows
__device__ float g_Wge[208*128];
__device__ float g_Wgd[208*128];
__device__ float g_Wue[208*64];
__device__ float g_Wud[208*64];

// feature col -> original W row
__device__ __forceinline__ int wmap(int c) {
    if (c < 64)  return c + 2;
    if (c < 128) return c + 4;
    if (c < 192) return c + 6;
    return ((c - 192) >> 1) * 66 + (c & 1);
}

// ---------------- tf32 helpers ----------------
__device__ __forceinline__ unsigned f2tf(float f) {
    unsigned u;
    asm("cvt.rna.tf32.f32 %0, %1;" : "=r"(u) : "f"(f));
    return u;
}
__device__ __forceinline__ float tf32r(float f) { return __uint_as_float(f2tf(f)); }

__device__ __forceinline__ void mma_tf32(float* d,
    unsigned a0, unsigned a1, unsigned a2, unsigned a3,
    unsigned b0, unsigned b1) {
    asm volatile(
        "mma.sync.aligned.m16n8k8.row.col.f32.tf32.tf32.f32 "
        "{%0,%1,%2,%3}, {%4,%5,%6,%7}, {%8,%9}, {%0,%1,%2,%3};\n"
        : "+f"(d[0]), "+f"(d[1]), "+f"(d[2]), "+f"(d[3])
        : "r"(a0), "r"(a1), "r"(a2), "r"(a3), "r"(b0), "r"(b1));
}

__device__ __forceinline__ void cpa16(void* smem, const void* g) {
    unsigned s = (unsigned)__cvta_generic_to_shared(smem);
    asm volatile("cp.async.cg.shared.global [%0], [%1], 16;\n" :: "r"(s), "l"(g));
}
#define CP_COMMIT() asm volatile("cp.async.commit_group;\n" ::: "memory")
#define CP_WAIT1()  asm volatile("cp.async.wait_group 1;\n" ::: "memory")

// ---------------- init ----------------
__global__ void k_zero() {
    size_t i = (size_t)blockIdx.x*blockDim.x + threadIdx.x;
    size_t st = (size_t)gridDim.x*blockDim.x;
    for (size_t j=i; j<(size_t)BN*XGP; j+=st) g_xg[j] = 0.f;
    for (size_t j=i; j<BN*HID; j+=st) g_h[j]  = 0.f;
    for (size_t j=i; j<BN;     j+=st) g_go[j] = 0.f;
}

// ---------------- weight reorder + round (selector: 0=ge,1=gd,2=ue,3=ud) ----
__global__ void k_prep(const float* __restrict__ W, int which) {
    int nc = (which < 2) ? 128 : 64;
    float* dst = (which == 0) ? g_Wge : (which == 1) ? g_Wgd
               : (which == 2) ? g_Wue : g_Wud;
    int idx = blockIdx.x*blockDim.x + threadIdx.x;
    if (idx >= 208*nc) return;
    int c = idx / nc, o = idx - c*nc;
    float v = 0.f;
    if (c < 198) v = W[wmap(c)*nc + o];
    dst[idx] = tf32r(v);
}

// ---------------- supports (emit tf32-rounded) ----------------
__global__ void k_support_en(const float* __restrict__ emb) {
    int n = blockIdx.x, tid = threadIdx.x;
    __shared__ float embn[EMB];
    __shared__ float row[NN];
    __shared__ float red[256];
    if (tid < EMB) embn[tid] = emb[n*EMB + tid];
    __syncthreads();
    for (int m=tid; m<NN; m+=256) {
        float s = 0.f;
        #pragma unroll
        for (int e=0; e<EMB; e++) s += embn[e]*emb[m*EMB+e];
        row[m] = fmaxf(s, 0.f);
    }
    __syncthreads();
    float lm = -1e30f;
    for (int m=tid; m<NN; m+=256) lm = fmaxf(lm, row[m]);
    red[tid]=lm; __syncthreads();
    for (int s=128;s>0;s>>=1){ if(tid<s) red[tid]=fmaxf(red[tid],red[tid+s]); __syncthreads(); }
    float mx = red[0]; __syncthreads();
    float ls = 0.f;
    for (int m=tid; m<NN; m+=256){ float e=expf(row[m]-mx); row[m]=e; ls+=e; }
    red[tid]=ls; __syncthreads();
    for (int s=128;s>0;s>>=1){ if(tid<s) red[tid]+=red[tid+s]; __syncthreads(); }
    float inv = 1.f/red[0];
    for (int m=tid; m<NN; m+=256) g_sup_en[n*NN+m] = tf32r(row[m]*inv);
}

__global__ void k_support_de() {
    int bn = blockIdx.x;
    int b = bn >> 9, n = bn & 511;
    int tid = threadIdx.x;
    const float* neb = g_ne + (size_t)b*NN*EMB;
    __shared__ float embn[EMB];
    __shared__ float row[NN];
    __shared__ float red[256];
    if (tid < EMB) embn[tid] = neb[n*EMB + tid];
    __syncthreads();
    for (int m=tid; m<NN; m+=256) {
        float s = 0.f;
        #pragma unroll
        for (int e=0; e<EMB; e++) s += embn[e]*neb[m*EMB+e];
        row[m] = fmaxf(s, 0.f);
    }
    __syncthreads();
    float lm = -1e30f;
    for (int m=tid; m<NN; m+=256) lm = fmaxf(lm, row[m]);
    red[tid]=lm; __syncthreads();
    for (int s=128;s>0;s>>=1){ if(tid<s) red[tid]=fmaxf(red[tid],red[tid+s]); __syncthreads(); }
    float mx = red[0]; __syncthreads();
    float ls = 0.f;
    for (int m=tid; m<NN; m+=256){ float e=expf(row[m]-mx); row[m]=e; ls+=e; }
    red[tid]=ls; __syncthreads();
    for (int s=128;s>0;s>>=1){ if(tid<s) red[tid]+=red[tid+s]; __syncthreads(); }
    float inv = 1.f/red[0];
    float* outr = g_sup_de + (size_t)b*NN*NN + (size_t)n*NN;
    for (int m=tid; m<NN; m+=256) outr[m] = tf32r(row[m]*inv);
}

// ---------------- encoder x-feature precompute (k-split + shfl) -------------
__global__ void __launch_bounds__(256) k_pre_enc(const float* __restrict__ x, int phase) {
    __shared__ float xsh[512*24];
    int b = blockIdx.y, m0 = blockIdx.x*32;
    int tid = threadIdx.x;
    for (int idx = tid; idx < 512*24; idx += 256) {
        int k = idx/24, tc = idx%24;
        float v;
        if (phase == 1) { int t = tc>>1, c = tc&1; v = x[(((size_t)b*TT+t)*NN + k)*2 + c]; }
        else            v = g_xf1[((size_t)b*NN + k)*24 + tc];
        xsh[idx] = v;
    }
    __syncthreads();
    int rl = tid>>3, kh = (tid>>2)&1, cg = tid&3;
    int row = m0 + rl, g = cg*6;
    float acc[6] = {};
    const float* Srow = g_sup_en + (size_t)row*NN + kh*256;
    const float* xp = &xsh[kh*256*24];
    for (int k=0;k<256;k+=4){
        float4 s = *(const float4*)&Srow[k];
        #pragma unroll
        for (int j=0;j<6;j++)
            acc[j] += s.x*xp[(k+0)*24+g+j] + s.y*xp[(k+1)*24+g+j]
                    + s.z*xp[(k+2)*24+g+j] + s.w*xp[(k+3)*24+g+j];
    }
    #pragma unroll
    for (int j=0;j<6;j++) acc[j] += __shfl_xor_sync(0xffffffffu, acc[j], 4);
    if (kh == 0) {
        #pragma unroll
        for (int j=0;j<6;j++) {
            int col = g + j;
            if (phase == 1) g_xf1[((size_t)b*NN + row)*24 + col] = acc[j];
            else {
                int t = col>>1, c = col&1;
                g_xf2[((size_t)b*NN + row)*24 + col] =
                    2.f*acc[j] - x[(((size_t)b*TT+t)*NN + row)*2 + c];
            }
        }
    }
}

// ---------------- decoder ycov-feature precompute ---------------------------
__global__ void __launch_bounds__(256) k_pre_dec(const float* __restrict__ ycov, int phase) {
    __shared__ float ysh[512*12];
    int b = blockIdx.y, m0 = blockIdx.x*32;
    int tid = threadIdx.x;
    for (int idx = tid; idx < 512*12; idx += 256) {
        int k = idx/12, t = idx%12;
        float v;
        if (phase == 1) v = ycov[((size_t)b*TT+t)*NN + k];
        else            v = g_yf1[((size_t)b*NN + k)*12 + t];
        ysh[idx] = v;
    }
    __syncthreads();
    int rl = tid>>3, kh = (tid>>2)&1, cg = tid&3;
    int row = m0 + rl, g = cg*3;
    float acc[3] = {};
    const float* Srow = g_sup_de + (size_t)b*NN*NN + (size_t)row*NN + kh*256;
    const float* yp = &ysh[kh*256*12];
    for (int k=0;k<256;k+=4){
        float4 s = *(const float4*)&Srow[k];
        #pragma unroll
        for (int j=0;j<3;j++)
            acc[j] += s.x*yp[(k+0)*12+g+j] + s.y*yp[(k+1)*12+g+j]
                    + s.z*yp[(k+2)*12+g+j] + s.w*yp[(k+3)*12+g+j];
    }
    #pragma unroll
    for (int j=0;j<3;j++) acc[j] += __shfl_xor_sync(0xffffffffu, acc[j], 4);
    if (kh == 0) {
        #pragma unroll
        for (int j=0;j<3;j++) {
            int t = g + j;
            if (phase == 1) g_yf1[((size_t)b*NN + row)*12 + t] = acc[j];
            else            g_yf2[((size_t)b*NN + row)*12 + t] =
                                2.f*acc[j] - ycov[((size_t)b*TT+t)*NN + row];
        }
    }
}

// ---------------- decoder go mat-vecs ---------------------------------------
__global__ void __launch_bounds__(256) k_mv_go(int phase) {
    __shared__ float gsh[NN];
    int b = blockIdx.y;
    int tid = threadIdx.x, lane = tid & 31, w = tid >> 5;
    int row = blockIdx.x*8 + w;
    const float* src = (phase == 1) ? g_go : g_tmp;
    gsh[tid]       = src[(size_t)b*NN + tid];
    gsh[tid + 256] = src[(size_t)b*NN + tid + 256];
    __syncthreads();
    const float* Srow = g_sup_de + (size_t)b*NN*NN + (size_t)row*NN;
    float acc = 0.f;
    #pragma unroll
    for (int i=0;i<4;i++) {
        int k = lane*4 + 128*i;
        float4 s = *(const float4*)&Srow[k];
        acc += s.x*gsh[k] + s.y*gsh[k+1] + s.z*gsh[k+2] + s.w*gsh[k+3];
    }
    #pragma unroll
    for (int o=16;o>0;o>>=1) acc += __shfl_xor_sync(0xffffffffu, acc, o);
    if (lane == 0) {
        size_t bn = (size_t)b*NN + row;
        if (phase == 1) { g_tmp[bn] = acc; g_xg[bn*XGP + 194] = tf32r(acc); }
        else            g_xg[bn*XGP + 196] = tf32r(2.f*acc - g_go[bn]);
    }
}

// ---------------- builders ---------------------------------------------------
__global__ void k_build_enc(const float* __restrict__ x, int t) {
    int bn = blockIdx.x*blockDim.x + threadIdx.x;
    if (bn >= BN) return;
    int b = bn >> 9, n = bn & 511;
    float* f = &g_xg[(size_t)bn*XGP];
    const float* xp = &x[(((size_t)b*TT+t)*NN + n)*2];
    f[192] = tf32r(xp[0]);
    f[193] = tf32r(xp[1]);
    f[194] = tf32r(g_xf1[(size_t)bn*24 + t*2 + 0]);
    f[195] = tf32r(g_xf1[(size_t)bn*24 + t*2 + 1]);
    f[196] = tf32r(g_xf2[(size_t)bn*24 + t*2 + 0]);
    f[197] = tf32r(g_xf2[(size_t)bn*24 + t*2 + 1]);
}

__global__ void k_build_dec(const float* __restrict__ ycov, int t) {
    int bn = blockIdx.x*blockDim.x + threadIdx.x;
    if (bn >= BN) return;
    int b = bn >> 9, n = bn & 511;
    float* f = &g_xg[(size_t)bn*XGP];
    f[192] = tf32r(g_go[bn]);
    f[193] = tf32r(ycov[((size_t)b*TT+t)*NN + n]);
    f[195] = tf32r(g_yf1[(size_t)bn*12 + t]);
    f[197] = tf32r(g_yf2[(size_t)bn*12 + t]);
}

// ---------------- h-chain spmm: TF32 MMA, 3-stage cp.async ------------------
// CTA 128x64, K=512, k-tile 16. 8 warps = 4(M)x2(N), warp tile 32x32.
__global__ void __launch_bounds__(256) k_spmm(int deFlag, int cheb) {
    __shared__ float As[3][128*20];
    __shared__ float Bs[3][16*72];
    const int b   = blockIdx.y;
    const int m0  = blockIdx.x*128;
    const int tid = threadIdx.x;
    const int warp = tid >> 5, lane = tid & 31;
    const int mw = warp & 3, nw = warp >> 2;
    const int tq = lane >> 2, tr = lane & 3;
    const float* Sb = deFlag ? g_sup_de + (size_t)b*NN*NN : g_sup_en;
    float* Xg = g_xg + (size_t)b*NN*XGP;
    const int inOff  = (cheb == 1) ? 0  : 64;
    const int outOff = (cheb == 1) ? 64 : 128;

    const int lr = tid >> 1, lc = (tid & 1)*8;   // A loader
    const int bk = tid >> 4, bn = (tid & 15)*4;  // B loader

    float acc[2][4][4] = {};

#define SP_LOAD(st, k0) do { \
    cpa16(&As[st][lr*20+lc],   &Sb[(size_t)(m0+lr)*NN + (k0)+lc]); \
    cpa16(&As[st][lr*20+lc+4], &Sb[(size_t)(m0+lr)*NN + (k0)+lc+4]); \
    cpa16(&Bs[st][bk*72+bn],   &Xg[(size_t)((k0)+bk)*XGP + inOff + bn]); \
} while(0)

    SP_LOAD(0, 0);  CP_COMMIT();
    SP_LOAD(1, 16); CP_COMMIT();
    for (int kt = 0; kt < 32; kt++) {
        CP_WAIT1();
        __syncthreads();
        if (kt < 30) SP_LOAD((kt+2)%3, (kt+2)*16);
        CP_COMMIT();
        const float* Ab = As[kt%3];
        const float* Bb = Bs[kt%3];
        #pragma unroll
        for (int ks = 0; ks < 16; ks += 8) {
            unsigned a[2][4], bb[4][2];
            #pragma unroll
            for (int mi = 0; mi < 2; mi++) {
                int r = mw*32 + mi*16 + tq;
                a[mi][0] = __float_as_uint(Ab[r*20 + ks + tr]);
                a[mi][1] = __float_as_uint(Ab[(r+8)*20 + ks + tr]);
                a[mi][2] = __float_as_uint(Ab[r*20 + ks + tr + 4]);
                a[mi][3] = __float_as_uint(Ab[(r+8)*20 + ks + tr + 4]);
            }
            #pragma unroll
            for (int nj = 0; nj < 4; nj++) {
                int c = nw*32 + nj*8 + tq;
                bb[nj][0] = __float_as_uint(Bb[(ks+tr)*72 + c]);
                bb[nj][1] = __float_as_uint(Bb[(ks+tr+4)*72 + c]);
            }
            #pragma unroll
            for (int mi = 0; mi < 2; mi++)
                #pragma unroll
                for (int nj = 0; nj < 4; nj++)
                    mma_tf32(acc[mi][nj], a[mi][0], a[mi][1], a[mi][2], a[mi][3],
                             bb[nj][0], bb[nj][1]);
        }
    }

    __syncthreads();
    #pragma unroll
    for (int mi = 0; mi < 2; mi++) {
        int r0 = m0 + mw*32 + mi*16 + tq;
        #pragma unroll
        for (int nj = 0; nj < 4; nj++) {
            int c = nw*32 + nj*8 + tr*2;
            float v00 = acc[mi][nj][0], v01 = acc[mi][nj][1];
            float v10 = acc[mi][nj][2], v11 = acc[mi][nj][3];
            if (cheb == 2) {
                float2 x0 = *(const float2*)&Xg[(size_t)r0*XGP + c];
                float2 x1 = *(const float2*)&Xg[(size_t)(r0+8)*XGP + c];
                v00 = 2.f*v00 - x0.x; v01 = 2.f*v01 - x0.y;
                v10 = 2.f*v10 - x1.x; v11 = 2.f*v11 - x1.y;
            }
            float2 o0 = make_float2(tf32r(v00), tf32r(v01));
            float2 o1 = make_float2(tf32r(v10), tf32r(v11));
            *(float2*)&Xg[(size_t)r0*XGP + outOff + c]     = o0;
            *(float2*)&Xg[(size_t)(r0+8)*XGP + outOff + c] = o1;
        }
    }
#undef SP_LOAD
}

// ---------------- gate GEMM: TF32 MMA, CTA 128x128, warp 32x64 --------------
// which: 0 = encoder weights, 1 = decoder weights
__global__ void __launch_bounds__(256) k_gate(int which, const float* __restrict__ bias) {
    __shared__ float As[2][128*20];
    __shared__ float Bs[2][16*136];
    const float* W = which ? g_Wgd : g_Wge;
    const int m0 = blockIdx.x*128;
    const int tid = threadIdx.x;
    const int warp = tid >> 5, lane = tid & 31;
    const int mw = warp & 3, nw = warp >> 2;
    const int tq = lane >> 2, tr = lane & 3;
    const int lr = tid >> 1, lc = (tid & 1)*8;

    float acc[2][8][4] = {};

#define GT_LOAD(st, k0) do { \
    cpa16(&As[st][lr*20+lc],   &g_xg[(size_t)(m0+lr)*XGP + (k0)+lc]); \
    cpa16(&As[st][lr*20+lc+4], &g_xg[(size_t)(m0+lr)*XGP + (k0)+lc+4]); \
    { int i0 = tid;       int rB = i0>>5, cB = (i0&31)*4; \
      cpa16(&Bs[st][rB*136+cB], &W[(size_t)((k0)+rB)*128 + cB]); } \
    { int i1 = tid + 256; int rB = i1>>5, cB = (i1&31)*4; \
      cpa16(&Bs[st][rB*136+cB], &W[(size_t)((k0)+rB)*128 + cB]); } \
} while(0)

    GT_LOAD(0, 0); CP_COMMIT();
    for (int kt = 0; kt < 13; kt++) {
        if (kt+1 < 13) GT_LOAD((kt+1)&1, (kt+1)*16);
        CP_COMMIT();
        CP_WAIT1();
        __syncthreads();
        const float* Ab = As[kt&1];
        const float* Bb = Bs[kt&1];
        #pragma unroll
        for (int ks = 0; ks < 16; ks += 8) {
            unsigned a[2][4], bb[8][2];
            #pragma unroll
            for (int mi = 0; mi < 2; mi++) {
                int r = mw*32 + mi*16 + tq;
                a[mi][0] = __float_as_uint(Ab[r*20 + ks + tr]);
                a[mi][1] = __float_as_uint(Ab[(r+8)*20 + ks + tr]);
                a[mi][2] = __float_as_uint(Ab[r*20 + ks + tr + 4]);
                a[mi][3] = __float_as_uint(Ab[(r+8)*20 + ks + tr + 4]);
            }
            #pragma unroll
            for (int nj = 0; nj < 8; nj++) {
                int c = nw*64 + nj*8 + tq;
                bb[nj][0] = __float_as_uint(Bb[(ks+tr)*136 + c]);
                bb[nj][1] = __float_as_uint(Bb[(ks+tr+4)*136 + c]);
            }
            #pragma unroll
            for (int mi = 0; mi < 2; mi++)
                #pragma unroll
                for (int nj = 0; nj < 8; nj++)
                    mma_tf32(acc[mi][nj], a[mi][0], a[mi][1], a[mi][2], a[mi][3],
                             bb[nj][0], bb[nj][1]);
        }
        __syncthreads();
    }

    #pragma unroll
    for (int mi = 0; mi < 2; mi++) {
        int r0 = m0 + mw*32 + mi*16 + tq;
        #pragma unroll
        for (int nj = 0; nj < 8; nj++) {
            int c = nw*64 + nj*8 + tr*2;
            #pragma unroll
            for (int hh = 0; hh < 2; hh++) {
                int row = r0 + hh*8;
                float va = acc[mi][nj][hh*2], vb = acc[mi][nj][hh*2+1];
                float za = 1.f/(1.f + expf(-(va + bias[c])));
                float zb = 1.f/(1.f + expf(-(vb + bias[c+1])));
                if (c < 64) {
                    g_xg[(size_t)row*XGP + c]   = tf32r(za * g_h[(size_t)row*HID + c]);
                    g_xg[(size_t)row*XGP + c+1] = tf32r(zb * g_h[(size_t)row*HID + c+1]);
                } else {
                    g_r[(size_t)row*HID + (c-64)]   = za;
                    g_r[(size_t)row*HID + (c-64)+1] = zb;
                }
            }
        }
    }
#undef GT_LOAD
}

// ---------------- update GEMM: TF32 MMA, CTA 128x64, warp 32x32 -------------
// which: 0 = encoder weights, 1 = decoder weights
__global__ void __launch_bounds__(256) k_upd(int which, const float* __restrict__ bias) {
    __shared__ float As[2][128*20];
    __shared__ float Bs[2][16*72];
    const float* W = which ? g_Wud : g_Wue;
    const int m0 = blockIdx.x*128;
    const int tid = threadIdx.x;
    const int warp = tid >> 5, lane = tid & 31;
    const int mw = warp & 3, nw = warp >> 2;
    const int tq = lane >> 2, tr = lane & 3;
    const int lr = tid >> 1, lc = (tid & 1)*8;
    const int bk = tid >> 4, bn = (tid & 15)*4;

    float acc[2][4][4] = {};

#define UP_LOAD(st, k0) do { \
    cpa16(&As[st][lr*20+lc],   &g_xg[(size_t)(m0+lr)*XGP + (k0)+lc]); \
    cpa16(&As[st][lr*20+lc+4], &g_xg[(size_t)(m0+lr)*XGP + (k0)+lc+4]); \
    cpa16(&Bs[st][bk*72+bn],   &W[(size_t)((k0)+bk)*64 + bn]); \
} while(0)

    UP_LOAD(0, 0); CP_COMMIT();
    for (int kt = 0; kt < 13; kt++) {
        if (kt+1 < 13) UP_LOAD((kt+1)&1, (kt+1)*16);
        CP_COMMIT();
        CP_WAIT1();
        __syncthreads();
        const float* Ab = As[kt&1];
        const float* Bb = Bs[kt&1];
        #pragma unroll
        for (int ks = 0; ks < 16; ks += 8) {
            unsigned a[2][4], bb[4][2];
            #pragma unroll
            for (int mi = 0; mi < 2; mi++) {
                int r = mw*32 + mi*16 + tq;
                a[mi][0] = __float_as_uint(Ab[r*20 + ks + tr]);
                a[mi][1] = __float_as_uint(Ab[(r+8)*20 + ks + tr]);
                a[mi][2] = __float_as_uint(Ab[r*20 + ks + tr + 4]);
                a[mi][3] = __float_as_uint(Ab[(r+8)*20 + ks + tr + 4]);
            }
            #pragma unroll
            for (int nj = 0; nj < 4; nj++) {
                int c = nw*32 + nj*8 + tq;
                bb[nj][0] = __float_as_uint(Bb[(ks+tr)*72 + c]);
                bb[nj][1] = __float_as_uint(Bb[(ks+tr+4)*72 + c]);
            }
            #pragma unroll
            for (int mi = 0; mi < 2; mi++)
                #pragma unroll
                for (int nj = 0; nj < 4; nj++)
                    mma_tf32(acc[mi][nj], a[mi][0], a[mi][1], a[mi][2], a[mi][3],
                             bb[nj][0], bb[nj][1]);
        }
        __syncthreads();
    }

    #pragma unroll
    for (int mi = 0; mi < 2; mi++) {
        int r0 = m0 + mw*32 + mi*16 + tq;
        #pragma unroll
        for (int nj = 0; nj < 4; nj++) {
            int c = nw*32 + nj*8 + tr*2;
            #pragma unroll
            for (int hh = 0; hh < 2; hh++) {
                int row = r0 + hh*8;
                #pragma unroll
                for (int jj = 0; jj < 2; jj++) {
                    int o = c + jj;
                    float hc = tanhf(acc[mi][nj][hh*2+jj] + bias[o]);
                    float r  = g_r[(size_t)row*HID + o];
                    float h  = g_h[(size_t)row*HID + o];
                    float hn = r*h + (1.f - r)*hc;
                    g_h[(size_t)row*HID + o] = hn;
                    g_xg[(size_t)row*XGP + o] = tf32r(hn);
                }
            }
        }
    }
#undef UP_LOAD
}

// ---------------- hyper projection ------------------------------------------
__global__ void k_hyper(const float* __restrict__ hW, const float* __restrict__ hb) {
    int idx = blockIdx.x*blockDim.x + threadIdx.x;
    if (idx >= BN*EMB) return;
    int bn = idx / EMB, e = idx % EMB;
    float s = hb[e];
    #pragma unroll
    for (int k = 0; k < HID; k++) s += g_h[(size_t)bn*HID + k] * hW[k*EMB + e];
    g_ne[idx] = s;
}

// ---------------- output projection -----------------------------------------
__global__ void k_proj(const float* __restrict__ pW, const float* __restrict__ pb,
                       float* __restrict__ out, int t) {
    int gtid = blockIdx.x*blockDim.x + threadIdx.x;
    int warp = gtid >> 5;
    int lane = threadIdx.x & 31;
    if (warp >= BN) return;
    float s = g_h[(size_t)warp*64 + lane]      * pW[lane]
            + g_h[(size_t)warp*64 + 32 + lane] * pW[32 + lane];
    #pragma unroll
    for (int o = 16; o > 0; o >>= 1) s += __shfl_xor_sync(0xffffffffu, s, o);
    if (lane == 0) {
        float go = s + pb[0];
        g_go[warp] = go;
        int b = warp >> 9, n = warp & 511;
        out[((size_t)b*TT + t)*NN + n] = go;
    }
}

// ---------------- orchestration ---------------------------------------------
extern "C" void kernel_launch(void* const* d_in, const int* in_sizes, int n_in,
                              void* d_out, int out_size) {
    const float* x       = (const float*)d_in[0];
    const float* ycov    = (const float*)d_in[1];
    const float* emb     = (const float*)d_in[2];
    const float* enc_gW  = (const float*)d_in[3];
    const float* enc_gb  = (const float*)d_in[4];
    const float* enc_uW  = (const float*)d_in[5];
    const float* enc_ub  = (const float*)d_in[6];
    const float* dec_gW  = (const float*)d_in[7];
    const float* dec_gb  = (const float*)d_in[8];
    const float* dec_uW  = (const float*)d_in[9];
    const float* dec_ub  = (const float*)d_in[10];
    const float* proj_W  = (const float*)d_in[11];
    const float* proj_b  = (const float*)d_in[12];
    const float* hyper_W = (const float*)d_in[13];
    const float* hyper_b = (const float*)d_in[14];
    float* out = (float*)d_out;

    dim3 gs_spmm(4, BB);
    dim3 gs_pre(16, BB);
    dim3 gs_mv(64, BB);
    int  gs_gate = BN/128;
    int  gs_upd  = BN/128;
    int  nb2 = (BN + 255)/256;

    k_zero<<<1024, 256>>>();
    k_prep<<<(208*128+255)/256, 256>>>(enc_gW, 0);
    k_prep<<<(208*128+255)/256, 256>>>(dec_gW, 1);
    k_prep<<<(208*64+255)/256, 256>>>(enc_uW, 2);
    k_prep<<<(208*64+255)/256, 256>>>(dec_uW, 3);
    k_support_en<<<NN, 256>>>(emb);
    k_pre_enc<<<gs_pre, 256>>>(x, 1);
    k_pre_enc<<<gs_pre, 256>>>(x, 2);

    for (int t = 0; t < TT; t++) {
        k_build_enc<<<nb2, 256>>>(x, t);
        k_spmm<<<gs_spmm, 256>>>(0, 1);
        k_spmm<<<gs_spmm, 256>>>(0, 2);
        k_gate<<<gs_gate, 256>>>(0, enc_gb);
        k_spmm<<<gs_spmm, 256>>>(0, 1);
        k_spmm<<<gs_spmm, 256>>>(0, 2);
        k_upd<<<gs_upd, 256>>>(0, enc_ub);
    }

    k_hyper<<<(BN*EMB + 255)/256, 256>>>(hyper_W, hyper_b);
    k_support_de<<<BN, 256>>>();
    k_pre_dec<<<gs_pre, 256>>>(ycov, 1);
    k_pre_dec<<<gs_pre, 256>>>(ycov, 2);

    for (int t = 0; t < TT; t++) {
        k_build_dec<<<nb2, 256>>>(ycov, t);
        k_mv_go<<<gs_mv, 256>>>(1);
        k_mv_go<<<gs_mv, 256>>>(2);
        k_spmm<<<gs_spmm, 256>>>(1, 1);
        k_spmm<<<gs_spmm, 256>>>(1, 2);
        k_gate<<<gs_gate, 256>>>(1, dec_gb);
        k_spmm<<<gs_spmm, 256>>>(1, 1);
        k_spmm<<<gs_spmm, 256>>>(1, 2);
        k_upd<<<gs_upd, 256>>>(1, dec_ub);
        k_proj<<<(BN*32 + 255)/256, 256>>>(proj_W, proj_b, out, t);
    }
}

// round 7
// speedup vs baseline: 2.3212x; 1.0664x over previous
#include <cuda_runtime.h>
#include <math.h>

// ---------------- problem constants ----------------
#define BB   32
#define TT   12
#define NN   512
#define HID  64
#define EMB  10
#define BN   (BB*NN)     // 16384

// feature row layout, stride XGP=208:
//  [0..63]    X      (h or z*h)   <-> W rows 2..65
//  [64..127]  S@X                 <-> W rows 68..131
//  [128..191] (2S^2-I)@X          <-> W rows 134..197
//  [192..197] [x0,x1,Sx0,Sx1,S2x0,S2x1] <-> W rows 0,1,66,67,132,133
//  [198..207] pad (always 0)
#define XGP  208

// ---------------- device scratch ----------------
__device__ float g_h[BN*HID];
__device__ float g_r[BN*HID];
__device__ float g_xg[(size_t)BN*XGP];
__device__ float g_sup_en[NN*NN];
__device__ float g_sup_de[(size_t)BB*NN*NN];
__device__ float g_s2_en[NN*NN];
__device__ float g_s2_de[(size_t)BB*NN*NN];
__device__ float g_ne[BN*EMB];
__device__ float g_go[BN];
__device__ float g_xf1[BN*24];
__device__ float g_xf2[BN*24];
__device__ float g_yf1[BN*TT];
__device__ float g_yf2[BN*TT];
// reordered + tf32-rounded weights, feature-column order, 208 rows
__device__ float g_Wge[208*128];
__device__ float g_Wgd[208*128];
__device__ float g_Wue[208*64];
__device__ float g_Wud[208*64];

// feature col -> original W row
__device__ __forceinline__ int wmap(int c) {
    if (c < 64)  return c + 2;
    if (c < 128) return c + 4;
    if (c < 192) return c + 6;
    return ((c - 192) >> 1) * 66 + (c & 1);
}

// ---------------- tf32 helpers ----------------
__device__ __forceinline__ unsigned f2tf(float f) {
    unsigned u;
    asm("cvt.rna.tf32.f32 %0, %1;" : "=r"(u) : "f"(f));
    return u;
}
__device__ __forceinline__ float tf32r(float f) { return __uint_as_float(f2tf(f)); }

__device__ __forceinline__ void mma_tf32(float* d,
    unsigned a0, unsigned a1, unsigned a2, unsigned a3,
    unsigned b0, unsigned b1) {
    asm volatile(
        "mma.sync.aligned.m16n8k8.row.col.f32.tf32.tf32.f32 "
        "{%0,%1,%2,%3}, {%4,%5,%6,%7}, {%8,%9}, {%0,%1,%2,%3};\n"
        : "+f"(d[0]), "+f"(d[1]), "+f"(d[2]), "+f"(d[3])
        : "r"(a0), "r"(a1), "r"(a2), "r"(a3), "r"(b0), "r"(b1));
}

__device__ __forceinline__ void cpa16(void* smem, const void* g) {
    unsigned s = (unsigned)__cvta_generic_to_shared(smem);
    asm volatile("cp.async.cg.shared.global [%0], [%1], 16;\n" :: "r"(s), "l"(g));
}
#define CP_COMMIT() asm volatile("cp.async.commit_group;\n" ::: "memory")
#define CP_WAIT1()  asm volatile("cp.async.wait_group 1;\n" ::: "memory")

// ---------------- init ----------------
__global__ void k_zero() {
    size_t i = (size_t)blockIdx.x*blockDim.x + threadIdx.x;
    size_t st = (size_t)gridDim.x*blockDim.x;
    for (size_t j=i; j<(size_t)BN*XGP; j+=st) g_xg[j] = 0.f;
    for (size_t j=i; j<BN*HID; j+=st) g_h[j]  = 0.f;
    for (size_t j=i; j<BN;     j+=st) g_go[j] = 0.f;
}

// ---------------- weight reorder + round (0=ge,1=gd,2=ue,3=ud) --------------
__global__ void k_prep(const float* __restrict__ W, int which) {
    int nc = (which < 2) ? 128 : 64;
    float* dst = (which == 0) ? g_Wge : (which == 1) ? g_Wgd
               : (which == 2) ? g_Wue : g_Wud;
    int idx = blockIdx.x*blockDim.x + threadIdx.x;
    if (idx >= 208*nc) return;
    int c = idx / nc, o = idx - c*nc;
    float v = 0.f;
    if (c < 198) v = W[wmap(c)*nc + o];
    dst[idx] = tf32r(v);
}

// ---------------- supports (emit tf32-rounded) ----------------
__global__ void k_support_en(const float* __restrict__ emb) {
    int n = blockIdx.x, tid = threadIdx.x;
    __shared__ float embn[EMB];
    __shared__ float row[NN];
    __shared__ float red[256];
    if (tid < EMB) embn[tid] = emb[n*EMB + tid];
    __syncthreads();
    for (int m=tid; m<NN; m+=256) {
        float s = 0.f;
        #pragma unroll
        for (int e=0; e<EMB; e++) s += embn[e]*emb[m*EMB+e];
        row[m] = fmaxf(s, 0.f);
    }
    __syncthreads();
    float lm = -1e30f;
    for (int m=tid; m<NN; m+=256) lm = fmaxf(lm, row[m]);
    red[tid]=lm; __syncthreads();
    for (int s=128;s>0;s>>=1){ if(tid<s) red[tid]=fmaxf(red[tid],red[tid+s]); __syncthreads(); }
    float mx = red[0]; __syncthreads();
    float ls = 0.f;
    for (int m=tid; m<NN; m+=256){ float e=expf(row[m]-mx); row[m]=e; ls+=e; }
    red[tid]=ls; __syncthreads();
    for (int s=128;s>0;s>>=1){ if(tid<s) red[tid]+=red[tid+s]; __syncthreads(); }
    float inv = 1.f/red[0];
    for (int m=tid; m<NN; m+=256) g_sup_en[n*NN+m] = tf32r(row[m]*inv);
}

__global__ void k_support_de() {
    int bn = blockIdx.x;
    int b = bn >> 9, n = bn & 511;
    int tid = threadIdx.x;
    const float* neb = g_ne + (size_t)b*NN*EMB;
    __shared__ float embn[EMB];
    __shared__ float row[NN];
    __shared__ float red[256];
    if (tid < EMB) embn[tid] = neb[n*EMB + tid];
    __syncthreads();
    for (int m=tid; m<NN; m+=256) {
        float s = 0.f;
        #pragma unroll
        for (int e=0; e<EMB; e++) s += embn[e]*neb[m*EMB+e];
        row[m] = fmaxf(s, 0.f);
    }
    __syncthreads();
    float lm = -1e30f;
    for (int m=tid; m<NN; m+=256) lm = fmaxf(lm, row[m]);
    red[tid]=lm; __syncthreads();
    for (int s=128;s>0;s>>=1){ if(tid<s) red[tid]=fmaxf(red[tid],red[tid+s]); __syncthreads(); }
    float mx = red[0]; __syncthreads();
    float ls = 0.f;
    for (int m=tid; m<NN; m+=256){ float e=expf(row[m]-mx); row[m]=e; ls+=e; }
    red[tid]=ls; __syncthreads();
    for (int s=128;s>0;s>>=1){ if(tid<s) red[tid]+=red[tid+s]; __syncthreads(); }
    float inv = 1.f/red[0];
    float* outr = g_sup_de + (size_t)b*NN*NN + (size_t)n*NN;
    for (int m=tid; m<NN; m+=256) outr[m] = tf32r(row[m]*inv);
}

// ---------------- S2 = S @ S  (TF32 MMA, CTA 128x64) ------------------------
__global__ void __launch_bounds__(256) k_sq(int deFlag) {
    __shared__ float As[3][128*20];
    __shared__ float Bs[3][16*72];
    const int b  = blockIdx.z;
    const int m0 = blockIdx.x*128;
    const int n0 = blockIdx.y*64;
    const int tid = threadIdx.x;
    const int warp = tid >> 5, lane = tid & 31;
    const int mw = warp & 3, nw = warp >> 2;
    const int tq = lane >> 2, tr = lane & 3;
    const float* S = deFlag ? g_sup_de + (size_t)b*NN*NN : g_sup_en;
    float* D       = deFlag ? g_s2_de  + (size_t)b*NN*NN : g_s2_en;
    const int lr = tid >> 1, lc = (tid & 1)*8;
    const int bk = tid >> 4, bn = (tid & 15)*4;

    float acc[2][4][4] = {};

#define SQ_LOAD(st, k0) do { \
    cpa16(&As[st][lr*20+lc],   &S[(size_t)(m0+lr)*NN + (k0)+lc]); \
    cpa16(&As[st][lr*20+lc+4], &S[(size_t)(m0+lr)*NN + (k0)+lc+4]); \
    cpa16(&Bs[st][bk*72+bn],   &S[(size_t)((k0)+bk)*NN + n0 + bn]); \
} while(0)

    SQ_LOAD(0, 0);  CP_COMMIT();
    SQ_LOAD(1, 16); CP_COMMIT();
    for (int kt = 0; kt < 32; kt++) {
        CP_WAIT1();
        __syncthreads();
        if (kt < 30) SQ_LOAD((kt+2)%3, (kt+2)*16);
        CP_COMMIT();
        const float* Ab = As[kt%3];
        const float* Bb = Bs[kt%3];
        #pragma unroll
        for (int ks = 0; ks < 16; ks += 8) {
            unsigned a[2][4], bb[4][2];
            #pragma unroll
            for (int mi = 0; mi < 2; mi++) {
                int r = mw*32 + mi*16 + tq;
                a[mi][0] = __float_as_uint(Ab[r*20 + ks + tr]);
                a[mi][1] = __float_as_uint(Ab[(r+8)*20 + ks + tr]);
                a[mi][2] = __float_as_uint(Ab[r*20 + ks + tr + 4]);
                a[mi][3] = __float_as_uint(Ab[(r+8)*20 + ks + tr + 4]);
            }
            #pragma unroll
            for (int nj = 0; nj < 4; nj++) {
                int c = nw*32 + nj*8 + tq;
                bb[nj][0] = __float_as_uint(Bb[(ks+tr)*72 + c]);
                bb[nj][1] = __float_as_uint(Bb[(ks+tr+4)*72 + c]);
            }
            #pragma unroll
            for (int mi = 0; mi < 2; mi++)
                #pragma unroll
                for (int nj = 0; nj < 4; nj++)
                    mma_tf32(acc[mi][nj], a[mi][0], a[mi][1], a[mi][2], a[mi][3],
                             bb[nj][0], bb[nj][1]);
        }
    }
    __syncthreads();
    #pragma unroll
    for (int mi = 0; mi < 2; mi++) {
        int r0 = m0 + mw*32 + mi*16 + tq;
        #pragma unroll
        for (int nj = 0; nj < 4; nj++) {
            int c = n0 + nw*32 + nj*8 + tr*2;
            float2 o0 = make_float2(tf32r(acc[mi][nj][0]), tf32r(acc[mi][nj][1]));
            float2 o1 = make_float2(tf32r(acc[mi][nj][2]), tf32r(acc[mi][nj][3]));
            *(float2*)&D[(size_t)r0*NN + c]     = o0;
            *(float2*)&D[(size_t)(r0+8)*NN + c] = o1;
        }
    }
#undef SQ_LOAD
}

// ---------------- x/ycov feature precompute (z: 0 -> S@v, 1 -> 2S2@v - v) ---
__global__ void __launch_bounds__(256) k_pre_enc(const float* __restrict__ x) {
    __shared__ float xsh[512*24];
    int b = blockIdx.y, m0 = blockIdx.x*32, z = blockIdx.z;
    int tid = threadIdx.x;
    for (int idx = tid; idx < 512*24; idx += 256) {
        int k = idx/24, tc = idx%24;
        int t = tc>>1, c = tc&1;
        xsh[idx] = x[(((size_t)b*TT+t)*NN + k)*2 + c];
    }
    __syncthreads();
    int rl = tid>>3, kh = (tid>>2)&1, cg = tid&3;
    int row = m0 + rl, g = cg*6;
    float acc[6] = {};
    const float* Srow = (z ? g_s2_en : g_sup_en) + (size_t)row*NN + kh*256;
    const float* xp = &xsh[kh*256*24];
    for (int k=0;k<256;k+=4){
        float4 s = *(const float4*)&Srow[k];
        #pragma unroll
        for (int j=0;j<6;j++)
            acc[j] += s.x*xp[(k+0)*24+g+j] + s.y*xp[(k+1)*24+g+j]
                    + s.z*xp[(k+2)*24+g+j] + s.w*xp[(k+3)*24+g+j];
    }
    #pragma unroll
    for (int j=0;j<6;j++) acc[j] += __shfl_xor_sync(0xffffffffu, acc[j], 4);
    if (kh == 0) {
        #pragma unroll
        for (int j=0;j<6;j++) {
            int col = g + j;
            if (z == 0) g_xf1[((size_t)b*NN + row)*24 + col] = acc[j];
            else {
                int t = col>>1, c = col&1;
                g_xf2[((size_t)b*NN + row)*24 + col] =
                    2.f*acc[j] - x[(((size_t)b*TT+t)*NN + row)*2 + c];
            }
        }
    }
}

__global__ void __launch_bounds__(256) k_pre_dec(const float* __restrict__ ycov) {
    __shared__ float ysh[512*12];
    int b = blockIdx.y, m0 = blockIdx.x*32, z = blockIdx.z;
    int tid = threadIdx.x;
    for (int idx = tid; idx < 512*12; idx += 256) {
        int k = idx/12, t = idx%12;
        ysh[idx] = ycov[((size_t)b*TT+t)*NN + k];
    }
    __syncthreads();
    int rl = tid>>3, kh = (tid>>2)&1, cg = tid&3;
    int row = m0 + rl, g = cg*3;
    float acc[3] = {};
    const float* Srow = (z ? g_s2_de : g_sup_de) + (size_t)b*NN*NN + (size_t)row*NN + kh*256;
    const float* yp = &ysh[kh*256*12];
    for (int k=0;k<256;k+=4){
        float4 s = *(const float4*)&Srow[k];
        #pragma unroll
        for (int j=0;j<3;j++)
            acc[j] += s.x*yp[(k+0)*12+g+j] + s.y*yp[(k+1)*12+g+j]
                    + s.z*yp[(k+2)*12+g+j] + s.w*yp[(k+3)*12+g+j];
    }
    #pragma unroll
    for (int j=0;j<3;j++) acc[j] += __shfl_xor_sync(0xffffffffu, acc[j], 4);
    if (kh == 0) {
        #pragma unroll
        for (int j=0;j<3;j++) {
            int t = g + j;
            if (z == 0) g_yf1[((size_t)b*NN + row)*12 + t] = acc[j];
            else        g_yf2[((size_t)b*NN + row)*12 + t] =
                            2.f*acc[j] - ycov[((size_t)b*TT+t)*NN + row];
        }
    }
}

// ---------------- decoder input: features + both go mat-vecs ----------------
__global__ void __launch_bounds__(256) k_dec_in(const float* __restrict__ ycov, int t) {
    __shared__ float gsh[NN];
    int b = blockIdx.y;
    int tid = threadIdx.x, lane = tid & 31, w = tid >> 5;
    int row = blockIdx.x*8 + w;
    gsh[tid]       = g_go[(size_t)b*NN + tid];
    gsh[tid + 256] = g_go[(size_t)b*NN + tid + 256];
    __syncthreads();
    const float* Sr  = g_sup_de + (size_t)b*NN*NN + (size_t)row*NN;
    const float* S2r = g_s2_de  + (size_t)b*NN*NN + (size_t)row*NN;
    float d1 = 0.f, d2 = 0.f;
    #pragma unroll
    for (int i=0;i<4;i++) {
        int k = lane*4 + 128*i;
        float4 s = *(const float4*)&Sr[k];
        float4 q = *(const float4*)&S2r[k];
        d1 += s.x*gsh[k] + s.y*gsh[k+1] + s.z*gsh[k+2] + s.w*gsh[k+3];
        d2 += q.x*gsh[k] + q.y*gsh[k+1] + q.z*gsh[k+2] + q.w*gsh[k+3];
    }
    #pragma unroll
    for (int o=16;o>0;o>>=1) {
        d1 += __shfl_xor_sync(0xffffffffu, d1, o);
        d2 += __shfl_xor_sync(0xffffffffu, d2, o);
    }
    if (lane == 0) {
        size_t bn = (size_t)b*NN + row;
        float go = gsh[row];
        float* f = &g_xg[bn*XGP];
        f[192] = tf32r(go);
        f[193] = tf32r(ycov[((size_t)b*TT+t)*NN + row]);
        f[194] = tf32r(d1);
        f[195] = tf32r(g_yf1[bn*12 + t]);
        f[196] = tf32r(2.f*d2 - go);
        f[197] = tf32r(g_yf2[bn*12 + t]);
    }
}

// ---------------- encoder t=0 builder ---------------------------------------
__global__ void k_build_enc(const float* __restrict__ x, int t) {
    int bn = blockIdx.x*blockDim.x + threadIdx.x;
    if (bn >= BN) return;
    int b = bn >> 9, n = bn & 511;
    float* f = &g_xg[(size_t)bn*XGP];
    const float* xp = &x[(((size_t)b*TT+t)*NN + n)*2];
    f[192] = tf32r(xp[0]);
    f[193] = tf32r(xp[1]);
    f[194] = tf32r(g_xf1[(size_t)bn*24 + t*2 + 0]);
    f[195] = tf32r(g_xf1[(size_t)bn*24 + t*2 + 1]);
    f[196] = tf32r(g_xf2[(size_t)bn*24 + t*2 + 0]);
    f[197] = tf32r(g_xf2[(size_t)bn*24 + t*2 + 1]);
}

// ---------------- h-chain spmm: z=0 -> Y1=S@X, z=1 -> Y2=2*S2@X-X -----------
__global__ void __launch_bounds__(256) k_spmm(int deFlag) {
    __shared__ float As[3][128*20];
    __shared__ float Bs[3][16*72];
    const int b   = blockIdx.y;
    const int m0  = blockIdx.x*128;
    const int cheb = blockIdx.z;
    const int tid = threadIdx.x;
    const int warp = tid >> 5, lane = tid & 31;
    const int mw = warp & 3, nw = warp >> 2;
    const int tq = lane >> 2, tr = lane & 3;
    const float* Sb = cheb
        ? (deFlag ? g_s2_de  + (size_t)b*NN*NN : g_s2_en)
        : (deFlag ? g_sup_de + (size_t)b*NN*NN : g_sup_en);
    float* Xg = g_xg + (size_t)b*NN*XGP;
    const int outOff = 64 + 64*cheb;

    const int lr = tid >> 1, lc = (tid & 1)*8;
    const int bk = tid >> 4, bn = (tid & 15)*4;

    float acc[2][4][4] = {};

#define SP_LOAD(st, k0) do { \
    cpa16(&As[st][lr*20+lc],   &Sb[(size_t)(m0+lr)*NN + (k0)+lc]); \
    cpa16(&As[st][lr*20+lc+4], &Sb[(size_t)(m0+lr)*NN + (k0)+lc+4]); \
    cpa16(&Bs[st][bk*72+bn],   &Xg[(size_t)((k0)+bk)*XGP + bn]); \
} while(0)

    SP_LOAD(0, 0);  CP_COMMIT();
    SP_LOAD(1, 16); CP_COMMIT();
    for (int kt = 0; kt < 32; kt++) {
        CP_WAIT1();
        __syncthreads();
        if (kt < 30) SP_LOAD((kt+2)%3, (kt+2)*16);
        CP_COMMIT();
        const float* Ab = As[kt%3];
        const float* Bb = Bs[kt%3];
        #pragma unroll
        for (int ks = 0; ks < 16; ks += 8) {
            unsigned a[2][4], bb[4][2];
            #pragma unroll
            for (int mi = 0; mi < 2; mi++) {
                int r = mw*32 + mi*16 + tq;
                a[mi][0] = __float_as_uint(Ab[r*20 + ks + tr]);
                a[mi][1] = __float_as_uint(Ab[(r+8)*20 + ks + tr]);
                a[mi][2] = __float_as_uint(Ab[r*20 + ks + tr + 4]);
                a[mi][3] = __float_as_uint(Ab[(r+8)*20 + ks + tr + 4]);
            }
            #pragma unroll
            for (int nj = 0; nj < 4; nj++) {
                int c = nw*32 + nj*8 + tq;
                bb[nj][0] = __float_as_uint(Bb[(ks+tr)*72 + c]);
                bb[nj][1] = __float_as_uint(Bb[(ks+tr+4)*72 + c]);
            }
            #pragma unroll
            for (int mi = 0; mi < 2; mi++)
                #pragma unroll
                for (int nj = 0; nj < 4; nj++)
                    mma_tf32(acc[mi][nj], a[mi][0], a[mi][1], a[mi][2], a[mi][3],
                             bb[nj][0], bb[nj][1]);
        }
    }

    __syncthreads();
    #pragma unroll
    for (int mi = 0; mi < 2; mi++) {
        int r0 = m0 + mw*32 + mi*16 + tq;
        #pragma unroll
        for (int nj = 0; nj < 4; nj++) {
            int c = nw*32 + nj*8 + tr*2;
            float v00 = acc[mi][nj][0], v01 = acc[mi][nj][1];
            float v10 = acc[mi][nj][2], v11 = acc[mi][nj][3];
            if (cheb == 1) {
                float2 x0 = *(const float2*)&Xg[(size_t)r0*XGP + c];
                float2 x1 = *(const float2*)&Xg[(size_t)(r0+8)*XGP + c];
                v00 = 2.f*v00 - x0.x; v01 = 2.f*v01 - x0.y;
                v10 = 2.f*v10 - x1.x; v11 = 2.f*v11 - x1.y;
            }
            float2 o0 = make_float2(tf32r(v00), tf32r(v01));
            float2 o1 = make_float2(tf32r(v10), tf32r(v11));
            *(float2*)&Xg[(size_t)r0*XGP + outOff + c]     = o0;
            *(float2*)&Xg[(size_t)(r0+8)*XGP + outOff + c] = o1;
        }
    }
#undef SP_LOAD
}

// ---------------- gate GEMM: TF32 MMA, CTA 128x128 --------------------------
__global__ void __launch_bounds__(256) k_gate(int which, const float* __restrict__ bias) {
    __shared__ float As[2][128*20];
    __shared__ float Bs[2][16*136];
    const float* W = which ? g_Wgd : g_Wge;
    const int m0 = blockIdx.x*128;
    const int tid = threadIdx.x;
    const int warp = tid >> 5, lane = tid & 31;
    const int mw = warp & 3, nw = warp >> 2;
    const int tq = lane >> 2, tr = lane & 3;
    const int lr = tid >> 1, lc = (tid & 1)*8;

    float acc[2][8][4] = {};

#define GT_LOAD(st, k0) do { \
    cpa16(&As[st][lr*20+lc],   &g_xg[(size_t)(m0+lr)*XGP + (k0)+lc]); \
    cpa16(&As[st][lr*20+lc+4], &g_xg[(size_t)(m0+lr)*XGP + (k0)+lc+4]); \
    { int i0 = tid;       int rB = i0>>5, cB = (i0&31)*4; \
      cpa16(&Bs[st][rB*136+cB], &W[(size_t)((k0)+rB)*128 + cB]); } \
    { int i1 = tid + 256; int rB = i1>>5, cB = (i1&31)*4; \
      cpa16(&Bs[st][rB*136+cB], &W[(size_t)((k0)+rB)*128 + cB]); } \
} while(0)

    GT_LOAD(0, 0); CP_COMMIT();
    for (int kt = 0; kt < 13; kt++) {
        if (kt+1 < 13) GT_LOAD((kt+1)&1, (kt+1)*16);
        CP_COMMIT();
        CP_WAIT1();
        __syncthreads();
        const float* Ab = As[kt&1];
        const float* Bb = Bs[kt&1];
        #pragma unroll
        for (int ks = 0; ks < 16; ks += 8) {
            unsigned a[2][4], bb[8][2];
            #pragma unroll
            for (int mi = 0; mi < 2; mi++) {
                int r = mw*32 + mi*16 + tq;
                a[mi][0] = __float_as_uint(Ab[r*20 + ks + tr]);
                a[mi][1] = __float_as_uint(Ab[(r+8)*20 + ks + tr]);
                a[mi][2] = __float_as_uint(Ab[r*20 + ks + tr + 4]);
                a[mi][3] = __float_as_uint(Ab[(r+8)*20 + ks + tr + 4]);
            }
            #pragma unroll
            for (int nj = 0; nj < 8; nj++) {
                int c = nw*64 + nj*8 + tq;
                bb[nj][0] = __float_as_uint(Bb[(ks+tr)*136 + c]);
                bb[nj][1] = __float_as_uint(Bb[(ks+tr+4)*136 + c]);
            }
            #pragma unroll
            for (int mi = 0; mi < 2; mi++)
                #pragma unroll
                for (int nj = 0; nj < 8; nj++)
                    mma_tf32(acc[mi][nj], a[mi][0], a[mi][1], a[mi][2], a[mi][3],
                             bb[nj][0], bb[nj][1]);
        }
        __syncthreads();
    }

    #pragma unroll
    for (int mi = 0; mi < 2; mi++) {
        int r0 = m0 + mw*32 + mi*16 + tq;
        #pragma unroll
        for (int nj = 0; nj < 8; nj++) {
            int c = nw*64 + nj*8 + tr*2;
            #pragma unroll
            for (int hh = 0; hh < 2; hh++) {
                int row = r0 + hh*8;
                float va = acc[mi][nj][hh*2], vb = acc[mi][nj][hh*2+1];
                float za = 1.f/(1.f + expf(-(va + bias[c])));
                float zb = 1.f/(1.f + expf(-(vb + bias[c+1])));
                if (c < 64) {
                    g_xg[(size_t)row*XGP + c]   = tf32r(za * g_h[(size_t)row*HID + c]);
                    g_xg[(size_t)row*XGP + c+1] = tf32r(zb * g_h[(size_t)row*HID + c+1]);
                } else {
                    g_r[(size_t)row*HID + (c-64)]   = za;
                    g_r[(size_t)row*HID + (c-64)+1] = zb;
                }
            }
        }
    }
#undef GT_LOAD
}

// ---------------- update GEMM + fused proj / next-enc-features --------------
__global__ void __launch_bounds__(256) k_upd(int which, const float* __restrict__ bias,
                                             int encT, const float* __restrict__ x,
                                             const float* __restrict__ pW,
                                             const float* __restrict__ pb,
                                             float* __restrict__ out, int t) {
    __shared__ float As[2][128*20];
    __shared__ float Bs[2][16*72];
    __shared__ float pr[2][128];
    const float* W = which ? g_Wud : g_Wue;
    const int m0 = blockIdx.x*128;
    const int tid = threadIdx.x;
    const int warp = tid >> 5, lane = tid & 31;
    const int mw = warp & 3, nw = warp >> 2;
    const int tq = lane >> 2, tr = lane & 3;
    const int lr = tid >> 1, lc = (tid & 1)*8;
    const int bk = tid >> 4, bn = (tid & 15)*4;
    const bool doProj = (pW != nullptr);

    float acc[2][4][4] = {};

#define UP_LOAD(st, k0) do { \
    cpa16(&As[st][lr*20+lc],   &g_xg[(size_t)(m0+lr)*XGP + (k0)+lc]); \
    cpa16(&As[st][lr*20+lc+4], &g_xg[(size_t)(m0+lr)*XGP + (k0)+lc+4]); \
    cpa16(&Bs[st][bk*72+bn],   &W[(size_t)((k0)+bk)*64 + bn]); \
} while(0)

    UP_LOAD(0, 0); CP_COMMIT();
    for (int kt = 0; kt < 13; kt++) {
        if (kt+1 < 13) UP_LOAD((kt+1)&1, (kt+1)*16);
        CP_COMMIT();
        CP_WAIT1();
        __syncthreads();
        const float* Ab = As[kt&1];
        const float* Bb = Bs[kt&1];
        #pragma unroll
        for (int ks = 0; ks < 16; ks += 8) {
            unsigned a[2][4], bb[4][2];
            #pragma unroll
            for (int mi = 0; mi < 2; mi++) {
                int r = mw*32 + mi*16 + tq;
                a[mi][0] = __float_as_uint(Ab[r*20 + ks + tr]);
                a[mi][1] = __float_as_uint(Ab[(r+8)*20 + ks + tr]);
                a[mi][2] = __float_as_uint(Ab[r*20 + ks + tr + 4]);
                a[mi][3] = __float_as_uint(Ab[(r+8)*20 + ks + tr + 4]);
            }
            #pragma unroll
            for (int nj = 0; nj < 4; nj++) {
                int c = nw*32 + nj*8 + tq;
                bb[nj][0] = __float_as_uint(Bb[(ks+tr)*72 + c]);
                bb[nj][1] = __float_as_uint(Bb[(ks+tr+4)*72 + c]);
            }
            #pragma unroll
            for (int mi = 0; mi < 2; mi++)
                #pragma unroll
                for (int nj = 0; nj < 4; nj++)
                    mma_tf32(acc[mi][nj], a[mi][0], a[mi][1], a[mi][2], a[mi][3],
                             bb[nj][0], bb[nj][1]);
        }
        __syncthreads();
    }

    float rowsum[2][2] = {};
    #pragma unroll
    for (int mi = 0; mi < 2; mi++) {
        int r0 = m0 + mw*32 + mi*16 + tq;
        #pragma unroll
        for (int nj = 0; nj < 4; nj++) {
            int c = nw*32 + nj*8 + tr*2;
            #pragma unroll
            for (int hh = 0; hh < 2; hh++) {
                int row = r0 + hh*8;
                #pragma unroll
                for (int jj = 0; jj < 2; jj++) {
                    int o = c + jj;
                    float hc = tanhf(acc[mi][nj][hh*2+jj] + bias[o]);
                    float r  = g_r[(size_t)row*HID + o];
                    float h  = g_h[(size_t)row*HID + o];
                    float hn = r*h + (1.f - r)*hc;
                    g_h[(size_t)row*HID + o] = hn;
                    g_xg[(size_t)row*XGP + o] = tf32r(hn);
                    if (doProj) rowsum[mi][hh] += hn * pW[o];
                }
            }
        }
    }

    if (doProj) {
        #pragma unroll
        for (int mi = 0; mi < 2; mi++)
            #pragma unroll
            for (int hh = 0; hh < 2; hh++) {
                float v = rowsum[mi][hh];
                v += __shfl_xor_sync(0xffffffffu, v, 1);
                v += __shfl_xor_sync(0xffffffffu, v, 2);
                if (tr == 0) pr[nw][mw*32 + mi*16 + tq + hh*8] = v;
            }
        __syncthreads();
        if (tid < 128) {
            int row = m0 + tid;
            float go = pr[0][tid] + pr[1][tid] + pb[0];
            g_go[row] = go;
            int bI = row >> 9, n = row & 511;
            out[((size_t)bI*TT + t)*NN + n] = go;
        }
    }

    if (encT >= 0 && tid < 128) {
        int bnn = m0 + tid;
        int bI = bnn >> 9, n = bnn & 511;
        float* f = &g_xg[(size_t)bnn*XGP];
        const float* xp = &x[(((size_t)bI*TT+encT)*NN + n)*2];
        f[192] = tf32r(xp[0]);
        f[193] = tf32r(xp[1]);
        f[194] = tf32r(g_xf1[(size_t)bnn*24 + encT*2 + 0]);
        f[195] = tf32r(g_xf1[(size_t)bnn*24 + encT*2 + 1]);
        f[196] = tf32r(g_xf2[(size_t)bnn*24 + encT*2 + 0]);
        f[197] = tf32r(g_xf2[(size_t)bnn*24 + encT*2 + 1]);
    }
#undef UP_LOAD
}

// ---------------- hyper projection ------------------------------------------
__global__ void k_hyper(const float* __restrict__ hW, const float* __restrict__ hb) {
    int idx = blockIdx.x*blockDim.x + threadIdx.x;
    if (idx >= BN*EMB) return;
    int bn = idx / EMB, e = idx % EMB;
    float s = hb[e];
    #pragma unroll
    for (int k = 0; k < HID; k++) s += g_h[(size_t)bn*HID + k] * hW[k*EMB + e];
    g_ne[idx] = s;
}

// ---------------- orchestration ---------------------------------------------
extern "C" void kernel_launch(void* const* d_in, const int* in_sizes, int n_in,
                              void* d_out, int out_size) {
    const float* x       = (const float*)d_in[0];
    const float* ycov    = (const float*)d_in[1];
    const float* emb     = (const float*)d_in[2];
    const float* enc_gW  = (const float*)d_in[3];
    const float* enc_gb  = (const float*)d_in[4];
    const float* enc_uW  = (const float*)d_in[5];
    const float* enc_ub  = (const float*)d_in[6];
    const float* dec_gW  = (const float*)d_in[7];
    const float* dec_gb  = (const float*)d_in[8];
    const float* dec_uW  = (const float*)d_in[9];
    const float* dec_ub  = (const float*)d_in[10];
    const float* proj_W  = (const float*)d_in[11];
    const float* proj_b  = (const float*)d_in[12];
    const float* hyper_W = (const float*)d_in[13];
    const float* hyper_b = (const float*)d_in[14];
    float* out = (float*)d_out;

    dim3 gs_spmm(4, BB, 2);
    dim3 gs_sq_en(4, 8, 1);
    dim3 gs_sq_de(4, 8, BB);
    dim3 gs_pre(16, BB, 2);
    dim3 gs_dec(64, BB);
    int  gs_mm = BN/128;
    int  nb2 = (BN + 255)/256;

    k_zero<<<1024, 256>>>();
    k_prep<<<(208*128+255)/256, 256>>>(enc_gW, 0);
    k_prep<<<(208*128+255)/256, 256>>>(dec_gW, 1);
    k_prep<<<(208*64+255)/256, 256>>>(enc_uW, 2);
    k_prep<<<(208*64+255)/256, 256>>>(dec_uW, 3);
    k_support_en<<<NN, 256>>>(emb);
    k_sq<<<gs_sq_en, 256>>>(0);
    k_pre_enc<<<gs_pre, 256>>>(x);
    k_build_enc<<<nb2, 256>>>(x, 0);

    for (int t = 0; t < TT; t++) {
        k_spmm<<<gs_spmm, 256>>>(0);
        k_gate<<<gs_mm, 256>>>(0, enc_gb);
        k_spmm<<<gs_spmm, 256>>>(0);
        k_upd<<<gs_mm, 256>>>(0, enc_ub, (t+1 < TT) ? t+1 : -1, x,
                              nullptr, nullptr, nullptr, 0);
    }

    k_hyper<<<(BN*EMB + 255)/256, 256>>>(hyper_W, hyper_b);
    k_support_de<<<BN, 256>>>();
    k_sq<<<gs_sq_de, 256>>>(1);
    k_pre_dec<<<gs_pre, 256>>>(ycov);

    for (int t = 0; t < TT; t++) {
        k_dec_in<<<gs_dec, 256>>>(ycov, t);
        k_spmm<<<gs_spmm, 256>>>(1);
        k_gate<<<gs_mm, 256>>>(1, dec_gb);
        k_spmm<<<gs_spmm, 256>>>(1);
        k_upd<<<gs_mm, 256>>>(1, dec_ub, -1, nullptr,
                              proj_W, proj_b, out, t);
    }
}

// round 8
// speedup vs baseline: 2.4137x; 1.0398x over previous
#include <cuda_runtime.h>
#include <math.h>

// ---------------- problem constants ----------------
#define BB   32
#define TT   12
#define NN   512
#define HID  64
#define EMB  10
#define BN   (BB*NN)     // 16384

// g_xg now holds ONLY the X section (h or z*h), 64 cols per row.
#define XGP  64

// Weight layout (208 rows, feature-col order):
//  rows 0..63   <-> X        (orig W rows 2..65)
//  rows 64..127 <-> S@X      (orig 68..131)
//  rows 128..191<-> 2S^2X-X  (orig 134..197)
//  rows 192..197<-> [x0,x1,Sx0,Sx1,S2x0,S2x1] (orig 0,1,66,67,132,133)
//  rows 198..207 zero pad

// ---------------- dynamic smem layout (floats) ----------------
// A-panel: 13 k-tiles, each 128 rows * pitch 20
#define OFF_PANEL 0
#define TILE_F    2560              // 128*20
#define OFF_S     (13*TILE_F)       // 33280 : 3 stages * 2560 (S tiles / W reuse)
#define OFF_S2    (OFF_S + 3*TILE_F)   // 40960 : 3 stages * 2560
#define OFF_XB    (OFF_S2 + 3*TILE_F)  // 48640 : 3 stages * 1152
#define OFF_GO    (OFF_XB + 3*1152)    // 52096 : 512
#define SM_FLOATS (OFF_GO + 512)       // 52608
#define SM_BYTES  (SM_FLOATS*4)        // 210432

// ---------------- device scratch ----------------
__device__ float g_h[BN*HID];
__device__ float g_r[BN*HID];
__device__ float g_xg[(size_t)BN*XGP];
__device__ float g_sup_en[NN*NN];
__device__ float g_sup_de[(size_t)BB*NN*NN];
__device__ float g_s2_en[NN*NN];
__device__ float g_s2_de[(size_t)BB*NN*NN];
__device__ float g_ne[BN*EMB];
__device__ float g_go[BN];
__device__ float g_xf1[BN*24];
__device__ float g_xf2[BN*24];
__device__ float g_yf1[BN*TT];
__device__ float g_yf2[BN*TT];
__device__ float g_Wge[208*128];
__device__ float g_Wgd[208*128];
__device__ float g_Wue[208*64];
__device__ float g_Wud[208*64];

__device__ __forceinline__ int wmap(int c) {
    if (c < 64)  return c + 2;
    if (c < 128) return c + 4;
    if (c < 192) return c + 6;
    return ((c - 192) >> 1) * 66 + (c & 1);
}

// ---------------- tf32 helpers ----------------
__device__ __forceinline__ unsigned f2tf(float f) {
    unsigned u;
    asm("cvt.rna.tf32.f32 %0, %1;" : "=r"(u) : "f"(f));
    return u;
}
__device__ __forceinline__ float tf32r(float f) { return __uint_as_float(f2tf(f)); }

__device__ __forceinline__ void mma_tf32(float* d,
    unsigned a0, unsigned a1, unsigned a2, unsigned a3,
    unsigned b0, unsigned b1) {
    asm volatile(
        "mma.sync.aligned.m16n8k8.row.col.f32.tf32.tf32.f32 "
        "{%0,%1,%2,%3}, {%4,%5,%6,%7}, {%8,%9}, {%0,%1,%2,%3};\n"
        : "+f"(d[0]), "+f"(d[1]), "+f"(d[2]), "+f"(d[3])
        : "r"(a0), "r"(a1), "r"(a2), "r"(a3), "r"(b0), "r"(b1));
}

__device__ __forceinline__ void cpa16(void* smem, const void* g) {
    unsigned s = (unsigned)__cvta_generic_to_shared(smem);
    asm volatile("cp.async.cg.shared.global [%0], [%1], 16;\n" :: "r"(s), "l"(g));
}
#define CP_COMMIT() asm volatile("cp.async.commit_group;\n" ::: "memory")
#define CP_WAIT1()  asm volatile("cp.async.wait_group 1;\n" ::: "memory")
#define CP_WAIT0()  asm volatile("cp.async.wait_group 0;\n" ::: "memory")

// ---------------- init ----------------
__global__ void k_zero() {
    size_t i = (size_t)blockIdx.x*blockDim.x + threadIdx.x;
    size_t st = (size_t)gridDim.x*blockDim.x;
    for (size_t j=i; j<(size_t)BN*XGP; j+=st) g_xg[j] = 0.f;
    for (size_t j=i; j<BN*HID; j+=st) g_h[j]  = 0.f;
    for (size_t j=i; j<BN;     j+=st) g_go[j] = 0.f;
}

// ---------------- weight reorder + round (0=ge,1=gd,2=ue,3=ud) --------------
__global__ void k_prep(const float* __restrict__ W, int which) {
    int nc = (which < 2) ? 128 : 64;
    float* dst = (which == 0) ? g_Wge : (which == 1) ? g_Wgd
               : (which == 2) ? g_Wue : g_Wud;
    int idx = blockIdx.x*blockDim.x + threadIdx.x;
    if (idx >= 208*nc) return;
    int c = idx / nc, o = idx - c*nc;
    float v = 0.f;
    if (c < 198) v = W[wmap(c)*nc + o];
    dst[idx] = tf32r(v);
}

// ---------------- supports (emit tf32-rounded) ----------------
__global__ void k_support_en(const float* __restrict__ emb) {
    int n = blockIdx.x, tid = threadIdx.x;
    __shared__ float embn[EMB];
    __shared__ float row[NN];
    __shared__ float red[256];
    if (tid < EMB) embn[tid] = emb[n*EMB + tid];
    __syncthreads();
    for (int m=tid; m<NN; m+=256) {
        float s = 0.f;
        #pragma unroll
        for (int e=0; e<EMB; e++) s += embn[e]*emb[m*EMB+e];
        row[m] = fmaxf(s, 0.f);
    }
    __syncthreads();
    float lm = -1e30f;
    for (int m=tid; m<NN; m+=256) lm = fmaxf(lm, row[m]);
    red[tid]=lm; __syncthreads();
    for (int s=128;s>0;s>>=1){ if(tid<s) red[tid]=fmaxf(red[tid],red[tid+s]); __syncthreads(); }
    float mx = red[0]; __syncthreads();
    float ls = 0.f;
    for (int m=tid; m<NN; m+=256){ float e=expf(row[m]-mx); row[m]=e; ls+=e; }
    red[tid]=ls; __syncthreads();
    for (int s=128;s>0;s>>=1){ if(tid<s) red[tid]+=red[tid+s]; __syncthreads(); }
    float inv = 1.f/red[0];
    for (int m=tid; m<NN; m+=256) g_sup_en[n*NN+m] = tf32r(row[m]*inv);
}

__global__ void k_support_de() {
    int bn = blockIdx.x;
    int b = bn >> 9, n = bn & 511;
    int tid = threadIdx.x;
    const float* neb = g_ne + (size_t)b*NN*EMB;
    __shared__ float embn[EMB];
    __shared__ float row[NN];
    __shared__ float red[256];
    if (tid < EMB) embn[tid] = neb[n*EMB + tid];
    __syncthreads();
    for (int m=tid; m<NN; m+=256) {
        float s = 0.f;
        #pragma unroll
        for (int e=0; e<EMB; e++) s += embn[e]*neb[m*EMB+e];
        row[m] = fmaxf(s, 0.f);
    }
    __syncthreads();
    float lm = -1e30f;
    for (int m=tid; m<NN; m+=256) lm = fmaxf(lm, row[m]);
    red[tid]=lm; __syncthreads();
    for (int s=128;s>0;s>>=1){ if(tid<s) red[tid]=fmaxf(red[tid],red[tid+s]); __syncthreads(); }
    float mx = red[0]; __syncthreads();
    float ls = 0.f;
    for (int m=tid; m<NN; m+=256){ float e=expf(row[m]-mx); row[m]=e; ls+=e; }
    red[tid]=ls; __syncthreads();
    for (int s=128;s>0;s>>=1){ if(tid<s) red[tid]+=red[tid+s]; __syncthreads(); }
    float inv = 1.f/red[0];
    float* outr = g_sup_de + (size_t)b*NN*NN + (size_t)n*NN;
    for (int m=tid; m<NN; m+=256) outr[m] = tf32r(row[m]*inv);
}

// ---------------- S2 = S @ S  (TF32 MMA, CTA 128x64, static smem) -----------
__global__ void __launch_bounds__(256) k_sq(int deFlag) {
    __shared__ float As[3][128*20];
    __shared__ float Bs[3][16*72];
    const int b  = blockIdx.z;
    const int m0 = blockIdx.x*128;
    const int n0 = blockIdx.y*64;
    const int tid = threadIdx.x;
    const int warp = tid >> 5, lane = tid & 31;
    const int mw = warp & 3, nw = warp >> 2;
    const int tq = lane >> 2, tr = lane & 3;
    const float* S = deFlag ? g_sup_de + (size_t)b*NN*NN : g_sup_en;
    float* D       = deFlag ? g_s2_de  + (size_t)b*NN*NN : g_s2_en;
    const int lr = tid >> 1, lc = (tid & 1)*8;
    const int bk = tid >> 4, bn = (tid & 15)*4;

    float acc[2][4][4] = {};

#define SQ_LOAD(st, k0) do { \
    cpa16(&As[st][lr*20+lc],   &S[(size_t)(m0+lr)*NN + (k0)+lc]); \
    cpa16(&As[st][lr*20+lc+4], &S[(size_t)(m0+lr)*NN + (k0)+lc+4]); \
    cpa16(&Bs[st][bk*72+bn],   &S[(size_t)((k0)+bk)*NN + n0 + bn]); \
} while(0)

    SQ_LOAD(0, 0);  CP_COMMIT();
    SQ_LOAD(1, 16); CP_COMMIT();
    for (int kt = 0; kt < 32; kt++) {
        CP_WAIT1();
        __syncthreads();
        if (kt < 30) SQ_LOAD((kt+2)%3, (kt+2)*16);
        CP_COMMIT();
        const float* Ab = As[kt%3];
        const float* Bb = Bs[kt%3];
        #pragma unroll
        for (int ks = 0; ks < 16; ks += 8) {
            unsigned a[2][4], bb[4][2];
            #pragma unroll
            for (int mi = 0; mi < 2; mi++) {
                int r = mw*32 + mi*16 + tq;
                a[mi][0] = __float_as_uint(Ab[r*20 + ks + tr]);
                a[mi][1] = __float_as_uint(Ab[(r+8)*20 + ks + tr]);
                a[mi][2] = __float_as_uint(Ab[r*20 + ks + tr + 4]);
                a[mi][3] = __float_as_uint(Ab[(r+8)*20 + ks + tr + 4]);
            }
            #pragma unroll
            for (int nj = 0; nj < 4; nj++) {
                int c = nw*32 + nj*8 + tq;
                bb[nj][0] = __float_as_uint(Bb[(ks+tr)*72 + c]);
                bb[nj][1] = __float_as_uint(Bb[(ks+tr+4)*72 + c]);
            }
            #pragma unroll
            for (int mi = 0; mi < 2; mi++)
                #pragma unroll
                for (int nj = 0; nj < 4; nj++)
                    mma_tf32(acc[mi][nj], a[mi][0], a[mi][1], a[mi][2], a[mi][3],
                             bb[nj][0], bb[nj][1]);
        }
    }
    __syncthreads();
    #pragma unroll
    for (int mi = 0; mi < 2; mi++) {
        int r0 = m0 + mw*32 + mi*16 + tq;
        #pragma unroll
        for (int nj = 0; nj < 4; nj++) {
            int c = n0 + nw*32 + nj*8 + tr*2;
            float2 o0 = make_float2(tf32r(acc[mi][nj][0]), tf32r(acc[mi][nj][1]));
            float2 o1 = make_float2(tf32r(acc[mi][nj][2]), tf32r(acc[mi][nj][3]));
            *(float2*)&D[(size_t)r0*NN + c]     = o0;
            *(float2*)&D[(size_t)(r0+8)*NN + c] = o1;
        }
    }
#undef SQ_LOAD
}

// ---------------- x/ycov feature precompute ---------------------------------
__global__ void __launch_bounds__(256) k_pre_enc(const float* __restrict__ x) {
    __shared__ float xsh[512*24];
    int b = blockIdx.y, m0 = blockIdx.x*32, z = blockIdx.z;
    int tid = threadIdx.x;
    for (int idx = tid; idx < 512*24; idx += 256) {
        int k = idx/24, tc = idx%24;
        int t = tc>>1, c = tc&1;
        xsh[idx] = x[(((size_t)b*TT+t)*NN + k)*2 + c];
    }
    __syncthreads();
    int rl = tid>>3, kh = (tid>>2)&1, cg = tid&3;
    int row = m0 + rl, g = cg*6;
    float acc[6] = {};
    const float* Srow = (z ? g_s2_en : g_sup_en) + (size_t)row*NN + kh*256;
    const float* xp = &xsh[kh*256*24];
    for (int k=0;k<256;k+=4){
        float4 s = *(const float4*)&Srow[k];
        #pragma unroll
        for (int j=0;j<6;j++)
            acc[j] += s.x*xp[(k+0)*24+g+j] + s.y*xp[(k+1)*24+g+j]
                    + s.z*xp[(k+2)*24+g+j] + s.w*xp[(k+3)*24+g+j];
    }
    #pragma unroll
    for (int j=0;j<6;j++) acc[j] += __shfl_xor_sync(0xffffffffu, acc[j], 4);
    if (kh == 0) {
        #pragma unroll
        for (int j=0;j<6;j++) {
            int col = g + j;
            if (z == 0) g_xf1[((size_t)b*NN + row)*24 + col] = acc[j];
            else {
                int t = col>>1, c = col&1;
                g_xf2[((size_t)b*NN + row)*24 + col] =
                    2.f*acc[j] - x[(((size_t)b*TT+t)*NN + row)*2 + c];
            }
        }
    }
}

__global__ void __launch_bounds__(256) k_pre_dec(const float* __restrict__ ycov) {
    __shared__ float ysh[512*12];
    int b = blockIdx.y, m0 = blockIdx.x*32, z = blockIdx.z;
    int tid = threadIdx.x;
    for (int idx = tid; idx < 512*12; idx += 256) {
        int k = idx/12, t = idx%12;
        ysh[idx] = ycov[((size_t)b*TT+t)*NN + k];
    }
    __syncthreads();
    int rl = tid>>3, kh = (tid>>2)&1, cg = tid&3;
    int row = m0 + rl, g = cg*3;
    float acc[3] = {};
    const float* Srow = (z ? g_s2_de : g_sup_de) + (size_t)b*NN*NN + (size_t)row*NN + kh*256;
    const float* yp = &ysh[kh*256*12];
    for (int k=0;k<256;k+=4){
        float4 s = *(const float4*)&Srow[k];
        #pragma unroll
        for (int j=0;j<3;j++)
            acc[j] += s.x*yp[(k+0)*12+g+j] + s.y*yp[(k+1)*12+g+j]
                    + s.z*yp[(k+2)*12+g+j] + s.w*yp[(k+3)*12+g+j];
    }
    #pragma unroll
    for (int j=0;j<3;j++) acc[j] += __shfl_xor_sync(0xffffffffu, acc[j], 4);
    if (kh == 0) {
        #pragma unroll
        for (int j=0;j<3;j++) {
            int t = g + j;
            if (z == 0) g_yf1[((size_t)b*NN + row)*12 + t] = acc[j];
            else        g_yf2[((size_t)b*NN + row)*12 + t] =
                            2.f*acc[j] - ycov[((size_t)b*TT+t)*NN + row];
        }
    }
}

// ---------------- fused cell-phase kernel ------------------------------------
// phase 0: gate  (spmm on X -> gate GEMM(128 out) -> z*h, r)
// phase 1: update(spmm on z*h -> upd GEMM(64 out) -> h; decoder: + proj/out)
__global__ void __launch_bounds__(256) k_cell(
    int phase, int deFlag, int t,
    const float* __restrict__ x, const float* __restrict__ ycov,
    const float* __restrict__ bias,
    const float* __restrict__ pW, const float* __restrict__ pb,
    float* __restrict__ out)
{
    extern __shared__ float sm[];
    float* PAN = sm + OFF_PANEL;
    float* SS  = sm + OFF_S;
    float* S2S = sm + OFF_S2;
    float* XB  = sm + OFF_XB;
    float* GOs = sm + OFF_GO;
    __shared__ float pr[2][128];

    const int b  = blockIdx.y;
    const int m0 = blockIdx.x*128;
    const int tid = threadIdx.x;
    const int warp = tid >> 5, lane = tid & 31;
    const int mw = warp & 3, nw = warp >> 2;
    const int tq = lane >> 2, tr = lane & 3;

    const float* S  = deFlag ? g_sup_de + (size_t)b*NN*NN : g_sup_en;
    const float* S2 = deFlag ? g_s2_de  + (size_t)b*NN*NN : g_s2_en;
    float* Xg = g_xg + (size_t)b*NN*XGP;

    // ---- preload A-panel tiles 0..3 (X own rows) as cp.async group ----
    #pragma unroll
    for (int i = 0; i < 8; i++) {
        int ch = tid + i*256;              // 0..2047
        int row = ch >> 4, q = ch & 15;    // 16 chunks of 4 floats per row
        cpa16(&PAN[(q>>2)*TILE_F + row*20 + (q&3)*4],
              &Xg[(size_t)(m0+row)*XGP + q*4]);
    }
    if (deFlag) {
        GOs[tid]       = g_go[(size_t)b*NN + tid];
        GOs[tid + 256] = g_go[(size_t)b*NN + tid + 256];
    }
    CP_COMMIT();

    // ---- phase A: Y1 = S@X, Y2 = 2*S2@X - X (K=512) ----
    const int lr = tid >> 1, lc = (tid & 1)*8;
    const int bk = tid >> 4, bn = (tid & 15)*4;

    float acc1[2][4][4] = {};
    float acc2[2][4][4] = {};
    float d1 = 0.f, d2 = 0.f;
    const int mvrow = tid >> 1, mvh = (tid & 1)*8;

#define PA_LOAD(st, k0) do { \
    cpa16(&SS [(st)*TILE_F + lr*20+lc],   &S [(size_t)(m0+lr)*NN + (k0)+lc]); \
    cpa16(&SS [(st)*TILE_F + lr*20+lc+4], &S [(size_t)(m0+lr)*NN + (k0)+lc+4]); \
    cpa16(&S2S[(st)*TILE_F + lr*20+lc],   &S2[(size_t)(m0+lr)*NN + (k0)+lc]); \
    cpa16(&S2S[(st)*TILE_F + lr*20+lc+4], &S2[(size_t)(m0+lr)*NN + (k0)+lc+4]); \
    cpa16(&XB [(st)*1152 + bk*72+bn],     &Xg[(size_t)((k0)+bk)*XGP + bn]); \
} while(0)

    PA_LOAD(0, 0);  CP_COMMIT();
    PA_LOAD(1, 16); CP_COMMIT();
    for (int kt = 0; kt < 32; kt++) {
        CP_WAIT1();
        __syncthreads();
        if (kt < 30) PA_LOAD((kt+2)%3, (kt+2)*16);
        CP_COMMIT();
        const float* Ab  = SS  + (kt%3)*TILE_F;
        const float* A2b = S2S + (kt%3)*TILE_F;
        const float* Bb  = XB  + (kt%3)*1152;
        #pragma unroll
        for (int ks = 0; ks < 16; ks += 8) {
            unsigned a[2][4], a2[2][4], bb[4][2];
            #pragma unroll
            for (int mi = 0; mi < 2; mi++) {
                int r = mw*32 + mi*16 + tq;
                a [mi][0] = __float_as_uint(Ab [r*20 + ks + tr]);
                a [mi][1] = __float_as_uint(Ab [(r+8)*20 + ks + tr]);
                a [mi][2] = __float_as_uint(Ab [r*20 + ks + tr + 4]);
                a [mi][3] = __float_as_uint(Ab [(r+8)*20 + ks + tr + 4]);
                a2[mi][0] = __float_as_uint(A2b[r*20 + ks + tr]);
                a2[mi][1] = __float_as_uint(A2b[(r+8)*20 + ks + tr]);
                a2[mi][2] = __float_as_uint(A2b[r*20 + ks + tr + 4]);
                a2[mi][3] = __float_as_uint(A2b[(r+8)*20 + ks + tr + 4]);
            }
            #pragma unroll
            for (int nj = 0; nj < 4; nj++) {
                int c = nw*32 + nj*8 + tq;
                bb[nj][0] = __float_as_uint(Bb[(ks+tr)*72 + c]);
                bb[nj][1] = __float_as_uint(Bb[(ks+tr+4)*72 + c]);
            }
            #pragma unroll
            for (int mi = 0; mi < 2; mi++)
                #pragma unroll
                for (int nj = 0; nj < 4; nj++) {
                    mma_tf32(acc1[mi][nj], a [mi][0], a [mi][1], a [mi][2], a [mi][3],
                             bb[nj][0], bb[nj][1]);
                    mma_tf32(acc2[mi][nj], a2[mi][0], a2[mi][1], a2[mi][2], a2[mi][3],
                             bb[nj][0], bb[nj][1]);
                }
        }
        if (deFlag) {
            const float* gop = &GOs[kt*16 + mvh];
            #pragma unroll
            for (int j = 0; j < 8; j++) {
                d1 += Ab [mvrow*20 + mvh + j] * gop[j];
                d2 += A2b[mvrow*20 + mvh + j] * gop[j];
            }
        }
    }
    CP_WAIT0();
    __syncthreads();

    // ---- write Y1 (tiles 4..7) and Y2 (tiles 8..11) into panel ----
    #pragma unroll
    for (int mi = 0; mi < 2; mi++) {
        int r = mw*32 + mi*16 + tq;      // local row
        #pragma unroll
        for (int nj = 0; nj < 4; nj++) {
            int c = nw*32 + nj*8 + tr*2; // col 0..63 (even)
            int tI = c >> 4, kk = c & 15;
            #pragma unroll
            for (int hh = 0; hh < 2; hh++) {
                int rr = r + hh*8;
                float v1a = acc1[mi][nj][hh*2], v1b = acc1[mi][nj][hh*2+1];
                float v2a = acc2[mi][nj][hh*2], v2b = acc2[mi][nj][hh*2+1];
                float xa = PAN[tI*TILE_F + rr*20 + kk];
                float xb = PAN[tI*TILE_F + rr*20 + kk + 1];
                *(float2*)&PAN[(4+tI)*TILE_F + rr*20 + kk] =
                    make_float2(tf32r(v1a), tf32r(v1b));
                *(float2*)&PAN[(8+tI)*TILE_F + rr*20 + kk] =
                    make_float2(tf32r(2.f*v2a - xa), tf32r(2.f*v2b - xb));
            }
        }
    }

    // ---- fill tile 12 (feature cols 192..207) ----
    if (deFlag) {
        d1 += __shfl_xor_sync(0xffffffffu, d1, 1);
        d2 += __shfl_xor_sync(0xffffffffu, d2, 1);
        if ((tid & 1) == 0) {
            int row = tid >> 1;
            size_t gr = (size_t)b*NN + m0 + row;
            float go = GOs[m0 + row];
            float* T = &PAN[12*TILE_F + row*20];
            T[0] = tf32r(go);
            T[1] = tf32r(ycov[((size_t)b*TT + t)*NN + m0 + row]);
            T[2] = tf32r(d1);
            T[3] = tf32r(g_yf1[gr*12 + t]);
            T[4] = tf32r(2.f*d2 - go);
            T[5] = tf32r(g_yf2[gr*12 + t]);
            #pragma unroll
            for (int j = 6; j < 16; j++) T[j] = 0.f;
        }
    } else {
        if (tid < 128) {
            int row = tid;
            size_t gr = (size_t)b*NN + m0 + row;
            const float* xp = &x[(((size_t)b*TT + t)*NN + m0 + row)*2];
            float* T = &PAN[12*TILE_F + row*20];
            T[0] = tf32r(xp[0]);
            T[1] = tf32r(xp[1]);
            T[2] = tf32r(g_xf1[gr*24 + t*2 + 0]);
            T[3] = tf32r(g_xf1[gr*24 + t*2 + 1]);
            T[4] = tf32r(g_xf2[gr*24 + t*2 + 0]);
            T[5] = tf32r(g_xf2[gr*24 + t*2 + 1]);
            #pragma unroll
            for (int j = 6; j < 16; j++) T[j] = 0.f;
        }
    }
    __syncthreads();

    // ---- phase B: weight GEMM over K=208 from the panel ----
    float* WS = SS;  // reuse (phase A drained)

    if (phase == 0) {
        const float* W = deFlag ? g_Wgd : g_Wge;
        float acc[2][8][4] = {};
#define WB_LOAD128(st, k0) do { \
    { int rB = tid>>5, cB = (tid&31)*4; \
      cpa16(&WS[(st)*2176 + rB*136 + cB], &W[(size_t)((k0)+rB)*128 + cB]); } \
    { int rB = 8 + (tid>>5), cB = (tid&31)*4; \
      cpa16(&WS[(st)*2176 + rB*136 + cB], &W[(size_t)((k0)+rB)*128 + cB]); } \
} while(0)
        WB_LOAD128(0, 0); CP_COMMIT();
        for (int kt = 0; kt < 13; kt++) {
            if (kt+1 < 13) WB_LOAD128((kt+1)&1, (kt+1)*16);
            CP_COMMIT();
            CP_WAIT1();
            __syncthreads();
            const float* Ab = PAN + kt*TILE_F;
            const float* Bb = WS + (kt&1)*2176;
            #pragma unroll
            for (int ks = 0; ks < 16; ks += 8) {
                unsigned a[2][4], bb[8][2];
                #pragma unroll
                for (int mi = 0; mi < 2; mi++) {
                    int r = mw*32 + mi*16 + tq;
                    a[mi][0] = __float_as_uint(Ab[r*20 + ks + tr]);
                    a[mi][1] = __float_as_uint(Ab[(r+8)*20 + ks + tr]);
                    a[mi][2] = __float_as_uint(Ab[r*20 + ks + tr + 4]);
                    a[mi][3] = __float_as_uint(Ab[(r+8)*20 + ks + tr + 4]);
                }
                #pragma unroll
                for (int nj = 0; nj < 8; nj++) {
                    int c = nw*64 + nj*8 + tq;
                    bb[nj][0] = __float_as_uint(Bb[(ks+tr)*136 + c]);
                    bb[nj][1] = __float_as_uint(Bb[(ks+tr+4)*136 + c]);
                }
                #pragma unroll
                for (int mi = 0; mi < 2; mi++)
                    #pragma unroll
                    for (int nj = 0; nj < 8; nj++)
                        mma_tf32(acc[mi][nj], a[mi][0], a[mi][1], a[mi][2], a[mi][3],
                                 bb[nj][0], bb[nj][1]);
            }
            __syncthreads();
        }
        // epilogue: z*h -> g_xg, r -> g_r
        #pragma unroll
        for (int mi = 0; mi < 2; mi++) {
            int r0 = mw*32 + mi*16 + tq;
            #pragma unroll
            for (int nj = 0; nj < 8; nj++) {
                int c = nw*64 + nj*8 + tr*2;
                #pragma unroll
                for (int hh = 0; hh < 2; hh++) {
                    size_t row = (size_t)b*NN + m0 + r0 + hh*8;
                    float va = acc[mi][nj][hh*2], vb = acc[mi][nj][hh*2+1];
                    float za = 1.f/(1.f + expf(-(va + bias[c])));
                    float zb = 1.f/(1.f + expf(-(vb + bias[c+1])));
                    if (c < 64) {
                        g_xg[row*XGP + c]   = tf32r(za * g_h[row*HID + c]);
                        g_xg[row*XGP + c+1] = tf32r(zb * g_h[row*HID + c+1]);
                    } else {
                        g_r[row*HID + (c-64)]   = za;
                        g_r[row*HID + (c-64)+1] = zb;
                    }
                }
            }
        }
#undef WB_LOAD128
    } else {
        const float* W = deFlag ? g_Wud : g_Wue;
        float acc[2][4][4] = {};
#define WB_LOAD64(st, k0) do { \
    int rB = tid>>4, cB = (tid&15)*4; \
    cpa16(&WS[(st)*1152 + rB*72 + cB], &W[(size_t)((k0)+rB)*64 + cB]); \
} while(0)
        WB_LOAD64(0, 0); CP_COMMIT();
        for (int kt = 0; kt < 13; kt++) {
            if (kt+1 < 13) WB_LOAD64((kt+1)&1, (kt+1)*16);
            CP_COMMIT();
            CP_WAIT1();
            __syncthreads();
            const float* Ab = PAN + kt*TILE_F;
            const float* Bb = WS + (kt&1)*1152;
            #pragma unroll
            for (int ks = 0; ks < 16; ks += 8) {
                unsigned a[2][4], bb[4][2];
                #pragma unroll
                for (int mi = 0; mi < 2; mi++) {
                    int r = mw*32 + mi*16 + tq;
                    a[mi][0] = __float_as_uint(Ab[r*20 + ks + tr]);
                    a[mi][1] = __float_as_uint(Ab[(r+8)*20 + ks + tr]);
                    a[mi][2] = __float_as_uint(Ab[r*20 + ks + tr + 4]);
                    a[mi][3] = __float_as_uint(Ab[(r+8)*20 + ks + tr + 4]);
                }
                #pragma unroll
                for (int nj = 0; nj < 4; nj++) {
                    int c = nw*32 + nj*8 + tq;
                    bb[nj][0] = __float_as_uint(Bb[(ks+tr)*72 + c]);
                    bb[nj][1] = __float_as_uint(Bb[(ks+tr+4)*72 + c]);
                }
                #pragma unroll
                for (int mi = 0; mi < 2; mi++)
                    #pragma unroll
                    for (int nj = 0; nj < 4; nj++)
                        mma_tf32(acc[mi][nj], a[mi][0], a[mi][1], a[mi][2], a[mi][3],
                                 bb[nj][0], bb[nj][1]);
            }
            __syncthreads();
        }
        // epilogue: h update (+ projection for decoder)
        const bool doProj = (deFlag != 0);
        float rowsum[2][2] = {};
        #pragma unroll
        for (int mi = 0; mi < 2; mi++) {
            int r0 = mw*32 + mi*16 + tq;
            #pragma unroll
            for (int nj = 0; nj < 4; nj++) {
                int c = nw*32 + nj*8 + tr*2;
                #pragma unroll
                for (int hh = 0; hh < 2; hh++) {
                    size_t row = (size_t)b*NN + m0 + r0 + hh*8;
                    #pragma unroll
                    for (int jj = 0; jj < 2; jj++) {
                        int o = c + jj;
                        float hc = tanhf(acc[mi][nj][hh*2+jj] + bias[o]);
                        float r  = g_r[row*HID + o];
                        float h  = g_h[row*HID + o];
                        float hn = r*h + (1.f - r)*hc;
                        g_h[row*HID + o] = hn;
                        g_xg[row*XGP + o] = tf32r(hn);
                        if (doProj) rowsum[mi][hh] += hn * pW[o];
                    }
                }
            }
        }
        if (doProj) {
            #pragma unroll
            for (int mi = 0; mi < 2; mi++)
                #pragma unroll
                for (int hh = 0; hh < 2; hh++) {
                    float v = rowsum[mi][hh];
                    v += __shfl_xor_sync(0xffffffffu, v, 1);
                    v += __shfl_xor_sync(0xffffffffu, v, 2);
                    if (tr == 0) pr[nw][mw*32 + mi*16 + tq + hh*8] = v;
                }
            __syncthreads();
            if (tid < 128) {
                int n = m0 + tid;
                float go = pr[0][tid] + pr[1][tid] + pb[0];
                g_go[(size_t)b*NN + n] = go;
                out[((size_t)b*TT + t)*NN + n] = go;
            }
        }
#undef WB_LOAD64
    }
#undef PA_LOAD
}

// ---------------- hyper projection ------------------------------------------
__global__ void k_hyper(const float* __restrict__ hW, const float* __restrict__ hb) {
    int idx = blockIdx.x*blockDim.x + threadIdx.x;
    if (idx >= BN*EMB) return;
    int bn = idx / EMB, e = idx % EMB;
    float s = hb[e];
    #pragma unroll
    for (int k = 0; k < HID; k++) s += g_h[(size_t)bn*HID + k] * hW[k*EMB + e];
    g_ne[idx] = s;
}

// ---------------- orchestration ---------------------------------------------
extern "C" void kernel_launch(void* const* d_in, const int* in_sizes, int n_in,
                              void* d_out, int out_size) {
    const float* x       = (const float*)d_in[0];
    const float* ycov    = (const float*)d_in[1];
    const float* emb     = (const float*)d_in[2];
    const float* enc_gW  = (const float*)d_in[3];
    const float* enc_gb  = (const float*)d_in[4];
    const float* enc_uW  = (const float*)d_in[5];
    const float* enc_ub  = (const float*)d_in[6];
    const float* dec_gW  = (const float*)d_in[7];
    const float* dec_gb  = (const float*)d_in[8];
    const float* dec_uW  = (const float*)d_in[9];
    const float* dec_ub  = (const float*)d_in[10];
    const float* proj_W  = (const float*)d_in[11];
    const float* proj_b  = (const float*)d_in[12];
    const float* hyper_W = (const float*)d_in[13];
    const float* hyper_b = (const float*)d_in[14];
    float* out = (float*)d_out;

    static int smem_set = 0;
    if (!smem_set) {
        cudaFuncSetAttribute(k_cell, cudaFuncAttributeMaxDynamicSharedMemorySize,
                             SM_BYTES);
        smem_set = 1;
    }

    dim3 gs_cell(4, BB);
    dim3 gs_sq_en(4, 8, 1);
    dim3 gs_sq_de(4, 8, BB);
    dim3 gs_pre(16, BB, 2);

    k_zero<<<1024, 256>>>();
    k_prep<<<(208*128+255)/256, 256>>>(enc_gW, 0);
    k_prep<<<(208*128+255)/256, 256>>>(dec_gW, 1);
    k_prep<<<(208*64+255)/256, 256>>>(enc_uW, 2);
    k_prep<<<(208*64+255)/256, 256>>>(dec_uW, 3);
    k_support_en<<<NN, 256>>>(emb);
    k_sq<<<gs_sq_en, 256>>>(0);
    k_pre_enc<<<gs_pre, 256>>>(x);

    for (int t = 0; t < TT; t++) {
        k_cell<<<gs_cell, 256, SM_BYTES>>>(0, 0, t, x, ycov, enc_gb,
                                           nullptr, nullptr, nullptr);
        k_cell<<<gs_cell, 256, SM_BYTES>>>(1, 0, t, x, ycov, enc_ub,
                                           nullptr, nullptr, nullptr);
    }

    k_hyper<<<(BN*EMB + 255)/256, 256>>>(hyper_W, hyper_b);
    k_support_de<<<BN, 256>>>();
    k_sq<<<gs_sq_de, 256>>>(1);
    k_pre_dec<<<gs_pre, 256>>>(ycov);

    for (int t = 0; t < TT; t++) {
        k_cell<<<gs_cell, 256, SM_BYTES>>>(0, 1, t, x, ycov, dec_gb,
                                           nullptr, nullptr, nullptr);
        k_cell<<<gs_cell, 256, SM_BYTES>>>(1, 1, t, x, ycov, dec_ub,
                                           proj_W, proj_b, out);
    }
}

// round 9
// speedup vs baseline: 3.4227x; 1.4180x over previous
#include <cuda_runtime.h>
#include <cuda_fp16.h>
#include <math.h>

// ---------------- problem constants ----------------
#define BB   32
#define TT   12
#define NN   512
#define HID  64
#define EMB  10
#define BN   (BB*NN)     // 16384

// Feature K layout for the weight GEMM (208 rows):
//  0..63   X (h or z*h) | 64..127 S@X | 128..191 2S^2X-X
//  192..197 [x0,x1,Sx0,Sx1,S2x0,S2x1] | 198..207 zero pad

// ---------------- dynamic smem layout (bytes) ----------------
// half tiles: 128 rows x 24 halves (pitch 24) = 6144 B
#define TILEH   3072        // halves per 128x24 tile
#define TILEB   6144
#define OFF_PAN 0           // 13 tiles       -> 79872
#define OFF_SS  79872       // 3 stages S     -> 18432
#define OFF_S2  98304       // 3 stages S2    -> 18432
#define OFF_XB  116736      // 3 stages 64x24 -> 9216
#define OFF_GO  125952      // 512 floats     -> 2048
#define SM_BYTES 128000

// ---------------- device scratch ----------------
__device__ float  g_h[BN*HID];
__device__ float  g_r[BN*HID];
__device__ __half g_x0 [BN*64];          // h, row-major
__device__ __half g_x0T[BB*64*NN];       // h, [b][c][n]
__device__ __half g_x1 [BN*64];          // z*h, row-major
__device__ __half g_x1T[BB*64*NN];
__device__ float  g_sup_en_f[NN*NN];
__device__ __half g_sup_en_h[NN*NN];
__device__ float  g_sup_de_f[(size_t)BB*NN*NN];
__device__ __half g_sup_de_h[(size_t)BB*NN*NN];
__device__ float  g_s2_en_f[NN*NN];
__device__ __half g_s2_en_h[NN*NN];
__device__ float  g_s2_de_f[(size_t)BB*NN*NN];
__device__ __half g_s2_de_h[(size_t)BB*NN*NN];
__device__ float  g_ne[BN*EMB];
__device__ float  g_go[BN];
__device__ float  g_xf1[BN*24];
__device__ float  g_xf2[BN*24];
__device__ float  g_yf1[BN*TT];
__device__ float  g_yf2[BN*TT];
// transposed fp16 weights: [n][208]
__device__ __half g_WgeT[128*208];
__device__ __half g_WgdT[128*208];
__device__ __half g_WueT[64*208];
__device__ __half g_WudT[64*208];

__device__ __forceinline__ int wmap(int c) {
    if (c < 64)  return c + 2;
    if (c < 128) return c + 4;
    if (c < 192) return c + 6;
    return ((c - 192) >> 1) * 66 + (c & 1);
}

// ---------------- mma helpers ----------------
__device__ __forceinline__ unsigned f2tf(float f) {
    unsigned u;
    asm("cvt.rna.tf32.f32 %0, %1;" : "=r"(u) : "f"(f));
    return u;
}
__device__ __forceinline__ void mma_tf32(float* d,
    unsigned a0, unsigned a1, unsigned a2, unsigned a3,
    unsigned b0, unsigned b1) {
    asm volatile(
        "mma.sync.aligned.m16n8k8.row.col.f32.tf32.tf32.f32 "
        "{%0,%1,%2,%3}, {%4,%5,%6,%7}, {%8,%9}, {%0,%1,%2,%3};\n"
        : "+f"(d[0]), "+f"(d[1]), "+f"(d[2]), "+f"(d[3])
        : "r"(a0), "r"(a1), "r"(a2), "r"(a3), "r"(b0), "r"(b1));
}
__device__ __forceinline__ void mma_f16(float* d,
    unsigned a0, unsigned a1, unsigned a2, unsigned a3,
    unsigned b0, unsigned b1) {
    asm volatile(
        "mma.sync.aligned.m16n8k16.row.col.f32.f16.f16.f32 "
        "{%0,%1,%2,%3}, {%4,%5,%6,%7}, {%8,%9}, {%0,%1,%2,%3};\n"
        : "+f"(d[0]), "+f"(d[1]), "+f"(d[2]), "+f"(d[3])
        : "r"(a0), "r"(a1), "r"(a2), "r"(a3), "r"(b0), "r"(b1));
}

__device__ __forceinline__ void cpa16(void* smem, const void* g) {
    unsigned s = (unsigned)__cvta_generic_to_shared(smem);
    asm volatile("cp.async.cg.shared.global [%0], [%1], 16;\n" :: "r"(s), "l"(g));
}
#define CP_COMMIT() asm volatile("cp.async.commit_group;\n" ::: "memory")
#define CP_WAIT1()  asm volatile("cp.async.wait_group 1;\n" ::: "memory")
#define CP_WAIT0()  asm volatile("cp.async.wait_group 0;\n" ::: "memory")

// ---------------- init ----------------
__global__ void k_zero() {
    size_t i = (size_t)blockIdx.x*blockDim.x + threadIdx.x;
    size_t st = (size_t)gridDim.x*blockDim.x;
    const __half hz = __float2half(0.f);
    for (size_t j=i; j<(size_t)BN*64; j+=st) { g_x0[j] = hz; g_x0T[j] = hz; }
    for (size_t j=i; j<BN*HID; j+=st) g_h[j]  = 0.f;
    for (size_t j=i; j<BN;     j+=st) g_go[j] = 0.f;
}

// ---------------- weight reorder (transposed fp16) --------------------------
__global__ void k_prep(const float* __restrict__ W, int which) {
    int nc = (which < 2) ? 128 : 64;
    __half* dst = (which == 0) ? g_WgeT : (which == 1) ? g_WgdT
               : (which == 2) ? g_WueT : g_WudT;
    int idx = blockIdx.x*blockDim.x + threadIdx.x;
    if (idx >= 208*nc) return;
    int c = idx / nc, o = idx - c*nc;
    float v = 0.f;
    if (c < 198) v = W[wmap(c)*nc + o];
    dst[(size_t)o*208 + c] = __float2half(v);
}

// ---------------- supports (fp32 + fp16 copies) ----------------
__global__ void k_support_en(const float* __restrict__ emb) {
    int n = blockIdx.x, tid = threadIdx.x;
    __shared__ float embn[EMB];
    __shared__ float row[NN];
    __shared__ float red[256];
    if (tid < EMB) embn[tid] = emb[n*EMB + tid];
    __syncthreads();
    for (int m=tid; m<NN; m+=256) {
        float s = 0.f;
        #pragma unroll
        for (int e=0; e<EMB; e++) s += embn[e]*emb[m*EMB+e];
        row[m] = fmaxf(s, 0.f);
    }
    __syncthreads();
    float lm = -1e30f;
    for (int m=tid; m<NN; m+=256) lm = fmaxf(lm, row[m]);
    red[tid]=lm; __syncthreads();
    for (int s=128;s>0;s>>=1){ if(tid<s) red[tid]=fmaxf(red[tid],red[tid+s]); __syncthreads(); }
    float mx = red[0]; __syncthreads();
    float ls = 0.f;
    for (int m=tid; m<NN; m+=256){ float e=expf(row[m]-mx); row[m]=e; ls+=e; }
    red[tid]=ls; __syncthreads();
    for (int s=128;s>0;s>>=1){ if(tid<s) red[tid]+=red[tid+s]; __syncthreads(); }
    float inv = 1.f/red[0];
    for (int m=tid; m<NN; m+=256) {
        float v = row[m]*inv;
        g_sup_en_f[n*NN+m] = v;
        g_sup_en_h[n*NN+m] = __float2half(v);
    }
}

__global__ void k_support_de() {
    int bn = blockIdx.x;
    int b = bn >> 9, n = bn & 511;
    int tid = threadIdx.x;
    const float* neb = g_ne + (size_t)b*NN*EMB;
    __shared__ float embn[EMB];
    __shared__ float row[NN];
    __shared__ float red[256];
    if (tid < EMB) embn[tid] = neb[n*EMB + tid];
    __syncthreads();
    for (int m=tid; m<NN; m+=256) {
        float s = 0.f;
        #pragma unroll
        for (int e=0; e<EMB; e++) s += embn[e]*neb[m*EMB+e];
        row[m] = fmaxf(s, 0.f);
    }
    __syncthreads();
    float lm = -1e30f;
    for (int m=tid; m<NN; m+=256) lm = fmaxf(lm, row[m]);
    red[tid]=lm; __syncthreads();
    for (int s=128;s>0;s>>=1){ if(tid<s) red[tid]=fmaxf(red[tid],red[tid+s]); __syncthreads(); }
    float mx = red[0]; __syncthreads();
    float ls = 0.f;
    for (int m=tid; m<NN; m+=256){ float e=expf(row[m]-mx); row[m]=e; ls+=e; }
    red[tid]=ls; __syncthreads();
    for (int s=128;s>0;s>>=1){ if(tid<s) red[tid]+=red[tid+s]; __syncthreads(); }
    float inv = 1.f/red[0];
    size_t base = (size_t)b*NN*NN + (size_t)n*NN;
    for (int m=tid; m<NN; m+=256) {
        float v = row[m]*inv;
        g_sup_de_f[base+m] = v;
        g_sup_de_h[base+m] = __float2half(v);
    }
}

// ---------------- S2 = S @ S  (tf32 MMA on fp32 S; dual-format output) ------
__global__ void __launch_bounds__(256) k_sq(int deFlag) {
    __shared__ float As[3][128*20];
    __shared__ float Bs[3][16*72];
    const int b  = blockIdx.z;
    const int m0 = blockIdx.x*128;
    const int n0 = blockIdx.y*64;
    const int tid = threadIdx.x;
    const int warp = tid >> 5, lane = tid & 31;
    const int mw = warp & 3, nw = warp >> 2;
    const int tq = lane >> 2, tr = lane & 3;
    const float* S = deFlag ? g_sup_de_f + (size_t)b*NN*NN : g_sup_en_f;
    float*  Df = deFlag ? g_s2_de_f + (size_t)b*NN*NN : g_s2_en_f;
    __half* Dh = deFlag ? g_s2_de_h + (size_t)b*NN*NN : g_s2_en_h;
    const int lr = tid >> 1, lc = (tid & 1)*8;
    const int bk = tid >> 4, bn = (tid & 15)*4;

    float acc[2][4][4] = {};

#define SQ_LOAD(st, k0) do { \
    cpa16(&As[st][lr*20+lc],   &S[(size_t)(m0+lr)*NN + (k0)+lc]); \
    cpa16(&As[st][lr*20+lc+4], &S[(size_t)(m0+lr)*NN + (k0)+lc+4]); \
    cpa16(&Bs[st][bk*72+bn],   &S[(size_t)((k0)+bk)*NN + n0 + bn]); \
} while(0)

    SQ_LOAD(0, 0);  CP_COMMIT();
    SQ_LOAD(1, 16); CP_COMMIT();
    for (int kt = 0; kt < 32; kt++) {
        CP_WAIT1();
        __syncthreads();
        if (kt < 30) SQ_LOAD((kt+2)%3, (kt+2)*16);
        CP_COMMIT();
        const float* Ab = As[kt%3];
        const float* Bb = Bs[kt%3];
        #pragma unroll
        for (int ks = 0; ks < 16; ks += 8) {
            unsigned a[2][4], bb[4][2];
            #pragma unroll
            for (int mi = 0; mi < 2; mi++) {
                int r = mw*32 + mi*16 + tq;
                a[mi][0] = f2tf(Ab[r*20 + ks + tr]);
                a[mi][1] = f2tf(Ab[(r+8)*20 + ks + tr]);
                a[mi][2] = f2tf(Ab[r*20 + ks + tr + 4]);
                a[mi][3] = f2tf(Ab[(r+8)*20 + ks + tr + 4]);
            }
            #pragma unroll
            for (int nj = 0; nj < 4; nj++) {
                int c = nw*32 + nj*8 + tq;
                bb[nj][0] = f2tf(Bb[(ks+tr)*72 + c]);
                bb[nj][1] = f2tf(Bb[(ks+tr+4)*72 + c]);
            }
            #pragma unroll
            for (int mi = 0; mi < 2; mi++)
                #pragma unroll
                for (int nj = 0; nj < 4; nj++)
                    mma_tf32(acc[mi][nj], a[mi][0], a[mi][1], a[mi][2], a[mi][3],
                             bb[nj][0], bb[nj][1]);
        }
    }
    __syncthreads();
    #pragma unroll
    for (int mi = 0; mi < 2; mi++) {
        int r0 = m0 + mw*32 + mi*16 + tq;
        #pragma unroll
        for (int nj = 0; nj < 4; nj++) {
            int c = n0 + nw*32 + nj*8 + tr*2;
            #pragma unroll
            for (int hh = 0; hh < 2; hh++) {
                int rr = r0 + hh*8;
                float va = acc[mi][nj][hh*2], vb = acc[mi][nj][hh*2+1];
                *(float2*)&Df[(size_t)rr*NN + c] = make_float2(va, vb);
                *(__half2*)&Dh[(size_t)rr*NN + c] = __floats2half2_rn(va, vb);
            }
        }
    }
#undef SQ_LOAD
}

// ---------------- x/ycov feature precompute ---------------------------------
__global__ void __launch_bounds__(256) k_pre_enc(const float* __restrict__ x) {
    __shared__ float xsh[512*24];
    int b = blockIdx.y, m0 = blockIdx.x*32, z = blockIdx.z;
    int tid = threadIdx.x;
    for (int idx = tid; idx < 512*24; idx += 256) {
        int k = idx/24, tc = idx%24;
        int t = tc>>1, c = tc&1;
        xsh[idx] = x[(((size_t)b*TT+t)*NN + k)*2 + c];
    }
    __syncthreads();
    int rl = tid>>3, kh = (tid>>2)&1, cg = tid&3;
    int row = m0 + rl, g = cg*6;
    float acc[6] = {};
    const float* Srow = (z ? g_s2_en_f : g_sup_en_f) + (size_t)row*NN + kh*256;
    const float* xp = &xsh[kh*256*24];
    for (int k=0;k<256;k+=4){
        float4 s = *(const float4*)&Srow[k];
        #pragma unroll
        for (int j=0;j<6;j++)
            acc[j] += s.x*xp[(k+0)*24+g+j] + s.y*xp[(k+1)*24+g+j]
                    + s.z*xp[(k+2)*24+g+j] + s.w*xp[(k+3)*24+g+j];
    }
    #pragma unroll
    for (int j=0;j<6;j++) acc[j] += __shfl_xor_sync(0xffffffffu, acc[j], 4);
    if (kh == 0) {
        #pragma unroll
        for (int j=0;j<6;j++) {
            int col = g + j;
            if (z == 0) g_xf1[((size_t)b*NN + row)*24 + col] = acc[j];
            else {
                int t = col>>1, c = col&1;
                g_xf2[((size_t)b*NN + row)*24 + col] =
                    2.f*acc[j] - x[(((size_t)b*TT+t)*NN + row)*2 + c];
            }
        }
    }
}

__global__ void __launch_bounds__(256) k_pre_dec(const float* __restrict__ ycov) {
    __shared__ float ysh[512*12];
    int b = blockIdx.y, m0 = blockIdx.x*32, z = blockIdx.z;
    int tid = threadIdx.x;
    for (int idx = tid; idx < 512*12; idx += 256) {
        int k = idx/12, t = idx%12;
        ysh[idx] = ycov[((size_t)b*TT+t)*NN + k];
    }
    __syncthreads();
    int rl = tid>>3, kh = (tid>>2)&1, cg = tid&3;
    int row = m0 + rl, g = cg*3;
    float acc[3] = {};
    const float* Srow = (z ? g_s2_de_f : g_sup_de_f)
                        + (size_t)b*NN*NN + (size_t)row*NN + kh*256;
    const float* yp = &ysh[kh*256*12];
    for (int k=0;k<256;k+=4){
        float4 s = *(const float4*)&Srow[k];
        #pragma unroll
        for (int j=0;j<3;j++)
            acc[j] += s.x*yp[(k+0)*12+g+j] + s.y*yp[(k+1)*12+g+j]
                    + s.z*yp[(k+2)*12+g+j] + s.w*yp[(k+3)*12+g+j];
    }
    #pragma unroll
    for (int j=0;j<3;j++) acc[j] += __shfl_xor_sync(0xffffffffu, acc[j], 4);
    if (kh == 0) {
        #pragma unroll
        for (int j=0;j<3;j++) {
            int t = g + j;
            if (z == 0) g_yf1[((size_t)b*NN + row)*12 + t] = acc[j];
            else        g_yf2[((size_t)b*NN + row)*12 + t] =
                            2.f*acc[j] - ycov[((size_t)b*TT+t)*NN + row];
        }
    }
}

// ---------------- fused cell-phase kernel (fp16 MMA) -------------------------
// phase 0: gate  (reads g_x0/g_x0T, writes z*h -> g_x1/g_x1T, r -> g_r)
// phase 1: update(reads g_x1/g_x1T, writes h -> g_x0/g_x0T; decoder: proj/out)
__global__ void __launch_bounds__(256) k_cell(
    int phase, int deFlag, int t,
    const float* __restrict__ x, const float* __restrict__ ycov,
    const float* __restrict__ bias,
    const float* __restrict__ pW, const float* __restrict__ pb,
    float* __restrict__ out)
{
    extern __shared__ char smx[];
    __half* PAN = (__half*)(smx + OFF_PAN);
    __half* SS  = (__half*)(smx + OFF_SS);
    __half* S2S = (__half*)(smx + OFF_S2);
    __half* XB  = (__half*)(smx + OFF_XB);
    float*  GOs = (float*)(smx + OFF_GO);
    __shared__ float pr[2][128];

    const int b  = blockIdx.y;
    const int m0 = blockIdx.x*128;
    const int tid = threadIdx.x;
    const int warp = tid >> 5, lane = tid & 31;
    const int mw = warp & 3, nw = warp >> 2;
    const int tq = lane >> 2, tr = lane & 3;

    const __half* Sh  = deFlag ? g_sup_de_h + (size_t)b*NN*NN : g_sup_en_h;
    const __half* S2h = deFlag ? g_s2_de_h  + (size_t)b*NN*NN : g_s2_en_h;
    const __half* Xrow = (phase == 0) ? g_x0 : g_x1;   // row-major X
    const __half* XT   = (phase == 0) ? g_x0T : g_x1T; // transposed X

    // ---- preload panel tiles 0..3 (X own rows, [row][k16]) ----
    #pragma unroll
    for (int i = 0; i < 4; i++) {
        int ch = tid + i*256;                 // 0..1023
        int tI = ch >> 8, rw = (ch >> 1) & 127, off = (ch & 1)*8;
        cpa16(&PAN[tI*TILEH + rw*24 + off],
              &Xrow[((size_t)b*NN + m0 + rw)*64 + tI*16 + off]);
    }
    if (deFlag) {
        GOs[tid]       = g_go[(size_t)b*NN + tid];
        GOs[tid + 256] = g_go[(size_t)b*NN + tid + 256];
    }
    CP_COMMIT();

    // ---- phase A: Y1 = S@X, Y2raw = S2@X (K=512, 32 k16-tiles) ----
    const int lrA = tid >> 1, loA = (tid & 1)*8;

    float acc1[2][4][4] = {};
    float acc2[2][4][4] = {};
    float d1 = 0.f, d2 = 0.f;
    const int mvrow = tid >> 1, mvh = (tid & 1)*8;

#define PA_LOAD(st, k0) do { \
    cpa16(&SS [(st)*TILEH + lrA*24 + loA], &Sh [(size_t)(m0+lrA)*NN + (k0)+loA]); \
    cpa16(&S2S[(st)*TILEH + lrA*24 + loA], &S2h[(size_t)(m0+lrA)*NN + (k0)+loA]); \
    if (tid < 128) \
        cpa16(&XB[(st)*1536 + lrA*24 + loA], &XT[((size_t)b*64 + lrA)*NN + (k0)+loA]); \
} while(0)

    PA_LOAD(0, 0);  CP_COMMIT();
    PA_LOAD(1, 16); CP_COMMIT();
    for (int kt = 0; kt < 32; kt++) {
        CP_WAIT1();
        __syncthreads();
        if (kt < 30) PA_LOAD((kt+2)%3, (kt+2)*16);
        CP_COMMIT();
        const __half* Ab  = SS  + (kt%3)*TILEH;
        const __half* A2b = S2S + (kt%3)*TILEH;
        const __half* Bb  = XB  + (kt%3)*1536;
        unsigned a[2][4], a2[2][4], bb[4][2];
        #pragma unroll
        for (int mi = 0; mi < 2; mi++) {
            int r = mw*32 + mi*16 + tq;
            a [mi][0] = *(const unsigned*)&Ab [r*24 + 2*tr];
            a [mi][1] = *(const unsigned*)&Ab [(r+8)*24 + 2*tr];
            a [mi][2] = *(const unsigned*)&Ab [r*24 + 2*tr + 8];
            a [mi][3] = *(const unsigned*)&Ab [(r+8)*24 + 2*tr + 8];
            a2[mi][0] = *(const unsigned*)&A2b[r*24 + 2*tr];
            a2[mi][1] = *(const unsigned*)&A2b[(r+8)*24 + 2*tr];
            a2[mi][2] = *(const unsigned*)&A2b[r*24 + 2*tr + 8];
            a2[mi][3] = *(const unsigned*)&A2b[(r+8)*24 + 2*tr + 8];
        }
        #pragma unroll
        for (int nj = 0; nj < 4; nj++) {
            int c = nw*32 + nj*8 + tq;
            bb[nj][0] = *(const unsigned*)&Bb[c*24 + 2*tr];
            bb[nj][1] = *(const unsigned*)&Bb[c*24 + 2*tr + 8];
        }
        #pragma unroll
        for (int mi = 0; mi < 2; mi++)
            #pragma unroll
            for (int nj = 0; nj < 4; nj++) {
                mma_f16(acc1[mi][nj], a [mi][0], a [mi][1], a [mi][2], a [mi][3],
                        bb[nj][0], bb[nj][1]);
                mma_f16(acc2[mi][nj], a2[mi][0], a2[mi][1], a2[mi][2], a2[mi][3],
                        bb[nj][0], bb[nj][1]);
            }
        if (deFlag) {
            const __half2* ap  = (const __half2*)&Ab [mvrow*24 + mvh];
            const __half2* a2p = (const __half2*)&A2b[mvrow*24 + mvh];
            const float* gop = &GOs[kt*16 + mvh];
            #pragma unroll
            for (int j = 0; j < 4; j++) {
                float2 v  = __half22float2(ap[j]);
                float2 v2 = __half22float2(a2p[j]);
                d1 += v.x*gop[2*j] + v.y*gop[2*j+1];
                d2 += v2.x*gop[2*j] + v2.y*gop[2*j+1];
            }
        }
    }
    CP_WAIT0();
    __syncthreads();

    // ---- write Y1 (tiles 4..7), Y2 = 2*acc2 - X (tiles 8..11) ----
    #pragma unroll
    for (int mi = 0; mi < 2; mi++) {
        int r = mw*32 + mi*16 + tq;
        #pragma unroll
        for (int nj = 0; nj < 4; nj++) {
            int c = nw*32 + nj*8 + tr*2;
            int tI = c >> 4, kk = c & 15;
            #pragma unroll
            for (int hh = 0; hh < 2; hh++) {
                int rr = r + hh*8;
                float v1a = acc1[mi][nj][hh*2], v1b = acc1[mi][nj][hh*2+1];
                float v2a = acc2[mi][nj][hh*2], v2b = acc2[mi][nj][hh*2+1];
                float xa = __half2float(PAN[tI*TILEH + rr*24 + kk]);
                float xb = __half2float(PAN[tI*TILEH + rr*24 + kk + 1]);
                *(__half2*)&PAN[(4+tI)*TILEH + rr*24 + kk] =
                    __floats2half2_rn(v1a, v1b);
                *(__half2*)&PAN[(8+tI)*TILEH + rr*24 + kk] =
                    __floats2half2_rn(2.f*v2a - xa, 2.f*v2b - xb);
            }
        }
    }

    // ---- tile 12: extra features ----
    if (deFlag) {
        d1 += __shfl_xor_sync(0xffffffffu, d1, 1);
        d2 += __shfl_xor_sync(0xffffffffu, d2, 1);
        if ((tid & 1) == 0) {
            int rw = tid >> 1;
            size_t gr = (size_t)b*NN + m0 + rw;
            float go = GOs[m0 + rw];
            __half* T = &PAN[12*TILEH + rw*24];
            T[0] = __float2half(go);
            T[1] = __float2half(ycov[((size_t)b*TT + t)*NN + m0 + rw]);
            T[2] = __float2half(d1);
            T[3] = __float2half(g_yf1[gr*12 + t]);
            T[4] = __float2half(2.f*d2 - go);
            T[5] = __float2half(g_yf2[gr*12 + t]);
            #pragma unroll
            for (int j = 6; j < 16; j++) T[j] = __float2half(0.f);
        }
    } else {
        if (tid < 128) {
            int rw = tid;
            size_t gr = (size_t)b*NN + m0 + rw;
            const float* xp = &x[(((size_t)b*TT + t)*NN + m0 + rw)*2];
            __half* T = &PAN[12*TILEH + rw*24];
            T[0] = __float2half(xp[0]);
            T[1] = __float2half(xp[1]);
            T[2] = __float2half(g_xf1[gr*24 + t*2 + 0]);
            T[3] = __float2half(g_xf1[gr*24 + t*2 + 1]);
            T[4] = __float2half(g_xf2[gr*24 + t*2 + 0]);
            T[5] = __float2half(g_xf2[gr*24 + t*2 + 1]);
            #pragma unroll
            for (int j = 6; j < 16; j++) T[j] = __float2half(0.f);
        }
    }
    __syncthreads();

    // ---- phase B: weight GEMM over K=208 from the panel ----
    __half* WS = SS;   // reuse

    if (phase == 0) {
        const __half* WT = deFlag ? g_WgdT : g_WgeT;
        float acc[2][8][4] = {};
#define WB_LOAD128(st, k0) do { \
    int n_ = tid >> 1, of_ = (tid & 1)*8; \
    cpa16(&WS[(st)*TILEH + n_*24 + of_], &WT[(size_t)n_*208 + (k0)+of_]); \
} while(0)
        WB_LOAD128(0, 0);  CP_COMMIT();
        WB_LOAD128(1, 16); CP_COMMIT();
        for (int kt = 0; kt < 13; kt++) {
            CP_WAIT1();
            __syncthreads();
            if (kt < 11) WB_LOAD128((kt+2)%3, (kt+2)*16);
            CP_COMMIT();
            const __half* Ab = PAN + kt*TILEH;
            const __half* Bb = WS + (kt%3)*TILEH;
            unsigned a[2][4], bb[8][2];
            #pragma unroll
            for (int mi = 0; mi < 2; mi++) {
                int r = mw*32 + mi*16 + tq;
                a[mi][0] = *(const unsigned*)&Ab[r*24 + 2*tr];
                a[mi][1] = *(const unsigned*)&Ab[(r+8)*24 + 2*tr];
                a[mi][2] = *(const unsigned*)&Ab[r*24 + 2*tr + 8];
                a[mi][3] = *(const unsigned*)&Ab[(r+8)*24 + 2*tr + 8];
            }
            #pragma unroll
            for (int nj = 0; nj < 8; nj++) {
                int c = nw*64 + nj*8 + tq;
                bb[nj][0] = *(const unsigned*)&Bb[c*24 + 2*tr];
                bb[nj][1] = *(const unsigned*)&Bb[c*24 + 2*tr + 8];
            }
            #pragma unroll
            for (int mi = 0; mi < 2; mi++)
                #pragma unroll
                for (int nj = 0; nj < 8; nj++)
                    mma_f16(acc[mi][nj], a[mi][0], a[mi][1], a[mi][2], a[mi][3],
                            bb[nj][0], bb[nj][1]);
        }
        // epilogue: z = sigmoid -> z*h into g_x1/g_x1T ; r into g_r
        #pragma unroll
        for (int mi = 0; mi < 2; mi++) {
            int r0 = mw*32 + mi*16 + tq;
            #pragma unroll
            for (int nj = 0; nj < 8; nj++) {
                int c = nw*64 + nj*8 + tr*2;
                #pragma unroll
                for (int hh = 0; hh < 2; hh++) {
                    int ln = m0 + r0 + hh*8;
                    size_t row = (size_t)b*NN + ln;
                    float va = acc[mi][nj][hh*2], vb = acc[mi][nj][hh*2+1];
                    float za = 1.f/(1.f + expf(-(va + bias[c])));
                    float zb = 1.f/(1.f + expf(-(vb + bias[c+1])));
                    if (c < 64) {
                        float ha = za * g_h[row*HID + c];
                        float hb = zb * g_h[row*HID + c+1];
                        *(__half2*)&g_x1[row*64 + c] = __floats2half2_rn(ha, hb);
                        g_x1T[((size_t)b*64 + c  )*NN + ln] = __float2half(ha);
                        g_x1T[((size_t)b*64 + c+1)*NN + ln] = __float2half(hb);
                    } else {
                        g_r[row*HID + (c-64)]   = za;
                        g_r[row*HID + (c-64)+1] = zb;
                    }
                }
            }
        }
#undef WB_LOAD128
    } else {
        const __half* WT = deFlag ? g_WudT : g_WueT;
        float acc[2][4][4] = {};
#define WB_LOAD64(st, k0) do { \
    if (tid < 128) { int n_ = tid >> 1, of_ = (tid & 1)*8; \
        cpa16(&WS[(st)*1536 + n_*24 + of_], &WT[(size_t)n_*208 + (k0)+of_]); } \
} while(0)
        WB_LOAD64(0, 0);  CP_COMMIT();
        WB_LOAD64(1, 16); CP_COMMIT();
        for (int kt = 0; kt < 13; kt++) {
            CP_WAIT1();
            __syncthreads();
            if (kt < 11) WB_LOAD64((kt+2)%3, (kt+2)*16);
            CP_COMMIT();
            const __half* Ab = PAN + kt*TILEH;
            const __half* Bb = WS + (kt%3)*1536;
            unsigned a[2][4], bb[4][2];
            #pragma unroll
            for (int mi = 0; mi < 2; mi++) {
                int r = mw*32 + mi*16 + tq;
                a[mi][0] = *(const unsigned*)&Ab[r*24 + 2*tr];
                a[mi][1] = *(const unsigned*)&Ab[(r+8)*24 + 2*tr];
                a[mi][2] = *(const unsigned*)&Ab[r*24 + 2*tr + 8];
                a[mi][3] = *(const unsigned*)&Ab[(r+8)*24 + 2*tr + 8];
            }
            #pragma unroll
            for (int nj = 0; nj < 4; nj++) {
                int c = nw*32 + nj*8 + tq;
                bb[nj][0] = *(const unsigned*)&Bb[c*24 + 2*tr];
                bb[nj][1] = *(const unsigned*)&Bb[c*24 + 2*tr + 8];
            }
            #pragma unroll
            for (int mi = 0; mi < 2; mi++)
                #pragma unroll
                for (int nj = 0; nj < 4; nj++)
                    mma_f16(acc[mi][nj], a[mi][0], a[mi][1], a[mi][2], a[mi][3],
                            bb[nj][0], bb[nj][1]);
        }
        // epilogue: h update (+ projection for decoder)
        const bool doProj = (deFlag != 0);
        float rowsum[2][2] = {};
        #pragma unroll
        for (int mi = 0; mi < 2; mi++) {
            int r0 = mw*32 + mi*16 + tq;
            #pragma unroll
            for (int nj = 0; nj < 4; nj++) {
                int c = nw*32 + nj*8 + tr*2;
                #pragma unroll
                for (int hh = 0; hh < 2; hh++) {
                    int ln = m0 + r0 + hh*8;
                    size_t row = (size_t)b*NN + ln;
                    float hn2[2];
                    #pragma unroll
                    for (int jj = 0; jj < 2; jj++) {
                        int o = c + jj;
                        float hc = tanhf(acc[mi][nj][hh*2+jj] + bias[o]);
                        float r  = g_r[row*HID + o];
                        float h  = g_h[row*HID + o];
                        float hn = r*h + (1.f - r)*hc;
                        g_h[row*HID + o] = hn;
                        g_x0T[((size_t)b*64 + o)*NN + ln] = __float2half(hn);
                        hn2[jj] = hn;
                        if (doProj) rowsum[mi][hh] += hn * pW[o];
                    }
                    *(__half2*)&g_x0[row*64 + c] = __floats2half2_rn(hn2[0], hn2[1]);
                }
            }
        }
        if (doProj) {
            #pragma unroll
            for (int mi = 0; mi < 2; mi++)
                #pragma unroll
                for (int hh = 0; hh < 2; hh++) {
                    float v = rowsum[mi][hh];
                    v += __shfl_xor_sync(0xffffffffu, v, 1);
                    v += __shfl_xor_sync(0xffffffffu, v, 2);
                    if (tr == 0) pr[nw][mw*32 + mi*16 + tq + hh*8] = v;
                }
            __syncthreads();
            if (tid < 128) {
                int n = m0 + tid;
                float go = pr[0][tid] + pr[1][tid] + pb[0];
                g_go[(size_t)b*NN + n] = go;
                out[((size_t)b*TT + t)*NN + n] = go;
            }
        }
#undef WB_LOAD64
    }
#undef PA_LOAD
}

// ---------------- hyper projection ------------------------------------------
__global__ void k_hyper(const float* __restrict__ hW, const float* __restrict__ hb) {
    int idx = blockIdx.x*blockDim.x + threadIdx.x;
    if (idx >= BN*EMB) return;
    int bn = idx / EMB, e = idx % EMB;
    float s = hb[e];
    #pragma unroll
    for (int k = 0; k < HID; k++) s += g_h[(size_t)bn*HID + k] * hW[k*EMB + e];
    g_ne[idx] = s;
}

// ---------------- orchestration ---------------------------------------------
extern "C" void kernel_launch(void* const* d_in, const int* in_sizes, int n_in,
                              void* d_out, int out_size) {
    const float* x       = (const float*)d_in[0];
    const float* ycov    = (const float*)d_in[1];
    const float* emb     = (const float*)d_in[2];
    const float* enc_gW  = (const float*)d_in[3];
    const float* enc_gb  = (const float*)d_in[4];
    const float* enc_uW  = (const float*)d_in[5];
    const float* enc_ub  = (const float*)d_in[6];
    const float* dec_gW  = (const float*)d_in[7];
    const float* dec_gb  = (const float*)d_in[8];
    const float* dec_uW  = (const float*)d_in[9];
    const float* dec_ub  = (const float*)d_in[10];
    const float* proj_W  = (const float*)d_in[11];
    const float* proj_b  = (const float*)d_in[12];
    const float* hyper_W = (const float*)d_in[13];
    const float* hyper_b = (const float*)d_in[14];
    float* out = (float*)d_out;

    static int smem_set = 0;
    if (!smem_set) {
        cudaFuncSetAttribute(k_cell, cudaFuncAttributeMaxDynamicSharedMemorySize,
                             SM_BYTES);
        smem_set = 1;
    }

    dim3 gs_cell(4, BB);
    dim3 gs_sq_en(4, 8, 1);
    dim3 gs_sq_de(4, 8, BB);
    dim3 gs_pre(16, BB, 2);

    k_zero<<<1024, 256>>>();
    k_prep<<<(208*128+255)/256, 256>>>(enc_gW, 0);
    k_prep<<<(208*128+255)/256, 256>>>(dec_gW, 1);
    k_prep<<<(208*64+255)/256, 256>>>(enc_uW, 2);
    k_prep<<<(208*64+255)/256, 256>>>(dec_uW, 3);
    k_support_en<<<NN, 256>>>(emb);
    k_sq<<<gs_sq_en, 256>>>(0);
    k_pre_enc<<<gs_pre, 256>>>(x);

    for (int t = 0; t < TT; t++) {
        k_cell<<<gs_cell, 256, SM_BYTES>>>(0, 0, t, x, ycov, enc_gb,
                                           nullptr, nullptr, nullptr);
        k_cell<<<gs_cell, 256, SM_BYTES>>>(1, 0, t, x, ycov, enc_ub,
                                           nullptr, nullptr, nullptr);
    }

    k_hyper<<<(BN*EMB + 255)/256, 256>>>(hyper_W, hyper_b);
    k_support_de<<<BN, 256>>>();
    k_sq<<<gs_sq_de, 256>>>(1);
    k_pre_dec<<<gs_pre, 256>>>(ycov);

    for (int t = 0; t < TT; t++) {
        k_cell<<<gs_cell, 256, SM_BYTES>>>(0, 1, t, x, ycov, dec_gb,
                                           nullptr, nullptr, nullptr);
        k_cell<<<gs_cell, 256, SM_BYTES>>>(1, 1, t, x, ycov, dec_ub,
                                           proj_W, proj_b, out);
    }
}

// round 10
// speedup vs baseline: 3.6780x; 1.0746x over previous
#include <cuda_runtime.h>
#include <cuda_fp16.h>
#include <math.h>

// ---------------- problem constants ----------------
#define BB   32
#define TT   12
#define NN   512
#define HID  64
#define EMB  10
#define BN   (BB*NN)     // 16384

// Feature K layout for the weight GEMM (208 rows):
//  0..63   X (h or z*h) | 64..127 S@X | 128..191 2S^2X-X
//  192..197 [x0,x1,Sx0,Sx1,S2x0,S2x1] | 198..207 zero pad

// ---------------- dynamic smem layout (bytes) ----------------
#define TILEH   3072        // halves per 128x24 tile
#define TILEB   6144
#define OFF_PAN 0           // 13 tiles       -> 79872
#define OFF_SS  79872       // 3 stages S     -> 18432
#define OFF_S2  98304       // 3 stages S2    -> 18432
#define OFF_XB  116736      // 3 stages 64x24 -> 9216
#define OFF_GO  125952      // 512 floats     -> 2048
#define SM_BYTES 128000

// ---------------- device scratch ----------------
__device__ float  g_h[BN*HID];
__device__ float  g_r[BN*HID];
__device__ __half g_x0 [BN*64];          // h, row-major
__device__ __half g_x0T[BB*64*NN];       // h, [b][c][n]
__device__ __half g_x1 [BN*64];          // z*h, row-major
__device__ __half g_x1T[BB*64*NN];
__device__ float  g_sup_en_f[NN*NN];
__device__ __half g_sup_en_h[NN*NN];
__device__ float  g_sup_de_f[(size_t)BB*NN*NN];
__device__ __half g_sup_de_h[(size_t)BB*NN*NN];
__device__ float  g_s2_en_f[NN*NN];
__device__ __half g_s2_en_h[NN*NN];
__device__ float  g_s2_de_f[(size_t)BB*NN*NN];
__device__ __half g_s2_de_h[(size_t)BB*NN*NN];
__device__ float  g_ne[BN*EMB];
__device__ float  g_go[BN];
__device__ float  g_xf1[BN*24];
__device__ float  g_xf2[BN*24];
__device__ float  g_yf1[BN*TT];
__device__ float  g_yf2[BN*TT];
// transposed fp16 weights: [n][208]
__device__ __half g_WgeT[128*208];
__device__ __half g_WgdT[128*208];
__device__ __half g_WueT[64*208];
__device__ __half g_WudT[64*208];

__device__ __forceinline__ int wmap(int c) {
    if (c < 64)  return c + 2;
    if (c < 128) return c + 4;
    if (c < 192) return c + 6;
    return ((c - 192) >> 1) * 66 + (c & 1);
}

// ---------------- mma helpers ----------------
__device__ __forceinline__ unsigned f2tf(float f) {
    unsigned u;
    asm("cvt.rna.tf32.f32 %0, %1;" : "=r"(u) : "f"(f));
    return u;
}
__device__ __forceinline__ void mma_tf32(float* d,
    unsigned a0, unsigned a1, unsigned a2, unsigned a3,
    unsigned b0, unsigned b1) {
    asm volatile(
        "mma.sync.aligned.m16n8k8.row.col.f32.tf32.tf32.f32 "
        "{%0,%1,%2,%3}, {%4,%5,%6,%7}, {%8,%9}, {%0,%1,%2,%3};\n"
        : "+f"(d[0]), "+f"(d[1]), "+f"(d[2]), "+f"(d[3])
        : "r"(a0), "r"(a1), "r"(a2), "r"(a3), "r"(b0), "r"(b1));
}
__device__ __forceinline__ void mma_f16(float* d,
    unsigned a0, unsigned a1, unsigned a2, unsigned a3,
    unsigned b0, unsigned b1) {
    asm volatile(
        "mma.sync.aligned.m16n8k16.row.col.f32.f16.f16.f32 "
        "{%0,%1,%2,%3}, {%4,%5,%6,%7}, {%8,%9}, {%0,%1,%2,%3};\n"
        : "+f"(d[0]), "+f"(d[1]), "+f"(d[2]), "+f"(d[3])
        : "r"(a0), "r"(a1), "r"(a2), "r"(a3), "r"(b0), "r"(b1));
}
__device__ __forceinline__ void ldsm_x4(unsigned& r0, unsigned& r1,
                                        unsigned& r2, unsigned& r3, unsigned addr) {
    asm volatile("ldmatrix.sync.aligned.m8n8.x4.shared.b16 {%0,%1,%2,%3}, [%4];"
        : "=r"(r0), "=r"(r1), "=r"(r2), "=r"(r3) : "r"(addr));
}

__device__ __forceinline__ void cpa16(void* smem, const void* g) {
    unsigned s = (unsigned)__cvta_generic_to_shared(smem);
    asm volatile("cp.async.cg.shared.global [%0], [%1], 16;\n" :: "r"(s), "l"(g));
}
#define CP_COMMIT() asm volatile("cp.async.commit_group;\n" ::: "memory")
#define CP_WAIT1()  asm volatile("cp.async.wait_group 1;\n" ::: "memory")
#define CP_WAIT0()  asm volatile("cp.async.wait_group 0;\n" ::: "memory")

// ---------------- init ----------------
__global__ void k_zero() {
    size_t i = (size_t)blockIdx.x*blockDim.x + threadIdx.x;
    size_t st = (size_t)gridDim.x*blockDim.x;
    const __half hz = __float2half(0.f);
    for (size_t j=i; j<(size_t)BN*64; j+=st) { g_x0[j] = hz; g_x0T[j] = hz; }
    for (size_t j=i; j<BN*HID; j+=st) g_h[j]  = 0.f;
    for (size_t j=i; j<BN;     j+=st) g_go[j] = 0.f;
}

// ---------------- weight reorder (transposed fp16) --------------------------
__global__ void k_prep(const float* __restrict__ W, int which) {
    int nc = (which < 2) ? 128 : 64;
    __half* dst = (which == 0) ? g_WgeT : (which == 1) ? g_WgdT
               : (which == 2) ? g_WueT : g_WudT;
    int idx = blockIdx.x*blockDim.x + threadIdx.x;
    if (idx >= 208*nc) return;
    int c = idx / nc, o = idx - c*nc;
    float v = 0.f;
    if (c < 198) v = W[wmap(c)*nc + o];
    dst[(size_t)o*208 + c] = __float2half(v);
}

// ---------------- supports (fp32 + fp16 copies) ----------------
__global__ void k_support_en(const float* __restrict__ emb) {
    int n = blockIdx.x, tid = threadIdx.x;
    __shared__ float embn[EMB];
    __shared__ float row[NN];
    __shared__ float red[256];
    if (tid < EMB) embn[tid] = emb[n*EMB + tid];
    __syncthreads();
    for (int m=tid; m<NN; m+=256) {
        float s = 0.f;
        #pragma unroll
        for (int e=0; e<EMB; e++) s += embn[e]*emb[m*EMB+e];
        row[m] = fmaxf(s, 0.f);
    }
    __syncthreads();
    float lm = -1e30f;
    for (int m=tid; m<NN; m+=256) lm = fmaxf(lm, row[m]);
    red[tid]=lm; __syncthreads();
    for (int s=128;s>0;s>>=1){ if(tid<s) red[tid]=fmaxf(red[tid],red[tid+s]); __syncthreads(); }
    float mx = red[0]; __syncthreads();
    float ls = 0.f;
    for (int m=tid; m<NN; m+=256){ float e=expf(row[m]-mx); row[m]=e; ls+=e; }
    red[tid]=ls; __syncthreads();
    for (int s=128;s>0;s>>=1){ if(tid<s) red[tid]+=red[tid+s]; __syncthreads(); }
    float inv = 1.f/red[0];
    for (int m=tid; m<NN; m+=256) {
        float v = row[m]*inv;
        g_sup_en_f[n*NN+m] = v;
        g_sup_en_h[n*NN+m] = __float2half(v);
    }
}

__global__ void k_support_de() {
    int bn = blockIdx.x;
    int b = bn >> 9, n = bn & 511;
    int tid = threadIdx.x;
    const float* neb = g_ne + (size_t)b*NN*EMB;
    __shared__ float embn[EMB];
    __shared__ float row[NN];
    __shared__ float red[256];
    if (tid < EMB) embn[tid] = neb[n*EMB + tid];
    __syncthreads();
    for (int m=tid; m<NN; m+=256) {
        float s = 0.f;
        #pragma unroll
        for (int e=0; e<EMB; e++) s += embn[e]*neb[m*EMB+e];
        row[m] = fmaxf(s, 0.f);
    }
    __syncthreads();
    float lm = -1e30f;
    for (int m=tid; m<NN; m+=256) lm = fmaxf(lm, row[m]);
    red[tid]=lm; __syncthreads();
    for (int s=128;s>0;s>>=1){ if(tid<s) red[tid]=fmaxf(red[tid],red[tid+s]); __syncthreads(); }
    float mx = red[0]; __syncthreads();
    float ls = 0.f;
    for (int m=tid; m<NN; m+=256){ float e=expf(row[m]-mx); row[m]=e; ls+=e; }
    red[tid]=ls; __syncthreads();
    for (int s=128;s>0;s>>=1){ if(tid<s) red[tid]+=red[tid+s]; __syncthreads(); }
    float inv = 1.f/red[0];
    size_t base = (size_t)b*NN*NN + (size_t)n*NN;
    for (int m=tid; m<NN; m+=256) {
        float v = row[m]*inv;
        g_sup_de_f[base+m] = v;
        g_sup_de_h[base+m] = __float2half(v);
    }
}

// ---------------- S2 = S @ S  (tf32 MMA on fp32 S; dual-format output) ------
__global__ void __launch_bounds__(256) k_sq(int deFlag) {
    __shared__ float As[3][128*20];
    __shared__ float Bs[3][16*72];
    const int b  = blockIdx.z;
    const int m0 = blockIdx.x*128;
    const int n0 = blockIdx.y*64;
    const int tid = threadIdx.x;
    const int warp = tid >> 5, lane = tid & 31;
    const int mw = warp & 3, nw = warp >> 2;
    const int tq = lane >> 2, tr = lane & 3;
    const float* S = deFlag ? g_sup_de_f + (size_t)b*NN*NN : g_sup_en_f;
    float*  Df = deFlag ? g_s2_de_f + (size_t)b*NN*NN : g_s2_en_f;
    __half* Dh = deFlag ? g_s2_de_h + (size_t)b*NN*NN : g_s2_en_h;
    const int lr = tid >> 1, lc = (tid & 1)*8;
    const int bk = tid >> 4, bn = (tid & 15)*4;

    float acc[2][4][4] = {};

#define SQ_LOAD(st, k0) do { \
    cpa16(&As[st][lr*20+lc],   &S[(size_t)(m0+lr)*NN + (k0)+lc]); \
    cpa16(&As[st][lr*20+lc+4], &S[(size_t)(m0+lr)*NN + (k0)+lc+4]); \
    cpa16(&Bs[st][bk*72+bn],   &S[(size_t)((k0)+bk)*NN + n0 + bn]); \
} while(0)

    SQ_LOAD(0, 0);  CP_COMMIT();
    SQ_LOAD(1, 16); CP_COMMIT();
    for (int kt = 0; kt < 32; kt++) {
        CP_WAIT1();
        __syncthreads();
        if (kt < 30) SQ_LOAD((kt+2)%3, (kt+2)*16);
        CP_COMMIT();
        const float* Ab = As[kt%3];
        const float* Bb = Bs[kt%3];
        #pragma unroll
        for (int ks = 0; ks < 16; ks += 8) {
            unsigned a[2][4], bb[4][2];
            #pragma unroll
            for (int mi = 0; mi < 2; mi++) {
                int r = mw*32 + mi*16 + tq;
                a[mi][0] = f2tf(Ab[r*20 + ks + tr]);
                a[mi][1] = f2tf(Ab[(r+8)*20 + ks + tr]);
                a[mi][2] = f2tf(Ab[r*20 + ks + tr + 4]);
                a[mi][3] = f2tf(Ab[(r+8)*20 + ks + tr + 4]);
            }
            #pragma unroll
            for (int nj = 0; nj < 4; nj++) {
                int c = nw*32 + nj*8 + tq;
                bb[nj][0] = f2tf(Bb[(ks+tr)*72 + c]);
                bb[nj][1] = f2tf(Bb[(ks+tr+4)*72 + c]);
            }
            #pragma unroll
            for (int mi = 0; mi < 2; mi++)
                #pragma unroll
                for (int nj = 0; nj < 4; nj++)
                    mma_tf32(acc[mi][nj], a[mi][0], a[mi][1], a[mi][2], a[mi][3],
                             bb[nj][0], bb[nj][1]);
        }
    }
    __syncthreads();
    #pragma unroll
    for (int mi = 0; mi < 2; mi++) {
        int r0 = m0 + mw*32 + mi*16 + tq;
        #pragma unroll
        for (int nj = 0; nj < 4; nj++) {
            int c = n0 + nw*32 + nj*8 + tr*2;
            #pragma unroll
            for (int hh = 0; hh < 2; hh++) {
                int rr = r0 + hh*8;
                float va = acc[mi][nj][hh*2], vb = acc[mi][nj][hh*2+1];
                *(float2*)&Df[(size_t)rr*NN + c] = make_float2(va, vb);
                *(__half2*)&Dh[(size_t)rr*NN + c] = __floats2half2_rn(va, vb);
            }
        }
    }
#undef SQ_LOAD
}

// ---------------- x/ycov feature precompute ---------------------------------
__global__ void __launch_bounds__(256) k_pre_enc(const float* __restrict__ x) {
    __shared__ float xsh[512*24];
    int b = blockIdx.y, m0 = blockIdx.x*32, z = blockIdx.z;
    int tid = threadIdx.x;
    for (int idx = tid; idx < 512*24; idx += 256) {
        int k = idx/24, tc = idx%24;
        int t = tc>>1, c = tc&1;
        xsh[idx] = x[(((size_t)b*TT+t)*NN + k)*2 + c];
    }
    __syncthreads();
    int rl = tid>>3, kh = (tid>>2)&1, cg = tid&3;
    int row = m0 + rl, g = cg*6;
    float acc[6] = {};
    const float* Srow = (z ? g_s2_en_f : g_sup_en_f) + (size_t)row*NN + kh*256;
    const float* xp = &xsh[kh*256*24];
    for (int k=0;k<256;k+=4){
        float4 s = *(const float4*)&Srow[k];
        #pragma unroll
        for (int j=0;j<6;j++)
            acc[j] += s.x*xp[(k+0)*24+g+j] + s.y*xp[(k+1)*24+g+j]
                    + s.z*xp[(k+2)*24+g+j] + s.w*xp[(k+3)*24+g+j];
    }
    #pragma unroll
    for (int j=0;j<6;j++) acc[j] += __shfl_xor_sync(0xffffffffu, acc[j], 4);
    if (kh == 0) {
        #pragma unroll
        for (int j=0;j<6;j++) {
            int col = g + j;
            if (z == 0) g_xf1[((size_t)b*NN + row)*24 + col] = acc[j];
            else {
                int t = col>>1, c = col&1;
                g_xf2[((size_t)b*NN + row)*24 + col] =
                    2.f*acc[j] - x[(((size_t)b*TT+t)*NN + row)*2 + c];
            }
        }
    }
}

__global__ void __launch_bounds__(256) k_pre_dec(const float* __restrict__ ycov) {
    __shared__ float ysh[512*12];
    int b = blockIdx.y, m0 = blockIdx.x*32, z = blockIdx.z;
    int tid = threadIdx.x;
    for (int idx = tid; idx < 512*12; idx += 256) {
        int k = idx/12, t = idx%12;
        ysh[idx] = ycov[((size_t)b*TT+t)*NN + k];
    }
    __syncthreads();
    int rl = tid>>3, kh = (tid>>2)&1, cg = tid&3;
    int row = m0 + rl, g = cg*3;
    float acc[3] = {};
    const float* Srow = (z ? g_s2_de_f : g_sup_de_f)
                        + (size_t)b*NN*NN + (size_t)row*NN + kh*256;
    const float* yp = &ysh[kh*256*12];
    for (int k=0;k<256;k+=4){
        float4 s = *(const float4*)&Srow[k];
        #pragma unroll
        for (int j=0;j<3;j++)
            acc[j] += s.x*yp[(k+0)*12+g+j] + s.y*yp[(k+1)*12+g+j]
                    + s.z*yp[(k+2)*12+g+j] + s.w*yp[(k+3)*12+g+j];
    }
    #pragma unroll
    for (int j=0;j<3;j++) acc[j] += __shfl_xor_sync(0xffffffffu, acc[j], 4);
    if (kh == 0) {
        #pragma unroll
        for (int j=0;j<3;j++) {
            int t = g + j;
            if (z == 0) g_yf1[((size_t)b*NN + row)*12 + t] = acc[j];
            else        g_yf2[((size_t)b*NN + row)*12 + t] =
                            2.f*acc[j] - ycov[((size_t)b*TT+t)*NN + row];
        }
    }
}

// ---------------- fused cell-phase kernel (fp16 MMA + ldmatrix) --------------
__global__ void __launch_bounds__(256) k_cell(
    int phase, int deFlag, int t,
    const float* __restrict__ x, const float* __restrict__ ycov,
    const float* __restrict__ bias,
    const float* __restrict__ pW, const float* __restrict__ pb,
    float* __restrict__ out)
{
    extern __shared__ char smx[];
    __half* PAN = (__half*)(smx + OFF_PAN);
    __half* SS  = (__half*)(smx + OFF_SS);
    __half* S2S = (__half*)(smx + OFF_S2);
    __half* XB  = (__half*)(smx + OFF_XB);
    float*  GOs = (float*)(smx + OFF_GO);
    __shared__ float pr[2][128];

    const int b  = blockIdx.y;
    const int m0 = blockIdx.x*128;
    const int tid = threadIdx.x;
    const int warp = tid >> 5, lane = tid & 31;
    const int mw = warp & 3, nw = warp >> 2;
    const int tq = lane >> 2, tr = lane & 3;

    // ldmatrix lane geometry
    const int l8 = lane & 7, mt = lane >> 3;
    const int arow = l8 + (mt & 1)*8;      // row within m16, matrices (0,1)=(k0),(2,3)=(k8)
    const int acol = (mt >> 1)*8;
    const int brow = l8 + (mt >> 1)*8;     // n-row within n16, matrices (0,1)=(n0),(2,3)=(n8)
    const int bcol = (mt & 1)*8;
    const unsigned aOff0 = ((mw*32 + arow)*24 + acol)*2;
    const unsigned aOff1 = aOff0 + 16*48;
    const unsigned bOff0 = ((nw*32 + brow)*24 + bcol)*2;
    const unsigned bOff1 = bOff0 + 16*48;
    const unsigned uPAN = (unsigned)__cvta_generic_to_shared(PAN);
    const unsigned uSS  = (unsigned)__cvta_generic_to_shared(SS);
    const unsigned uS2  = (unsigned)__cvta_generic_to_shared(S2S);
    const unsigned uXB  = (unsigned)__cvta_generic_to_shared(XB);

    const __half* Sh  = deFlag ? g_sup_de_h + (size_t)b*NN*NN : g_sup_en_h;
    const __half* S2h = deFlag ? g_s2_de_h  + (size_t)b*NN*NN : g_s2_en_h;
    const __half* Xrow = (phase == 0) ? g_x0 : g_x1;
    const __half* XT   = (phase == 0) ? g_x0T : g_x1T;

    // ---- preload panel tiles 0..3 (X own rows) ----
    #pragma unroll
    for (int i = 0; i < 4; i++) {
        int ch = tid + i*256;
        int tI = ch >> 8, rw = (ch >> 1) & 127, off = (ch & 1)*8;
        cpa16(&PAN[tI*TILEH + rw*24 + off],
              &Xrow[((size_t)b*NN + m0 + rw)*64 + tI*16 + off]);
    }
    if (deFlag) {
        GOs[tid]       = g_go[(size_t)b*NN + tid];
        GOs[tid + 256] = g_go[(size_t)b*NN + tid + 256];
    }
    CP_COMMIT();

    // ---- phase A: Y1 = S@X, Y2raw = S2@X (K=512) ----
    const int lrA = tid >> 1, loA = (tid & 1)*8;

    float acc1[2][4][4] = {};
    float acc2[2][4][4] = {};
    float d1 = 0.f, d2 = 0.f;
    const int mvrow = tid >> 1, mvh = (tid & 1)*8;

#define PA_LOAD(st, k0) do { \
    cpa16(&SS [(st)*TILEH + lrA*24 + loA], &Sh [(size_t)(m0+lrA)*NN + (k0)+loA]); \
    cpa16(&S2S[(st)*TILEH + lrA*24 + loA], &S2h[(size_t)(m0+lrA)*NN + (k0)+loA]); \
    if (tid < 128) \
        cpa16(&XB[(st)*1536 + lrA*24 + loA], &XT[((size_t)b*64 + lrA)*NN + (k0)+loA]); \
} while(0)

    PA_LOAD(0, 0);  CP_COMMIT();
    PA_LOAD(1, 16); CP_COMMIT();
    for (int kt = 0; kt < 32; kt++) {
        CP_WAIT1();
        __syncthreads();
        if (kt < 30) PA_LOAD((kt+2)%3, (kt+2)*16);
        CP_COMMIT();
        const unsigned sb  = uSS + (kt%3)*TILEB;
        const unsigned s2b = uS2 + (kt%3)*TILEB;
        const unsigned xb  = uXB + (kt%3)*3072;
        unsigned a[2][4], a2[2][4], bb[4][2];
        ldsm_x4(a [0][0], a [0][1], a [0][2], a [0][3], sb  + aOff0);
        ldsm_x4(a [1][0], a [1][1], a [1][2], a [1][3], sb  + aOff1);
        ldsm_x4(a2[0][0], a2[0][1], a2[0][2], a2[0][3], s2b + aOff0);
        ldsm_x4(a2[1][0], a2[1][1], a2[1][2], a2[1][3], s2b + aOff1);
        ldsm_x4(bb[0][0], bb[0][1], bb[1][0], bb[1][1], xb + bOff0);
        ldsm_x4(bb[2][0], bb[2][1], bb[3][0], bb[3][1], xb + bOff1);
        #pragma unroll
        for (int mi = 0; mi < 2; mi++)
            #pragma unroll
            for (int nj = 0; nj < 4; nj++) {
                mma_f16(acc1[mi][nj], a [mi][0], a [mi][1], a [mi][2], a [mi][3],
                        bb[nj][0], bb[nj][1]);
                mma_f16(acc2[mi][nj], a2[mi][0], a2[mi][1], a2[mi][2], a2[mi][3],
                        bb[nj][0], bb[nj][1]);
            }
        if (deFlag) {
            const __half* Ab  = SS  + (kt%3)*TILEH;
            const __half* A2b = S2S + (kt%3)*TILEH;
            const __half2* ap  = (const __half2*)&Ab [mvrow*24 + mvh];
            const __half2* a2p = (const __half2*)&A2b[mvrow*24 + mvh];
            const float* gop = &GOs[kt*16 + mvh];
            #pragma unroll
            for (int j = 0; j < 4; j++) {
                float2 v  = __half22float2(ap[j]);
                float2 v2 = __half22float2(a2p[j]);
                d1 += v.x*gop[2*j] + v.y*gop[2*j+1];
                d2 += v2.x*gop[2*j] + v2.y*gop[2*j+1];
            }
        }
    }
    CP_WAIT0();
    __syncthreads();

    // ---- write Y1 (tiles 4..7), Y2 = 2*acc2 - X (tiles 8..11) ----
    #pragma unroll
    for (int mi = 0; mi < 2; mi++) {
        int r = mw*32 + mi*16 + tq;
        #pragma unroll
        for (int nj = 0; nj < 4; nj++) {
            int c = nw*32 + nj*8 + tr*2;
            int tI = c >> 4, kk = c & 15;
            #pragma unroll
            for (int hh = 0; hh < 2; hh++) {
                int rr = r + hh*8;
                float v1a = acc1[mi][nj][hh*2], v1b = acc1[mi][nj][hh*2+1];
                float v2a = acc2[mi][nj][hh*2], v2b = acc2[mi][nj][hh*2+1];
                float xa = __half2float(PAN[tI*TILEH + rr*24 + kk]);
                float xb2 = __half2float(PAN[tI*TILEH + rr*24 + kk + 1]);
                *(__half2*)&PAN[(4+tI)*TILEH + rr*24 + kk] =
                    __floats2half2_rn(v1a, v1b);
                *(__half2*)&PAN[(8+tI)*TILEH + rr*24 + kk] =
                    __floats2half2_rn(2.f*v2a - xa, 2.f*v2b - xb2);
            }
        }
    }

    // ---- tile 12: extra features ----
    if (deFlag) {
        d1 += __shfl_xor_sync(0xffffffffu, d1, 1);
        d2 += __shfl_xor_sync(0xffffffffu, d2, 1);
        if ((tid & 1) == 0) {
            int rw = tid >> 1;
            size_t gr = (size_t)b*NN + m0 + rw;
            float go = GOs[m0 + rw];
            __half* T = &PAN[12*TILEH + rw*24];
            T[0] = __float2half(go);
            T[1] = __float2half(ycov[((size_t)b*TT + t)*NN + m0 + rw]);
            T[2] = __float2half(d1);
            T[3] = __float2half(g_yf1[gr*12 + t]);
            T[4] = __float2half(2.f*d2 - go);
            T[5] = __float2half(g_yf2[gr*12 + t]);
            #pragma unroll
            for (int j = 6; j < 16; j++) T[j] = __float2half(0.f);
        }
    } else {
        if (tid < 128) {
            int rw = tid;
            size_t gr = (size_t)b*NN + m0 + rw;
            const float* xp = &x[(((size_t)b*TT + t)*NN + m0 + rw)*2];
            __half* T = &PAN[12*TILEH + rw*24];
            T[0] = __float2half(xp[0]);
            T[1] = __float2half(xp[1]);
            T[2] = __float2half(g_xf1[gr*24 + t*2 + 0]);
            T[3] = __float2half(g_xf1[gr*24 + t*2 + 1]);
            T[4] = __float2half(g_xf2[gr*24 + t*2 + 0]);
            T[5] = __float2half(g_xf2[gr*24 + t*2 + 1]);
            #pragma unroll
            for (int j = 6; j < 16; j++) T[j] = __float2half(0.f);
        }
    }
    __syncthreads();

    // ---- phase B: weight GEMM over K=208 from the panel ----
    if (phase == 0) {
        const __half* WT = deFlag ? g_WgdT : g_WgeT;
        float acc[2][8][4] = {};
        const unsigned bG0 = ((nw*64 + brow)*24 + bcol)*2;
#define WB_LOAD128(st, k0) do { \
    int n_ = tid >> 1, of_ = (tid & 1)*8; \
    cpa16(&SS[(st)*TILEH + n_*24 + of_], &WT[(size_t)n_*208 + (k0)+of_]); \
} while(0)
        WB_LOAD128(0, 0);  CP_COMMIT();
        WB_LOAD128(1, 16); CP_COMMIT();
        for (int kt = 0; kt < 13; kt++) {
            CP_WAIT1();
            __syncthreads();
            if (kt < 11) WB_LOAD128((kt+2)%3, (kt+2)*16);
            CP_COMMIT();
            const unsigned pb_ = uPAN + kt*TILEB;
            const unsigned wb  = uSS + (kt%3)*TILEB;
            unsigned a[2][4], bb[8][2];
            ldsm_x4(a[0][0], a[0][1], a[0][2], a[0][3], pb_ + aOff0);
            ldsm_x4(a[1][0], a[1][1], a[1][2], a[1][3], pb_ + aOff1);
            #pragma unroll
            for (int j = 0; j < 4; j++)
                ldsm_x4(bb[2*j][0], bb[2*j][1], bb[2*j+1][0], bb[2*j+1][1],
                        wb + bG0 + j*16*48);
            #pragma unroll
            for (int mi = 0; mi < 2; mi++)
                #pragma unroll
                for (int nj = 0; nj < 8; nj++)
                    mma_f16(acc[mi][nj], a[mi][0], a[mi][1], a[mi][2], a[mi][3],
                            bb[nj][0], bb[nj][1]);
        }
        // epilogue: z = sigmoid -> z*h into g_x1/g_x1T ; r into g_r
        #pragma unroll
        for (int mi = 0; mi < 2; mi++) {
            int r0 = mw*32 + mi*16 + tq;
            #pragma unroll
            for (int nj = 0; nj < 8; nj++) {
                int c = nw*64 + nj*8 + tr*2;
                #pragma unroll
                for (int hh = 0; hh < 2; hh++) {
                    int ln = m0 + r0 + hh*8;
                    size_t row = (size_t)b*NN + ln;
                    float va = acc[mi][nj][hh*2], vb = acc[mi][nj][hh*2+1];
                    float za = 1.f/(1.f + expf(-(va + bias[c])));
                    float zb = 1.f/(1.f + expf(-(vb + bias[c+1])));
                    if (c < 64) {
                        float ha = za * g_h[row*HID + c];
                        float hb = zb * g_h[row*HID + c+1];
                        *(__half2*)&g_x1[row*64 + c] = __floats2half2_rn(ha, hb);
                        g_x1T[((size_t)b*64 + c  )*NN + ln] = __float2half(ha);
                        g_x1T[((size_t)b*64 + c+1)*NN + ln] = __float2half(hb);
                    } else {
                        g_r[row*HID + (c-64)]   = za;
                        g_r[row*HID + (c-64)+1] = zb;
                    }
                }
            }
        }
#undef WB_LOAD128
    } else {
        const __half* WT = deFlag ? g_WudT : g_WueT;
        float acc[2][4][4] = {};
#define WB_LOAD64(st, k0) do { \
    if (tid < 128) { int n_ = tid >> 1, of_ = (tid & 1)*8; \
        cpa16(&SS[(st)*1536 + n_*24 + of_], &WT[(size_t)n_*208 + (k0)+of_]); } \
} while(0)
        WB_LOAD64(0, 0);  CP_COMMIT();
        WB_LOAD64(1, 16); CP_COMMIT();
        for (int kt = 0; kt < 13; kt++) {
            CP_WAIT1();
            __syncthreads();
            if (kt < 11) WB_LOAD64((kt+2)%3, (kt+2)*16);
            CP_COMMIT();
            const unsigned pb_ = uPAN + kt*TILEB;
            const unsigned wb  = uSS + (kt%3)*3072;
            unsigned a[2][4], bb[4][2];
            ldsm_x4(a[0][0], a[0][1], a[0][2], a[0][3], pb_ + aOff0);
            ldsm_x4(a[1][0], a[1][1], a[1][2], a[1][3], pb_ + aOff1);
            ldsm_x4(bb[0][0], bb[0][1], bb[1][0], bb[1][1], wb + bOff0);
            ldsm_x4(bb[2][0], bb[2][1], bb[3][0], bb[3][1], wb + bOff1);
            #pragma unroll
            for (int mi = 0; mi < 2; mi++)
                #pragma unroll
                for (int nj = 0; nj < 4; nj++)
                    mma_f16(acc[mi][nj], a[mi][0], a[mi][1], a[mi][2], a[mi][3],
                            bb[nj][0], bb[nj][1]);
        }
        // epilogue: h update (+ projection for decoder)
        const bool doProj = (deFlag != 0);
        float rowsum[2][2] = {};
        #pragma unroll
        for (int mi = 0; mi < 2; mi++) {
            int r0 = mw*32 + mi*16 + tq;
            #pragma unroll
            for (int nj = 0; nj < 4; nj++) {
                int c = nw*32 + nj*8 + tr*2;
                #pragma unroll
                for (int hh = 0; hh < 2; hh++) {
                    int ln = m0 + r0 + hh*8;
                    size_t row = (size_t)b*NN + ln;
                    float hn2[2];
                    #pragma unroll
                    for (int jj = 0; jj < 2; jj++) {
                        int o = c + jj;
                        float hc = tanhf(acc[mi][nj][hh*2+jj] + bias[o]);
                        float r  = g_r[row*HID + o];
                        float h  = g_h[row*HID + o];
                        float hn = r*h + (1.f - r)*hc;
                        g_h[row*HID + o] = hn;
                        g_x0T[((size_t)b*64 + o)*NN + ln] = __float2half(hn);
                        hn2[jj] = hn;
                        if (doProj) rowsum[mi][hh] += hn * pW[o];
                    }
                    *(__half2*)&g_x0[row*64 + c] = __floats2half2_rn(hn2[0], hn2[1]);
                }
            }
        }
        if (doProj) {
            #pragma unroll
            for (int mi = 0; mi < 2; mi++)
                #pragma unroll
                for (int hh = 0; hh < 2; hh++) {
                    float v = rowsum[mi][hh];
                    v += __shfl_xor_sync(0xffffffffu, v, 1);
                    v += __shfl_xor_sync(0xffffffffu, v, 2);
                    if (tr == 0) pr[nw][mw*32 + mi*16 + tq + hh*8] = v;
                }
            __syncthreads();
            if (tid < 128) {
                int n = m0 + tid;
                float go = pr[0][tid] + pr[1][tid] + pb[0];
                g_go[(size_t)b*NN + n] = go;
                out[((size_t)b*TT + t)*NN + n] = go;
            }
        }
#undef WB_LOAD64
    }
#undef PA_LOAD
}

// ---------------- hyper projection ------------------------------------------
__global__ void k_hyper(const float* __restrict__ hW, const float* __restrict__ hb) {
    int idx = blockIdx.x*blockDim.x + threadIdx.x;
    if (idx >= BN*EMB) return;
    int bn = idx / EMB, e = idx % EMB;
    float s = hb[e];
    #pragma unroll
    for (int k = 0; k < HID; k++) s += g_h[(size_t)bn*HID + k] * hW[k*EMB + e];
    g_ne[idx] = s;
}

// ---------------- orchestration ---------------------------------------------
extern "C" void kernel_launch(void* const* d_in, const int* in_sizes, int n_in,
                              void* d_out, int out_size) {
    const float* x       = (const float*)d_in[0];
    const float* ycov    = (const float*)d_in[1];
    const float* emb     = (const float*)d_in[2];
    const float* enc_gW  = (const float*)d_in[3];
    const float* enc_gb  = (const float*)d_in[4];
    const float* enc_uW  = (const float*)d_in[5];
    const float* enc_ub  = (const float*)d_in[6];
    const float* dec_gW  = (const float*)d_in[7];
    const float* dec_gb  = (const float*)d_in[8];
    const float* dec_uW  = (const float*)d_in[9];
    const float* dec_ub  = (const float*)d_in[10];
    const float* proj_W  = (const float*)d_in[11];
    const float* proj_b  = (const float*)d_in[12];
    const float* hyper_W = (const float*)d_in[13];
    const float* hyper_b = (const float*)d_in[14];
    float* out = (float*)d_out;

    static int smem_set = 0;
    if (!smem_set) {
        cudaFuncSetAttribute(k_cell, cudaFuncAttributeMaxDynamicSharedMemorySize,
                             SM_BYTES);
        smem_set = 1;
    }

    dim3 gs_cell(4, BB);
    dim3 gs_sq_en(4, 8, 1);
    dim3 gs_sq_de(4, 8, BB);
    dim3 gs_pre(16, BB, 2);

    k_zero<<<1024, 256>>>();
    k_prep<<<(208*128+255)/256, 256>>>(enc_gW, 0);
    k_prep<<<(208*128+255)/256, 256>>>(dec_gW, 1);
    k_prep<<<(208*64+255)/256, 256>>>(enc_uW, 2);
    k_prep<<<(208*64+255)/256, 256>>>(dec_uW, 3);
    k_support_en<<<NN, 256>>>(emb);
    k_sq<<<gs_sq_en, 256>>>(0);
    k_pre_enc<<<gs_pre, 256>>>(x);

    for (int t = 0; t < TT; t++) {
        k_cell<<<gs_cell, 256, SM_BYTES>>>(0, 0, t, x, ycov, enc_gb,
                                           nullptr, nullptr, nullptr);
        k_cell<<<gs_cell, 256, SM_BYTES>>>(1, 0, t, x, ycov, enc_ub,
                                           nullptr, nullptr, nullptr);
    }

    k_hyper<<<(BN*EMB + 255)/256, 256>>>(hyper_W, hyper_b);
    k_support_de<<<BN, 256>>>();
    k_sq<<<gs_sq_de, 256>>>(1);
    k_pre_dec<<<gs_pre, 256>>>(ycov);

    for (int t = 0; t < TT; t++) {
        k_cell<<<gs_cell, 256, SM_BYTES>>>(0, 1, t, x, ycov, dec_gb,
                                           nullptr, nullptr, nullptr);
        k_cell<<<gs_cell, 256, SM_BYTES>>>(1, 1, t, x, ycov, dec_ub,
                                           proj_W, proj_b, out);
    }
}